// round 7
// baseline (speedup 1.0000x reference)
#include <cuda_runtime.h>
#include <math.h>

#define NB   128   // batch
#define LS   128   // sentence length
#define LT   8     // target length
#define EDIM 300   // embedding dim (E=300! in_sizes: emb=100000*300, Wih=1024*300)
#define EPAD 320   // padded embedding dim for GEMM
#define HDIM 256
#define GDIM 1024  // 4*H
#define NOUT 3

// ----------------------------- scratch (static __device__, no allocs) ------
__device__ __align__(128) float d_x_sen[LS * NB * EPAD];     // [t][b][e], zero-padded
__device__ __align__(128) float d_x_tgt[LT * NB * EPAD];
__device__ __align__(128) float d_Wih_pad[4][GDIM * EPAD];   // zero-padded [n][k]
__device__ __align__(128) float d_WhhT[4][HDIM * GDIM];      // [k][n] transposed
__device__ __align__(128) float d_gates_sen[2][LS * NB * GDIM];
__device__ __align__(128) float d_gates_tgt[2][LT * NB * GDIM];
__device__ __align__(128) float d_h_sen[2][LS * NB * HDIM];  // [t][b][h]
__device__ __align__(128) float d_h_tgt[2][LT * NB * HDIM];

struct WPtrs {
    const float* wih[4];
    const float* whh[4];
    const float* bih[4];
    const float* bhh[4];
};

__device__ __forceinline__ float sigf(float x) { return 1.f / (1.f + expf(-x)); }

// ----------------------------- K0: weight prep ------------------------------
// (a) pad Wih [1024,300] -> [1024,320] with zeros; (b) transpose Whh -> WhhT
__global__ void prep_kernel(WPtrs p) {
    int l = blockIdx.y;
    int stride = gridDim.x * blockDim.x;
    int start = blockIdx.x * blockDim.x + threadIdx.x;
    for (int i = start; i < GDIM * EPAD; i += stride) {
        int n = i / EPAD;
        int k = i - n * EPAD;
        d_Wih_pad[l][i] = (k < EDIM) ? p.wih[l][(size_t)n * EDIM + k] : 0.f;
    }
    for (int i = start; i < GDIM * HDIM; i += stride) {
        int n = i >> 8;          // 0..1023
        int k = i & 255;         // 0..255
        d_WhhT[l][k * GDIM + n] = p.whh[l][(size_t)n * HDIM + k];
    }
}

// ----------------------------- K1: embedding gather -------------------------
__global__ void embed_kernel(const int* __restrict__ sen_src,
                             const int* __restrict__ tgt_src,
                             const float* __restrict__ emb) {
    int row = blockIdx.x;
    int tid = threadIdx.x;  // 320 threads == EPAD
    if (row < LS * NB) {
        int t = row / NB, b = row % NB;
        int idx = sen_src[b * LS + t];
        float v = (idx == 0 || tid >= EDIM) ? 0.f : emb[(size_t)idx * EDIM + tid];
        d_x_sen[(size_t)row * EPAD + tid] = v;
    } else {
        int r = row - LS * NB;
        int t = r / NB, b = r % NB;
        int idx = tgt_src[b * LT + t];
        float v = (idx == 0 || tid >= EDIM) ? 0.f : emb[(size_t)idx * EDIM + tid];
        d_x_tgt[(size_t)r * EPAD + tid] = v;
    }
}

// ----------------------------- K2: input projection GEMM (fp32) -------------
// C[M,1024] = X[M,320] @ Wpad[1024,320]^T  (zero-padded K, exact)
#define BM 64
#define BN 64
#define BK 32

__global__ __launch_bounds__(256) void gemm_xw(int l) {
    const float* __restrict__ X = (l < 2) ? d_x_sen : d_x_tgt;
    const float* __restrict__ W = d_Wih_pad[l];
    float* __restrict__ C = (l < 2) ? d_gates_sen[l] : d_gates_tgt[l - 2];

    __shared__ float Xs[BM][BK + 1];
    __shared__ float Ws[BN][BK + 1];

    int tid = threadIdx.x;
    int tx = tid & 15, ty = tid >> 4;
    int m0 = blockIdx.x * BM;
    int n0 = blockIdx.y * BN;

    float acc[4][4];
    #pragma unroll
    for (int i = 0; i < 4; i++)
        #pragma unroll
        for (int j = 0; j < 4; j++) acc[i][j] = 0.f;

    for (int kc = 0; kc < EPAD; kc += BK) {
        for (int i = tid; i < BM * BK; i += 256) {
            int r = i >> 5, c = i & 31;
            Xs[r][c] = X[(size_t)(m0 + r) * EPAD + kc + c];
            Ws[r][c] = W[(size_t)(n0 + r) * EPAD + kc + c];
        }
        __syncthreads();
        #pragma unroll
        for (int kk = 0; kk < BK; kk++) {
            float a[4], bb[4];
            #pragma unroll
            for (int i = 0; i < 4; i++) a[i] = Xs[ty * 4 + i][kk];
            #pragma unroll
            for (int j = 0; j < 4; j++) bb[j] = Ws[tx * 4 + j][kk];
            #pragma unroll
            for (int i = 0; i < 4; i++)
                #pragma unroll
                for (int j = 0; j < 4; j++) acc[i][j] += a[i] * bb[j];
        }
        __syncthreads();
    }
    #pragma unroll
    for (int i = 0; i < 4; i++)
        #pragma unroll
        for (int j = 0; j < 4; j++)
            C[(size_t)(m0 + ty * 4 + i) * GDIM + n0 + tx * 4 + j] = acc[i][j];
}

// ----------------------------- K3: LSTM recurrence (fp32) -------------------
// Batch-parallel: block = (batch chunk of 8, lstm id). No inter-block sync.
#define BCH 8

__global__ __launch_bounds__(512) void lstm_kernel(WPtrs p) {
    __shared__ float h_s[BCH][HDIM];    // 8 KB
    __shared__ float g_s[BCH][GDIM];    // 32 KB

    int lstm = blockIdx.y;                  // 0=sf 1=sb 2=tf 3=tb
    int b0   = blockIdx.x * BCH;
    int T    = (lstm < 2) ? LS : LT;
    bool rev = (lstm & 1);
    const float* __restrict__ WT   = d_WhhT[lstm];
    const float* __restrict__ Xg   = (lstm < 2) ? d_gates_sen[lstm] : d_gates_tgt[lstm - 2];
    float* __restrict__       Hout = (lstm < 2) ? d_h_sen[lstm]     : d_h_tgt[lstm - 2];

    int tid = threadIdx.x;                  // 0..511
    int m   = tid & 255;                    // hidden unit for elementwise
    int kb0 = tid >> 8;                     // 0 or 1

    for (int i = tid; i < BCH * HDIM; i += 512) ((float*)h_s)[i] = 0.f;

    float cst[4] = {0.f, 0.f, 0.f, 0.f};    // c for kb = kb0, kb0+2, kb0+4, kb0+6

    const float bi = p.bih[lstm][m]       + p.bhh[lstm][m];
    const float bf = p.bih[lstm][m + 256] + p.bhh[lstm][m + 256];
    const float bg = p.bih[lstm][m + 512] + p.bhh[lstm][m + 512];
    const float bo = p.bih[lstm][m + 768] + p.bhh[lstm][m + 768];
    __syncthreads();

    for (int step = 0; step < T; step++) {
        int t = rev ? (T - 1 - step) : step;

        // g_s[kb][n] = sum_k h_s[kb][k] * WhhT[k][n]; thread owns n=tid, n=tid+512
        float a0[BCH], a1[BCH];
        #pragma unroll
        for (int kb = 0; kb < BCH; kb++) { a0[kb] = 0.f; a1[kb] = 0.f; }
        for (int k = 0; k < HDIM; k += 4) {
            float4 h4[BCH];
            #pragma unroll
            for (int kb = 0; kb < BCH; kb++)
                h4[kb] = *(const float4*)&h_s[kb][k];
            #pragma unroll
            for (int j = 0; j < 4; j++) {
                float w0 = WT[(size_t)(k + j) * GDIM + tid];
                float w1 = WT[(size_t)(k + j) * GDIM + tid + 512];
                #pragma unroll
                for (int kb = 0; kb < BCH; kb++) {
                    float hv = ((const float*)&h4[kb])[j];
                    a0[kb] += hv * w0;
                    a1[kb] += hv * w1;
                }
            }
        }
        #pragma unroll
        for (int kb = 0; kb < BCH; kb++) {
            g_s[kb][tid]       = a0[kb];
            g_s[kb][tid + 512] = a1[kb];
        }
        __syncthreads();

        const float* xg   = Xg   + (size_t)(t * NB + b0) * GDIM;
        float*       hrow = Hout + (size_t)(t * NB + b0) * HDIM;
        #pragma unroll
        for (int i = 0; i < 4; i++) {
            int kb = kb0 + 2 * i;
            const float* xr = xg + (size_t)kb * GDIM;
            float gi = g_s[kb][m]       + xr[m]       + bi;
            float gf = g_s[kb][m + 256] + xr[m + 256] + bf;
            float gg = g_s[kb][m + 512] + xr[m + 512] + bg;
            float go = g_s[kb][m + 768] + xr[m + 768] + bo;
            float cn = sigf(gf) * cst[i] + sigf(gi) * tanhf(gg);
            cst[i] = cn;
            float hv = sigf(go) * tanhf(cn);
            h_s[kb][m] = hv;
            hrow[(size_t)kb * HDIM + m] = hv;
        }
        __syncthreads();
    }
}

// ----------------------------- K4: attention + output (fp32) ----------------
__global__ __launch_bounds__(256) void attn_kernel(const float* __restrict__ Wout,
                                                   const float* __restrict__ bout,
                                                   float* __restrict__ out) {
    int b = blockIdx.x;
    int tid = threadIdx.x;

    __shared__ float tgt_s[LT][2 * HDIM];
    __shared__ float A_s[LS][LT];
    __shared__ float colmax[LT];
    __shared__ float colsum[LT];
    __shared__ float rowvec[LT];
    __shared__ float attn_s[LS];
    __shared__ float score_s[2 * HDIM];
    __shared__ float logit[NOUT];

    for (int i = tid; i < LT * 2 * HDIM; i += 256) {
        int t = i >> 9;
        int mm = i & 511;
        tgt_s[t][mm] = (mm < HDIM)
            ? d_h_tgt[0][((size_t)t * NB + b) * HDIM + mm]
            : d_h_tgt[1][((size_t)t * NB + b) * HDIM + (mm - HDIM)];
    }
    if (tid < LT) rowvec[tid] = 0.f;
    __syncthreads();

    for (int pidx = tid; pidx < LS * LT; pidx += 256) {
        int s = pidx >> 3;
        int t = pidx & 7;
        const float* f0 = &d_h_sen[0][((size_t)s * NB + b) * HDIM];
        const float* f1 = &d_h_sen[1][((size_t)s * NB + b) * HDIM];
        float acc = 0.f;
        for (int mm = 0; mm < HDIM; mm++) acc += f0[mm] * tgt_s[t][mm];
        for (int mm = 0; mm < HDIM; mm++) acc += f1[mm] * tgt_s[t][HDIM + mm];
        A_s[s][t] = acc;
    }
    __syncthreads();

    if (tid < LT) {
        float mx = -1e30f;
        for (int s = 0; s < LS; s++) mx = fmaxf(mx, A_s[s][tid]);
        float sm = 0.f;
        for (int s = 0; s < LS; s++) sm += expf(A_s[s][tid] - mx);
        colmax[tid] = mx;
        colsum[tid] = sm;
    }
    if (tid < LS) {
        float mx = -1e30f;
        #pragma unroll
        for (int t = 0; t < LT; t++) mx = fmaxf(mx, A_s[tid][t]);
        float e[LT], sm = 0.f;
        #pragma unroll
        for (int t = 0; t < LT; t++) { e[t] = expf(A_s[tid][t] - mx); sm += e[t]; }
        float inv = 1.f / (sm * (float)LS);
        #pragma unroll
        for (int t = 0; t < LT; t++) atomicAdd(&rowvec[t], e[t] * inv);
    }
    __syncthreads();

    if (tid < LS) {
        float a = 0.f;
        #pragma unroll
        for (int t = 0; t < LT; t++)
            a += (expf(A_s[tid][t] - colmax[t]) / colsum[t]) * rowvec[t];
        attn_s[tid] = a;
    }
    __syncthreads();

    for (int mm = tid; mm < 2 * HDIM; mm += 256) {
        const float* hp = (mm < HDIM) ? d_h_sen[0] : d_h_sen[1];
        int m2 = mm & (HDIM - 1);
        float acc = 0.f;
        for (int s = 0; s < LS; s++)
            acc += attn_s[s] * hp[((size_t)s * NB + b) * HDIM + m2];
        score_s[mm] = acc;
    }
    __syncthreads();

    if (tid < NOUT) {
        float acc = bout[tid];
        for (int mm = 0; mm < 2 * HDIM; mm++)
            acc += score_s[mm] * Wout[tid * 2 * HDIM + mm];
        logit[tid] = acc;
    }
    __syncthreads();

    if (tid == 0) {
        float mx = fmaxf(logit[0], fmaxf(logit[1], logit[2]));
        float e0 = expf(logit[0] - mx);
        float e1 = expf(logit[1] - mx);
        float e2 = expf(logit[2] - mx);
        float inv = 1.f / (e0 + e1 + e2);
        out[b * NOUT + 0] = e0 * inv;
        out[b * NOUT + 1] = e1 * inv;
        out[b * NOUT + 2] = e2 * inv;
    }
}

// ----------------------------- launch ---------------------------------------
extern "C" void kernel_launch(void* const* d_in, const int* in_sizes, int n_in,
                              void* d_out, int out_size) {
    const int*   sen_src = (const int*)d_in[0];
    const int*   tgt_src = (const int*)d_in[1];
    const float* emb     = (const float*)d_in[2];
    WPtrs wp;
    for (int l = 0; l < 4; l++) {
        wp.wih[l] = (const float*)d_in[3 + 4 * l];
        wp.whh[l] = (const float*)d_in[4 + 4 * l];
        wp.bih[l] = (const float*)d_in[5 + 4 * l];
        wp.bhh[l] = (const float*)d_in[6 + 4 * l];
    }
    const float* Wout = (const float*)d_in[19];
    const float* bout = (const float*)d_in[20];
    float* out = (float*)d_out;

    prep_kernel<<<dim3(256, 4), 256>>>(wp);
    embed_kernel<<<(LS + LT) * NB, EPAD>>>(sen_src, tgt_src, emb);
    gemm_xw<<<dim3(LS * NB / BM, GDIM / BN), 256>>>(0);
    gemm_xw<<<dim3(LS * NB / BM, GDIM / BN), 256>>>(1);
    gemm_xw<<<dim3(LT * NB / BM, GDIM / BN), 256>>>(2);
    gemm_xw<<<dim3(LT * NB / BM, GDIM / BN), 256>>>(3);
    lstm_kernel<<<dim3(NB / BCH, 4), 512>>>(wp);
    attn_kernel<<<NB, 256>>>(Wout, bout, out);
}

// round 8
// speedup vs baseline: 1.2149x; 1.2149x over previous
#include <cuda_runtime.h>
#include <cuda_bf16.h>
#include <math.h>
#include <mma.h>

using namespace nvcuda;

#define NB   128   // batch
#define LS   128   // sentence length
#define LT   8     // target length
#define EDIM 300   // true embedding dim (E=300)
#define EPAD 320   // padded embedding dim
#define HDIM 256
#define GDIM 1024  // 4*H
#define NOUT 3

// ----------------------------- scratch (static __device__, no allocs) ------
__device__ __align__(128) __nv_bfloat16 d_x_sen[LS * NB * EPAD];   // [t][b][e] zero-pad
__device__ __align__(128) __nv_bfloat16 d_x_tgt[LT * NB * EPAD];
__device__ __align__(128) __nv_bfloat16 d_Wih[4][GDIM * EPAD];     // zero-pad [n][k]
__device__ __align__(128) __nv_bfloat16 d_Whh[4][GDIM * HDIM];     // [n][k] row-major
__device__ __align__(128) float d_bias[4][GDIM];                   // bih+bhh
__device__ __align__(128) float d_gates_sen[2][LS * NB * GDIM];
__device__ __align__(128) float d_gates_tgt[2][LT * NB * GDIM];
__device__ __align__(128) float d_h_sen[2][LS * NB * HDIM];        // [t][b][h]
__device__ __align__(128) float d_h_tgt[2][LT * NB * HDIM];

struct WPtrs {
    const float* wih[4];
    const float* whh[4];
    const float* bih[4];
    const float* bhh[4];
};

__device__ __forceinline__ float sigf(float x) { return 1.f / (1.f + expf(-x)); }

// ----------------------------- K0: weight prep ------------------------------
__global__ void prep_kernel(WPtrs p) {
    int l = blockIdx.y;
    int stride = gridDim.x * blockDim.x;
    int start = blockIdx.x * blockDim.x + threadIdx.x;
    for (int i = start; i < GDIM * EPAD; i += stride) {
        int n = i / EPAD;
        int k = i - n * EPAD;
        d_Wih[l][i] = __float2bfloat16_rn((k < EDIM) ? p.wih[l][(size_t)n * EDIM + k] : 0.f);
    }
    for (int i = start; i < GDIM * HDIM; i += stride)
        d_Whh[l][i] = __float2bfloat16_rn(p.whh[l][i]);
    for (int i = start; i < GDIM; i += stride)
        d_bias[l][i] = p.bih[l][i] + p.bhh[l][i];
}

// ----------------------------- K1: embedding gather -------------------------
__global__ void embed_kernel(const int* __restrict__ sen_src,
                             const int* __restrict__ tgt_src,
                             const float* __restrict__ emb) {
    int row = blockIdx.x;
    int tid = threadIdx.x;  // 320 threads == EPAD
    if (row < LS * NB) {
        int t = row / NB, b = row % NB;
        int idx = sen_src[b * LS + t];
        float v = (idx == 0 || tid >= EDIM) ? 0.f : emb[(size_t)idx * EDIM + tid];
        d_x_sen[(size_t)row * EPAD + tid] = __float2bfloat16_rn(v);
    } else {
        int r = row - LS * NB;
        int t = r / NB, b = r % NB;
        int idx = tgt_src[b * LT + t];
        float v = (idx == 0 || tid >= EDIM) ? 0.f : emb[(size_t)idx * EDIM + tid];
        d_x_tgt[(size_t)r * EPAD + tid] = __float2bfloat16_rn(v);
    }
}

// ----------------------------- K2: input projection GEMM (bf16 wmma) --------
// C[M,1024] = X[M,320] @ W[1024,320]^T   (bf16 in, fp32 accum)
#define GBM 128
#define GBN 128
#define GBK 64
#define GLD 72   // padded smem leading dim (mult of 8)

__global__ __launch_bounds__(256) void gemm_xw(int l) {
    const __nv_bfloat16* __restrict__ X = (l < 2) ? d_x_sen : d_x_tgt;
    const __nv_bfloat16* __restrict__ W = d_Wih[l];
    float* __restrict__ C = (l < 2) ? d_gates_sen[l] : d_gates_tgt[l - 2];

    __shared__ __align__(128) __nv_bfloat16 As[GBM * GLD];
    __shared__ __align__(128) __nv_bfloat16 Bs[GBN * GLD];

    int tid = threadIdx.x;
    int warp = tid >> 5;
    int wm = warp & 1;        // 2 warps along M (64 rows each)
    int wn = warp >> 1;       // 4 warps along N (32 cols each)
    int m0 = blockIdx.x * GBM;
    int n0 = blockIdx.y * GBN;

    wmma::fragment<wmma::accumulator, 16, 16, 16, float> acc[4][2];
    #pragma unroll
    for (int mi = 0; mi < 4; mi++)
        #pragma unroll
        for (int ni = 0; ni < 2; ni++) wmma::fill_fragment(acc[mi][ni], 0.f);

    for (int kc = 0; kc < EPAD; kc += GBK) {
        int r0 = tid >> 3;
        int c  = (tid & 7) * 8;
        #pragma unroll
        for (int i = 0; i < 4; i++) {
            int r = r0 + i * 32;
            *(uint4*)&As[r * GLD + c] =
                *(const uint4*)&X[(size_t)(m0 + r) * EPAD + kc + c];
            *(uint4*)&Bs[r * GLD + c] =
                *(const uint4*)&W[(size_t)(n0 + r) * EPAD + kc + c];
        }
        __syncthreads();
        #pragma unroll
        for (int kk = 0; kk < GBK; kk += 16) {
            wmma::fragment<wmma::matrix_a, 16, 16, 16, __nv_bfloat16, wmma::row_major> af[4];
            wmma::fragment<wmma::matrix_b, 16, 16, 16, __nv_bfloat16, wmma::col_major> bf[2];
            #pragma unroll
            for (int mi = 0; mi < 4; mi++)
                wmma::load_matrix_sync(af[mi], &As[(wm * 64 + mi * 16) * GLD + kk], GLD);
            #pragma unroll
            for (int ni = 0; ni < 2; ni++)
                wmma::load_matrix_sync(bf[ni], &Bs[(wn * 32 + ni * 16) * GLD + kk], GLD);
            #pragma unroll
            for (int mi = 0; mi < 4; mi++)
                #pragma unroll
                for (int ni = 0; ni < 2; ni++)
                    wmma::mma_sync(acc[mi][ni], af[mi], bf[ni], acc[mi][ni]);
        }
        __syncthreads();
    }
    #pragma unroll
    for (int mi = 0; mi < 4; mi++)
        #pragma unroll
        for (int ni = 0; ni < 2; ni++)
            wmma::store_matrix_sync(
                &C[(size_t)(m0 + wm * 64 + mi * 16) * GDIM + n0 + wn * 32 + ni * 16],
                acc[mi][ni], GDIM, wmma::mem_row_major);
}

// ----------------------------- K3: LSTM recurrence (bf16 wmma) --------------
// Batch-parallel: block = (batch chunk of 16, lstm id). No inter-block sync.
#define BCH   16
#define HS_LD 264
#define LSTM_SMEM (BCH * GDIM * 4 + BCH * HS_LD * 2)  // 65536 + 8448 = 73984

__global__ __launch_bounds__(256) void lstm_kernel() {
    extern __shared__ __align__(128) unsigned char smem[];
    float*         gates_s = (float*)smem;                               // [16][1024]
    __nv_bfloat16* h_s     = (__nv_bfloat16*)(smem + BCH * GDIM * 4);    // [16][264]

    int lstm = blockIdx.y;                  // 0=sf 1=sb 2=tf 3=tb
    int b0   = blockIdx.x * BCH;
    int T    = (lstm < 2) ? LS : LT;
    bool rev = (lstm & 1);
    const __nv_bfloat16* __restrict__ Whh = d_Whh[lstm];
    const float* __restrict__ Xg   = (lstm < 2) ? d_gates_sen[lstm] : d_gates_tgt[lstm - 2];
    float* __restrict__       Hout = (lstm < 2) ? d_h_sen[lstm]     : d_h_tgt[lstm - 2];

    int tid  = threadIdx.x;
    int warp = tid >> 5;

    for (int i = tid; i < BCH * HS_LD; i += 256) h_s[i] = __float2bfloat16_rn(0.f);
    float c[BCH];
    #pragma unroll
    for (int k = 0; k < BCH; k++) c[k] = 0.f;

    const float bi  = d_bias[lstm][tid];
    const float bf_ = d_bias[lstm][tid + 256];
    const float bg  = d_bias[lstm][tid + 512];
    const float bo  = d_bias[lstm][tid + 768];
    __syncthreads();

    for (int step = 0; step < T; step++) {
        int t = rev ? (T - 1 - step) : step;

        // gates_s[16, warp*128 : warp*128+128] = h_s @ Whh^T  (warp's N slice)
        wmma::fragment<wmma::accumulator, 16, 16, 16, float> acc[8];
        #pragma unroll
        for (int nf = 0; nf < 8; nf++) wmma::fill_fragment(acc[nf], 0.f);
        #pragma unroll
        for (int kk = 0; kk < HDIM; kk += 16) {
            wmma::fragment<wmma::matrix_a, 16, 16, 16, __nv_bfloat16, wmma::row_major> af;
            wmma::load_matrix_sync(af, &h_s[kk], HS_LD);
            #pragma unroll
            for (int nf = 0; nf < 8; nf++) {
                wmma::fragment<wmma::matrix_b, 16, 16, 16, __nv_bfloat16, wmma::col_major> bfr;
                wmma::load_matrix_sync(bfr, &Whh[(size_t)(warp * 128 + nf * 16) * HDIM + kk], HDIM);
                wmma::mma_sync(acc[nf], af, bfr, acc[nf]);
            }
        }
        #pragma unroll
        for (int nf = 0; nf < 8; nf++)
            wmma::store_matrix_sync(&gates_s[warp * 128 + nf * 16], acc[nf], GDIM,
                                    wmma::mem_row_major);
        __syncthreads();

        // elementwise: thread owns hidden unit m=tid for all 16 local batch rows
        const float* xg   = Xg   + (size_t)(t * NB + b0) * GDIM;
        float*       hrow = Hout + (size_t)(t * NB + b0) * HDIM;
        #pragma unroll
        for (int k = 0; k < BCH; k++) {
            const float* xr = xg + (size_t)k * GDIM;
            float gi = gates_s[k * GDIM + tid      ] + xr[tid      ] + bi;
            float gf = gates_s[k * GDIM + tid + 256] + xr[tid + 256] + bf_;
            float gg = gates_s[k * GDIM + tid + 512] + xr[tid + 512] + bg;
            float go = gates_s[k * GDIM + tid + 768] + xr[tid + 768] + bo;
            float cn = sigf(gf) * c[k] + sigf(gi) * tanhf(gg);
            c[k] = cn;
            float hv = sigf(go) * tanhf(cn);
            h_s[k * HS_LD + tid] = __float2bfloat16_rn(hv);
            hrow[(size_t)k * HDIM + tid] = hv;
        }
        __syncthreads();
    }
}

// ----------------------------- K4: attention + output (fp32) ----------------
__global__ __launch_bounds__(256) void attn_kernel(const float* __restrict__ Wout,
                                                   const float* __restrict__ bout,
                                                   float* __restrict__ out) {
    int b = blockIdx.x;
    int tid = threadIdx.x;
    int lane = tid & 31, warp = tid >> 5;

    __shared__ float tgt_s[LT][2 * HDIM];
    __shared__ float A_s[LS][LT];
    __shared__ float colmax[LT];
    __shared__ float colsum[LT];
    __shared__ float rowvec[LT];
    __shared__ float attn_s[LS];
    __shared__ float score_s[2 * HDIM];
    __shared__ float logit[NOUT];

    for (int i = tid; i < LT * 2 * HDIM; i += 256) {
        int t = i >> 9;
        int mm = i & 511;
        tgt_s[t][mm] = (mm < HDIM)
            ? d_h_tgt[0][((size_t)t * NB + b) * HDIM + mm]
            : d_h_tgt[1][((size_t)t * NB + b) * HDIM + (mm - HDIM)];
    }
    if (tid < LT) rowvec[tid] = 0.f;
    __syncthreads();

    // A[s][t] via warp-parallel dot products (8 warps x 16 s-rows each)
    for (int s = warp; s < LS; s += 8) {
        float p[LT];
        #pragma unroll
        for (int t = 0; t < LT; t++) p[t] = 0.f;
        const float* f0 = &d_h_sen[0][((size_t)s * NB + b) * HDIM];
        const float* f1 = &d_h_sen[1][((size_t)s * NB + b) * HDIM];
        for (int mm = lane; mm < HDIM; mm += 32) {
            float v0 = f0[mm], v1 = f1[mm];
            #pragma unroll
            for (int t = 0; t < LT; t++)
                p[t] += v0 * tgt_s[t][mm] + v1 * tgt_s[t][HDIM + mm];
        }
        #pragma unroll
        for (int t = 0; t < LT; t++) {
            #pragma unroll
            for (int o = 16; o; o >>= 1) p[t] += __shfl_xor_sync(0xffffffffu, p[t], o);
            if (lane == 0) A_s[s][t] = p[t];
        }
    }
    __syncthreads();

    if (tid < LT) {
        float mx = -1e30f;
        for (int s = 0; s < LS; s++) mx = fmaxf(mx, A_s[s][tid]);
        float sm = 0.f;
        for (int s = 0; s < LS; s++) sm += expf(A_s[s][tid] - mx);
        colmax[tid] = mx;
        colsum[tid] = sm;
    }
    if (tid < LS) {
        float mx = -1e30f;
        #pragma unroll
        for (int t = 0; t < LT; t++) mx = fmaxf(mx, A_s[tid][t]);
        float e[LT], sm = 0.f;
        #pragma unroll
        for (int t = 0; t < LT; t++) { e[t] = expf(A_s[tid][t] - mx); sm += e[t]; }
        float inv = 1.f / (sm * (float)LS);
        #pragma unroll
        for (int t = 0; t < LT; t++) atomicAdd(&rowvec[t], e[t] * inv);
    }
    __syncthreads();

    if (tid < LS) {
        float a = 0.f;
        #pragma unroll
        for (int t = 0; t < LT; t++)
            a += (expf(A_s[tid][t] - colmax[t]) / colsum[t]) * rowvec[t];
        attn_s[tid] = a;
    }
    __syncthreads();

    for (int mm = tid; mm < 2 * HDIM; mm += 256) {
        const float* hp = (mm < HDIM) ? d_h_sen[0] : d_h_sen[1];
        int m2 = mm & (HDIM - 1);
        float acc = 0.f;
        for (int s = 0; s < LS; s++)
            acc += attn_s[s] * hp[((size_t)s * NB + b) * HDIM + m2];
        score_s[mm] = acc;
    }
    __syncthreads();

    if (warp < NOUT) {
        float acc = 0.f;
        for (int mm = lane; mm < 2 * HDIM; mm += 32)
            acc += score_s[mm] * Wout[warp * 2 * HDIM + mm];
        #pragma unroll
        for (int o = 16; o; o >>= 1) acc += __shfl_xor_sync(0xffffffffu, acc, o);
        if (lane == 0) logit[warp] = acc + bout[warp];
    }
    __syncthreads();

    if (tid == 0) {
        float mx = fmaxf(logit[0], fmaxf(logit[1], logit[2]));
        float e0 = expf(logit[0] - mx);
        float e1 = expf(logit[1] - mx);
        float e2 = expf(logit[2] - mx);
        float inv = 1.f / (e0 + e1 + e2);
        out[b * NOUT + 0] = e0 * inv;
        out[b * NOUT + 1] = e1 * inv;
        out[b * NOUT + 2] = e2 * inv;
    }
}

// ----------------------------- launch ---------------------------------------
extern "C" void kernel_launch(void* const* d_in, const int* in_sizes, int n_in,
                              void* d_out, int out_size) {
    const int*   sen_src = (const int*)d_in[0];
    const int*   tgt_src = (const int*)d_in[1];
    const float* emb     = (const float*)d_in[2];
    WPtrs wp;
    for (int l = 0; l < 4; l++) {
        wp.wih[l] = (const float*)d_in[3 + 4 * l];
        wp.whh[l] = (const float*)d_in[4 + 4 * l];
        wp.bih[l] = (const float*)d_in[5 + 4 * l];
        wp.bhh[l] = (const float*)d_in[6 + 4 * l];
    }
    const float* Wout = (const float*)d_in[19];
    const float* bout = (const float*)d_in[20];
    float* out = (float*)d_out;

    cudaFuncSetAttribute(lstm_kernel, cudaFuncAttributeMaxDynamicSharedMemorySize, LSTM_SMEM);

    prep_kernel<<<dim3(256, 4), 256>>>(wp);
    embed_kernel<<<(LS + LT) * NB, EPAD>>>(sen_src, tgt_src, emb);
    gemm_xw<<<dim3(LS * NB / GBM, GDIM / GBN), 256>>>(0);
    gemm_xw<<<dim3(LS * NB / GBM, GDIM / GBN), 256>>>(1);
    gemm_xw<<<dim3(LT * NB / GBM, GDIM / GBN), 256>>>(2);
    gemm_xw<<<dim3(LT * NB / GBM, GDIM / GBN), 256>>>(3);
    lstm_kernel<<<dim3(NB / BCH, 4), 256, LSTM_SMEM>>>();
    attn_kernel<<<NB, 256>>>(Wout, bout, out);
}

// round 10
// speedup vs baseline: 5.2867x; 4.3516x over previous
#include <cuda_runtime.h>
#include <cuda_bf16.h>
#include <cstdint>
#include <math.h>
#include <mma.h>

using namespace nvcuda;

#define NB   128   // batch
#define LS   128   // sentence length
#define LT   8     // target length
#define EDIM 300   // true embedding dim (E=300)
#define EPAD 320   // padded embedding dim
#define HDIM 256
#define GDIM 1024  // 4*H
#define NOUT 3

// ----------------------------- scratch (static __device__, no allocs) ------
__device__ __align__(128) __nv_bfloat16 d_x_sen[LS * NB * EPAD];   // [t][b][e] zero-pad
__device__ __align__(128) __nv_bfloat16 d_x_tgt[LT * NB * EPAD];
__device__ __align__(128) __nv_bfloat16 d_Wih[4][GDIM * EPAD];     // zero-pad [n][k]
__device__ __align__(128) __nv_bfloat16 d_Whh[4][GDIM * HDIM];     // [n][k] row-major
__device__ __align__(128) float d_bias[4][GDIM];                   // bih+bhh
__device__ __align__(128) float d_gates_sen[2][LS * NB * GDIM];
__device__ __align__(128) float d_gates_tgt[2][LT * NB * GDIM];
__device__ __align__(128) float d_h_sen[2][LS * NB * HDIM];        // [t][b][h]
__device__ __align__(128) float d_h_tgt[2][LT * NB * HDIM];

struct WPtrs {
    const float* wih[4];
    const float* whh[4];
    const float* bih[4];
    const float* bhh[4];
};

__device__ __forceinline__ float sigf(float x) { return 1.f / (1.f + expf(-x)); }

__device__ __forceinline__ uint32_t smem_u32(const void* p) {
    uint32_t a;
    asm("{ .reg .u64 t; cvta.to.shared.u64 t, %1; cvt.u32.u64 %0, t; }" : "=r"(a) : "l"(p));
    return a;
}
__device__ __forceinline__ uint32_t cluster_rank() {
    uint32_t r;
    asm("mov.u32 %0, %%cluster_ctarank;" : "=r"(r));
    return r;
}
__device__ __forceinline__ void st_dsmem_bf16(uint32_t laddr, uint32_t rank, __nv_bfloat16 v) {
    unsigned short s = *reinterpret_cast<unsigned short*>(&v);
    asm volatile(
        "{\n\t.reg .b32 ra;\n\t"
        "mapa.shared::cluster.u32 ra, %0, %1;\n\t"
        "st.shared::cluster.b16 [ra], %2;\n\t}"
        :: "r"(laddr), "r"(rank), "h"(s) : "memory");
}
#define CLUSTER_SYNC() do { \
    asm volatile("barrier.cluster.arrive.aligned;" ::: "memory"); \
    asm volatile("barrier.cluster.wait.aligned;" ::: "memory"); \
} while (0)

// ----------------------------- K0: weight prep ------------------------------
__global__ void prep_kernel(WPtrs p) {
    int l = blockIdx.y;
    int stride = gridDim.x * blockDim.x;
    int start = blockIdx.x * blockDim.x + threadIdx.x;
    for (int i = start; i < GDIM * EPAD; i += stride) {
        int n = i / EPAD;
        int k = i - n * EPAD;
        d_Wih[l][i] = __float2bfloat16_rn((k < EDIM) ? p.wih[l][(size_t)n * EDIM + k] : 0.f);
    }
    for (int i = start; i < GDIM * HDIM; i += stride)
        d_Whh[l][i] = __float2bfloat16_rn(p.whh[l][i]);
    for (int i = start; i < GDIM; i += stride)
        d_bias[l][i] = p.bih[l][i] + p.bhh[l][i];
}

// ----------------------------- K1: embedding gather -------------------------
__global__ void embed_kernel(const int* __restrict__ sen_src,
                             const int* __restrict__ tgt_src,
                             const float* __restrict__ emb) {
    int row = blockIdx.x;
    int tid = threadIdx.x;  // 320 threads == EPAD
    if (row < LS * NB) {
        int t = row / NB, b = row % NB;
        int idx = sen_src[b * LS + t];
        float v = (idx == 0 || tid >= EDIM) ? 0.f : emb[(size_t)idx * EDIM + tid];
        d_x_sen[(size_t)row * EPAD + tid] = __float2bfloat16_rn(v);
    } else {
        int r = row - LS * NB;
        int t = r / NB, b = r % NB;
        int idx = tgt_src[b * LT + t];
        float v = (idx == 0 || tid >= EDIM) ? 0.f : emb[(size_t)idx * EDIM + tid];
        d_x_tgt[(size_t)r * EPAD + tid] = __float2bfloat16_rn(v);
    }
}

// ----------------------------- K2: input projection GEMM (bf16 wmma) --------
#define GBM 128
#define GBN 128
#define GBK 64
#define GLD 72

__global__ __launch_bounds__(256) void gemm_xw(int l) {
    const __nv_bfloat16* __restrict__ X = (l < 2) ? d_x_sen : d_x_tgt;
    const __nv_bfloat16* __restrict__ W = d_Wih[l];
    float* __restrict__ C = (l < 2) ? d_gates_sen[l] : d_gates_tgt[l - 2];

    __shared__ __align__(128) __nv_bfloat16 As[GBM * GLD];
    __shared__ __align__(128) __nv_bfloat16 Bs[GBN * GLD];

    int tid = threadIdx.x;
    int warp = tid >> 5;
    int wm = warp & 1;
    int wn = warp >> 1;
    int m0 = blockIdx.x * GBM;
    int n0 = blockIdx.y * GBN;

    wmma::fragment<wmma::accumulator, 16, 16, 16, float> acc[4][2];
    #pragma unroll
    for (int mi = 0; mi < 4; mi++)
        #pragma unroll
        for (int ni = 0; ni < 2; ni++) wmma::fill_fragment(acc[mi][ni], 0.f);

    for (int kc = 0; kc < EPAD; kc += GBK) {
        int r0 = tid >> 3;
        int c  = (tid & 7) * 8;
        #pragma unroll
        for (int i = 0; i < 4; i++) {
            int r = r0 + i * 32;
            *(uint4*)&As[r * GLD + c] = *(const uint4*)&X[(size_t)(m0 + r) * EPAD + kc + c];
            *(uint4*)&Bs[r * GLD + c] = *(const uint4*)&W[(size_t)(n0 + r) * EPAD + kc + c];
        }
        __syncthreads();
        #pragma unroll
        for (int kk = 0; kk < GBK; kk += 16) {
            wmma::fragment<wmma::matrix_a, 16, 16, 16, __nv_bfloat16, wmma::row_major> af[4];
            wmma::fragment<wmma::matrix_b, 16, 16, 16, __nv_bfloat16, wmma::col_major> bf[2];
            #pragma unroll
            for (int mi = 0; mi < 4; mi++)
                wmma::load_matrix_sync(af[mi], &As[(wm * 64 + mi * 16) * GLD + kk], GLD);
            #pragma unroll
            for (int ni = 0; ni < 2; ni++)
                wmma::load_matrix_sync(bf[ni], &Bs[(wn * 32 + ni * 16) * GLD + kk], GLD);
            #pragma unroll
            for (int mi = 0; mi < 4; mi++)
                #pragma unroll
                for (int ni = 0; ni < 2; ni++)
                    wmma::mma_sync(acc[mi][ni], af[mi], bf[ni], acc[mi][ni]);
        }
        __syncthreads();
    }
    #pragma unroll
    for (int mi = 0; mi < 4; mi++)
        #pragma unroll
        for (int ni = 0; ni < 2; ni++)
            wmma::store_matrix_sync(
                &C[(size_t)(m0 + wm * 64 + mi * 16) * GDIM + n0 + wn * 32 + ni * 16],
                acc[mi][ni], GDIM, wmma::mem_row_major);
}

// ----------------------------- K3: LSTM recurrence (cluster, Whh-resident) --
// Cluster of 4 CTAs per (lstm, batch-chunk-of-16). CTA rank r owns hidden
// units [r*64, r*64+64): keeps its 256 Whh rows in smem; exchanges its h
// slice each step via DSMEM. One cluster sync per step (double-buffered h).
#define BCH    16
#define SLC    64                       // hidden units per CTA
#define WLD    264                      // smem leading dim (bf16)
#define W_SZ   (256 * WLD * 2)          // 135168 B
#define H_SZ   (BCH * WLD * 2)          // 8448 B per h buffer
#define G_SZ   (BCH * WLD * 4)          // 16896 B (fp32 gates, ld 264)
#define LSTM_SMEM (W_SZ + 2 * H_SZ + G_SZ)   // 168960 B

__global__ void __cluster_dims__(4, 1, 1) __launch_bounds__(256, 1) lstm_kernel() {
    extern __shared__ __align__(128) unsigned char smem[];
    __nv_bfloat16* Wsh  = (__nv_bfloat16*)smem;                       // [256][264]
    __nv_bfloat16* hbuf = (__nv_bfloat16*)(smem + W_SZ);              // [2][16][264]
    float*         gates = (float*)(smem + W_SZ + 2 * H_SZ);          // [16][264]

    int bx   = blockIdx.x;
    int cid  = bx >> 2;                 // cluster id 0..31
    int lstm = cid >> 3;                // 0=sf 1=sb 2=tf 3=tb
    int b0   = (cid & 7) * BCH;
    uint32_t r = cluster_rank();        // 0..3
    int T    = (lstm < 2) ? LS : LT;
    bool rev = (lstm & 1);
    const __nv_bfloat16* __restrict__ Wg = d_Whh[lstm];
    const float* __restrict__ Xg   = (lstm < 2) ? d_gates_sen[lstm] : d_gates_tgt[lstm - 2];
    float* __restrict__       Hout = (lstm < 2) ? d_h_sen[lstm]     : d_h_tgt[lstm - 2];

    int tid  = threadIdx.x;
    int warp = tid >> 5;
    int u    = tid & 63;                // hidden unit within slice
    int kbg  = tid >> 6;                // batch group 0..3
    int r64u = (int)r * SLC + u;        // global hidden unit

    // ---- load resident Whh slice: local row lr = g*64+u  <- global row g*256+r64u
    for (int i = tid; i < 256 * 32; i += 256) {
        int lr = i >> 5;
        int c8 = i & 31;
        int n  = ((lr >> 6) << 8) + (int)r * SLC + (lr & 63);
        *(uint4*)&Wsh[lr * WLD + c8 * 8] = *(const uint4*)&Wg[(size_t)n * HDIM + c8 * 8];
    }
    // ---- zero both h buffers
    for (int i = tid; i < 2 * BCH * WLD; i += 256) hbuf[i] = __float2bfloat16_rn(0.f);

    float c[4] = {0.f, 0.f, 0.f, 0.f};
    const float bi  = d_bias[lstm][r64u];
    const float bf_ = d_bias[lstm][r64u + 256];
    const float bg  = d_bias[lstm][r64u + 512];
    const float bo  = d_bias[lstm][r64u + 768];

    uint32_t hbase_u32 = smem_u32(hbuf);
    __syncthreads();
    CLUSTER_SYNC();

    for (int step = 0; step < T; step++) {
        int t = rev ? (T - 1 - step) : step;
        const __nv_bfloat16* hcur = hbuf + (step & 1) * (BCH * WLD);
        uint32_t hnxt_u32 = hbase_u32 + (uint32_t)(((step & 1) ^ 1) * H_SZ);

        // ---- gates[16][w*32 .. +32] = hcur @ Wsh^T  (warp's 32-col slice)
        {
            wmma::fragment<wmma::matrix_a, 16, 16, 16, __nv_bfloat16, wmma::row_major> af[16];
            #pragma unroll
            for (int kk = 0; kk < 16; kk++)
                wmma::load_matrix_sync(af[kk], &hcur[kk * 16], WLD);
            #pragma unroll
            for (int nf = 0; nf < 2; nf++) {
                wmma::fragment<wmma::accumulator, 16, 16, 16, float> acc;
                wmma::fill_fragment(acc, 0.f);
                #pragma unroll
                for (int kk = 0; kk < 16; kk++) {
                    wmma::fragment<wmma::matrix_b, 16, 16, 16, __nv_bfloat16, wmma::col_major> bfr;
                    wmma::load_matrix_sync(bfr, &Wsh[(warp * 32 + nf * 16) * WLD + kk * 16], WLD);
                    wmma::mma_sync(acc, af[kk], bfr, acc);
                }
                wmma::store_matrix_sync(&gates[warp * 32 + nf * 16], acc, WLD,
                                        wmma::mem_row_major);
            }
        }
        __syncthreads();

        // ---- elementwise for this CTA's 64 units x 16 batch (4 per thread)
        const float* xgt = Xg + (size_t)(t * NB + b0) * GDIM;
        #pragma unroll
        for (int j = 0; j < 4; j++) {
            int kb = j * 4 + kbg;
            const float* xr = xgt + (size_t)kb * GDIM;
            float gi = gates[kb * WLD + u]       + xr[r64u]       + bi;
            float gf = gates[kb * WLD + 64 + u]  + xr[r64u + 256] + bf_;
            float gg = gates[kb * WLD + 128 + u] + xr[r64u + 512] + bg;
            float go = gates[kb * WLD + 192 + u] + xr[r64u + 768] + bo;
            float cn = sigf(gf) * c[j] + sigf(gi) * tanhf(gg);
            c[j] = cn;
            float hv = sigf(go) * tanhf(cn);
            __nv_bfloat16 hb = __float2bfloat16_rn(hv);
            uint32_t off = hnxt_u32 + (uint32_t)(kb * WLD + r64u) * 2u;
            #pragma unroll
            for (uint32_t rk = 0; rk < 4; rk++) st_dsmem_bf16(off, rk, hb);
            Hout[(size_t)(t * NB + b0 + kb) * HDIM + r64u] = hv;
        }
        CLUSTER_SYNC();
    }
}

// ----------------------------- K4: attention + output (fp32) ----------------
__global__ __launch_bounds__(256) void attn_kernel(const float* __restrict__ Wout,
                                                   const float* __restrict__ bout,
                                                   float* __restrict__ out) {
    int b = blockIdx.x;
    int tid = threadIdx.x;
    int lane = tid & 31, warp = tid >> 5;

    __shared__ float tgt_s[LT][2 * HDIM];
    __shared__ float A_s[LS][LT];
    __shared__ float colmax[LT];
    __shared__ float colsum[LT];
    __shared__ float rowvec[LT];
    __shared__ float attn_s[LS];
    __shared__ float score_s[2 * HDIM];
    __shared__ float logit[NOUT];

    for (int i = tid; i < LT * 2 * HDIM; i += 256) {
        int t = i >> 9;
        int mm = i & 511;
        tgt_s[t][mm] = (mm < HDIM)
            ? d_h_tgt[0][((size_t)t * NB + b) * HDIM + mm]
            : d_h_tgt[1][((size_t)t * NB + b) * HDIM + (mm - HDIM)];
    }
    if (tid < LT) rowvec[tid] = 0.f;
    __syncthreads();

    for (int s = warp; s < LS; s += 8) {
        float p[LT];
        #pragma unroll
        for (int t = 0; t < LT; t++) p[t] = 0.f;
        const float* f0 = &d_h_sen[0][((size_t)s * NB + b) * HDIM];
        const float* f1 = &d_h_sen[1][((size_t)s * NB + b) * HDIM];
        for (int mm = lane; mm < HDIM; mm += 32) {
            float v0 = f0[mm], v1 = f1[mm];
            #pragma unroll
            for (int t = 0; t < LT; t++)
                p[t] += v0 * tgt_s[t][mm] + v1 * tgt_s[t][HDIM + mm];
        }
        #pragma unroll
        for (int t = 0; t < LT; t++) {
            #pragma unroll
            for (int o = 16; o; o >>= 1) p[t] += __shfl_xor_sync(0xffffffffu, p[t], o);
            if (lane == 0) A_s[s][t] = p[t];
        }
    }
    __syncthreads();

    if (tid < LT) {
        float mx = -1e30f;
        for (int s = 0; s < LS; s++) mx = fmaxf(mx, A_s[s][tid]);
        float sm = 0.f;
        for (int s = 0; s < LS; s++) sm += expf(A_s[s][tid] - mx);
        colmax[tid] = mx;
        colsum[tid] = sm;
    }
    if (tid < LS) {
        float mx = -1e30f;
        #pragma unroll
        for (int t = 0; t < LT; t++) mx = fmaxf(mx, A_s[tid][t]);
        float e[LT], sm = 0.f;
        #pragma unroll
        for (int t = 0; t < LT; t++) { e[t] = expf(A_s[tid][t] - mx); sm += e[t]; }
        float inv = 1.f / (sm * (float)LS);
        #pragma unroll
        for (int t = 0; t < LT; t++) atomicAdd(&rowvec[t], e[t] * inv);
    }
    __syncthreads();

    if (tid < LS) {
        float a = 0.f;
        #pragma unroll
        for (int t = 0; t < LT; t++)
            a += (expf(A_s[tid][t] - colmax[t]) / colsum[t]) * rowvec[t];
        attn_s[tid] = a;
    }
    __syncthreads();

    for (int mm = tid; mm < 2 * HDIM; mm += 256) {
        const float* hp = (mm < HDIM) ? d_h_sen[0] : d_h_sen[1];
        int m2 = mm & (HDIM - 1);
        float acc = 0.f;
        for (int s = 0; s < LS; s++)
            acc += attn_s[s] * hp[((size_t)s * NB + b) * HDIM + m2];
        score_s[mm] = acc;
    }
    __syncthreads();

    if (warp < NOUT) {
        float acc = 0.f;
        for (int mm = lane; mm < 2 * HDIM; mm += 32)
            acc += score_s[mm] * Wout[warp * 2 * HDIM + mm];
        #pragma unroll
        for (int o = 16; o; o >>= 1) acc += __shfl_xor_sync(0xffffffffu, acc, o);
        if (lane == 0) logit[warp] = acc + bout[warp];
    }
    __syncthreads();

    if (tid == 0) {
        float mx = fmaxf(logit[0], fmaxf(logit[1], logit[2]));
        float e0 = expf(logit[0] - mx);
        float e1 = expf(logit[1] - mx);
        float e2 = expf(logit[2] - mx);
        float inv = 1.f / (e0 + e1 + e2);
        out[b * NOUT + 0] = e0 * inv;
        out[b * NOUT + 1] = e1 * inv;
        out[b * NOUT + 2] = e2 * inv;
    }
}

// ----------------------------- launch ---------------------------------------
extern "C" void kernel_launch(void* const* d_in, const int* in_sizes, int n_in,
                              void* d_out, int out_size) {
    const int*   sen_src = (const int*)d_in[0];
    const int*   tgt_src = (const int*)d_in[1];
    const float* emb     = (const float*)d_in[2];
    WPtrs wp;
    for (int l = 0; l < 4; l++) {
        wp.wih[l] = (const float*)d_in[3 + 4 * l];
        wp.whh[l] = (const float*)d_in[4 + 4 * l];
        wp.bih[l] = (const float*)d_in[5 + 4 * l];
        wp.bhh[l] = (const float*)d_in[6 + 4 * l];
    }
    const float* Wout = (const float*)d_in[19];
    const float* bout = (const float*)d_in[20];
    float* out = (float*)d_out;

    cudaFuncSetAttribute(lstm_kernel, cudaFuncAttributeMaxDynamicSharedMemorySize, LSTM_SMEM);

    prep_kernel<<<dim3(256, 4), 256>>>(wp);
    embed_kernel<<<(LS + LT) * NB, EPAD>>>(sen_src, tgt_src, emb);
    gemm_xw<<<dim3(LS * NB / GBM, GDIM / GBN), 256>>>(0);
    gemm_xw<<<dim3(LS * NB / GBM, GDIM / GBN), 256>>>(1);
    gemm_xw<<<dim3(LT * NB / GBM, GDIM / GBN), 256>>>(2);
    gemm_xw<<<dim3(LT * NB / GBM, GDIM / GBN), 256>>>(3);
    lstm_kernel<<<128, 256, LSTM_SMEM>>>();   // 32 clusters x 4 CTAs
    attn_kernel<<<NB, 256>>>(Wout, bout, out);
}

// round 11
// speedup vs baseline: 5.7062x; 1.0793x over previous
#include <cuda_runtime.h>
#include <cuda_bf16.h>
#include <cstdint>
#include <math.h>
#include <mma.h>

using namespace nvcuda;

#define NB   128   // batch
#define LS   128   // sentence length
#define LT   8     // target length
#define EDIM 300   // true embedding dim (E=300)
#define EPAD 320   // padded embedding dim
#define HDIM 256
#define GDIM 1024  // 4*H
#define NOUT 3

// ----------------------------- scratch (static __device__, no allocs) ------
__device__ __align__(128) __nv_bfloat16 d_x_sen[LS * NB * EPAD];   // [t][b][e] zero-pad
__device__ __align__(128) __nv_bfloat16 d_x_tgt[LT * NB * EPAD];
__device__ __align__(128) __nv_bfloat16 d_Wih[4][GDIM * EPAD];     // zero-pad [n][k]
__device__ __align__(128) __nv_bfloat16 d_Whh[4][GDIM * HDIM];     // [n][k] row-major
__device__ __align__(128) float d_bias[4][GDIM];                   // bih+bhh
__device__ __align__(128) float d_gates_sen[2][LS * NB * GDIM];
__device__ __align__(128) float d_gates_tgt[2][LT * NB * GDIM];
__device__ __align__(128) float d_h_sen[2][LS * NB * HDIM];        // [t][b][h]
__device__ __align__(128) float d_h_tgt[2][LT * NB * HDIM];

struct WPtrs {
    const float* wih[4];
    const float* whh[4];
    const float* bih[4];
    const float* bhh[4];
};

// fast-math activation helpers (rel err ~1e-6; budget is 1e-3)
__device__ __forceinline__ float sigf(float x) {
    return __fdividef(1.f, 1.f + __expf(-x));
}
__device__ __forceinline__ float tanhf_(float x) {
    return 1.f - __fdividef(2.f, __expf(2.f * x) + 1.f);
}

__device__ __forceinline__ uint32_t smem_u32(const void* p) {
    uint32_t a;
    asm("{ .reg .u64 t; cvta.to.shared.u64 t, %1; cvt.u32.u64 %0, t; }" : "=r"(a) : "l"(p));
    return a;
}
__device__ __forceinline__ uint32_t cluster_rank() {
    uint32_t r;
    asm("mov.u32 %0, %%cluster_ctarank;" : "=r"(r));
    return r;
}
__device__ __forceinline__ void st_dsmem_u128(uint32_t laddr, uint32_t rank, uint4 v) {
    asm volatile(
        "{\n\t.reg .b32 ra;\n\t"
        "mapa.shared::cluster.u32 ra, %0, %1;\n\t"
        "st.shared::cluster.v4.b32 [ra], {%2, %3, %4, %5};\n\t}"
        :: "r"(laddr), "r"(rank), "r"(v.x), "r"(v.y), "r"(v.z), "r"(v.w) : "memory");
}
#define CLUSTER_SYNC() do { \
    asm volatile("barrier.cluster.arrive.aligned;" ::: "memory"); \
    asm volatile("barrier.cluster.wait.aligned;" ::: "memory"); \
} while (0)

// ----------------------------- K0: weight prep ------------------------------
__global__ void prep_kernel(WPtrs p) {
    int l = blockIdx.y;
    int stride = gridDim.x * blockDim.x;
    int start = blockIdx.x * blockDim.x + threadIdx.x;
    for (int i = start; i < GDIM * EPAD; i += stride) {
        int n = i / EPAD;
        int k = i - n * EPAD;
        d_Wih[l][i] = __float2bfloat16_rn((k < EDIM) ? p.wih[l][(size_t)n * EDIM + k] : 0.f);
    }
    for (int i = start; i < GDIM * HDIM; i += stride)
        d_Whh[l][i] = __float2bfloat16_rn(p.whh[l][i]);
    for (int i = start; i < GDIM; i += stride)
        d_bias[l][i] = p.bih[l][i] + p.bhh[l][i];
}

// ----------------------------- K1: embedding gather -------------------------
__global__ void embed_kernel(const int* __restrict__ sen_src,
                             const int* __restrict__ tgt_src,
                             const float* __restrict__ emb) {
    int row = blockIdx.x;
    int tid = threadIdx.x;  // 320 threads == EPAD
    if (row < LS * NB) {
        int t = row / NB, b = row % NB;
        int idx = sen_src[b * LS + t];
        float v = (idx == 0 || tid >= EDIM) ? 0.f : emb[(size_t)idx * EDIM + tid];
        d_x_sen[(size_t)row * EPAD + tid] = __float2bfloat16_rn(v);
    } else {
        int r = row - LS * NB;
        int t = r / NB, b = r % NB;
        int idx = tgt_src[b * LT + t];
        float v = (idx == 0 || tid >= EDIM) ? 0.f : emb[(size_t)idx * EDIM + tid];
        d_x_tgt[(size_t)r * EPAD + tid] = __float2bfloat16_rn(v);
    }
}

// ----------------------------- K2: input projection GEMM (bf16 wmma) --------
// One launch for all 4 layers: l = blockIdx.z. tgt layers use only 8 x-blocks.
#define GBM 128
#define GBN 128
#define GBK 64
#define GLD 72

__global__ __launch_bounds__(256) void gemm_xw() {
    int l = blockIdx.z;
    if (l >= 2 && blockIdx.x >= (LT * NB / GBM)) return;

    const __nv_bfloat16* __restrict__ X = (l < 2) ? d_x_sen : d_x_tgt;
    const __nv_bfloat16* __restrict__ W = d_Wih[l];
    float* __restrict__ C = (l < 2) ? d_gates_sen[l] : d_gates_tgt[l - 2];

    __shared__ __align__(128) __nv_bfloat16 As[GBM * GLD];
    __shared__ __align__(128) __nv_bfloat16 Bs[GBN * GLD];

    int tid = threadIdx.x;
    int warp = tid >> 5;
    int wm = warp & 1;
    int wn = warp >> 1;
    int m0 = blockIdx.x * GBM;
    int n0 = blockIdx.y * GBN;

    wmma::fragment<wmma::accumulator, 16, 16, 16, float> acc[4][2];
    #pragma unroll
    for (int mi = 0; mi < 4; mi++)
        #pragma unroll
        for (int ni = 0; ni < 2; ni++) wmma::fill_fragment(acc[mi][ni], 0.f);

    for (int kc = 0; kc < EPAD; kc += GBK) {
        int r0 = tid >> 3;
        int c  = (tid & 7) * 8;
        #pragma unroll
        for (int i = 0; i < 4; i++) {
            int r = r0 + i * 32;
            *(uint4*)&As[r * GLD + c] = *(const uint4*)&X[(size_t)(m0 + r) * EPAD + kc + c];
            *(uint4*)&Bs[r * GLD + c] = *(const uint4*)&W[(size_t)(n0 + r) * EPAD + kc + c];
        }
        __syncthreads();
        #pragma unroll
        for (int kk = 0; kk < GBK; kk += 16) {
            wmma::fragment<wmma::matrix_a, 16, 16, 16, __nv_bfloat16, wmma::row_major> af[4];
            wmma::fragment<wmma::matrix_b, 16, 16, 16, __nv_bfloat16, wmma::col_major> bf[2];
            #pragma unroll
            for (int mi = 0; mi < 4; mi++)
                wmma::load_matrix_sync(af[mi], &As[(wm * 64 + mi * 16) * GLD + kk], GLD);
            #pragma unroll
            for (int ni = 0; ni < 2; ni++)
                wmma::load_matrix_sync(bf[ni], &Bs[(wn * 32 + ni * 16) * GLD + kk], GLD);
            #pragma unroll
            for (int mi = 0; mi < 4; mi++)
                #pragma unroll
                for (int ni = 0; ni < 2; ni++)
                    wmma::mma_sync(acc[mi][ni], af[mi], bf[ni], acc[mi][ni]);
        }
        __syncthreads();
    }
    #pragma unroll
    for (int mi = 0; mi < 4; mi++)
        #pragma unroll
        for (int ni = 0; ni < 2; ni++)
            wmma::store_matrix_sync(
                &C[(size_t)(m0 + wm * 64 + mi * 16) * GDIM + n0 + wn * 32 + ni * 16],
                acc[mi][ni], GDIM, wmma::mem_row_major);
}

// ----------------------------- K3: LSTM recurrence (cluster, Whh-resident) --
// Cluster of 4 CTAs per (lstm, batch-chunk-of-16). CTA rank r owns hidden
// units [r*64, r*64+64): Whh rows resident in smem; h exchanged per step via
// staged wide DSMEM stores. One cluster sync per step (double-buffered h).
#define BCH    16
#define SLC    64                       // hidden units per CTA
#define WLD    264                      // smem leading dim (bf16)
#define W_SZ   (256 * WLD * 2)          // 135168 B
#define H_SZ   (BCH * WLD * 2)          // 8448 B per h buffer
#define G_SZ   (BCH * WLD * 4)          // 16896 B (fp32 gates, ld 264)
#define S_SZ   (BCH * SLC * 2)          // 2048 B staging slice
#define LSTM_SMEM (W_SZ + 2 * H_SZ + G_SZ + S_SZ)   // 171008 B

__global__ void __cluster_dims__(4, 1, 1) __launch_bounds__(256, 1) lstm_kernel() {
    extern __shared__ __align__(128) unsigned char smem[];
    __nv_bfloat16* Wsh   = (__nv_bfloat16*)smem;                        // [256][264]
    __nv_bfloat16* hbuf  = (__nv_bfloat16*)(smem + W_SZ);               // [2][16][264]
    float*         gates = (float*)(smem + W_SZ + 2 * H_SZ);            // [16][264]
    __nv_bfloat16* hstg  = (__nv_bfloat16*)(smem + W_SZ + 2 * H_SZ + G_SZ); // [16][64]

    int bx   = blockIdx.x;
    int cid  = bx >> 2;                 // cluster id 0..31
    int lstm = cid >> 3;                // 0=sf 1=sb 2=tf 3=tb
    int b0   = (cid & 7) * BCH;
    uint32_t r = cluster_rank();        // 0..3
    int T    = (lstm < 2) ? LS : LT;
    bool rev = (lstm & 1);
    const __nv_bfloat16* __restrict__ Wg = d_Whh[lstm];
    const float* __restrict__ Xg   = (lstm < 2) ? d_gates_sen[lstm] : d_gates_tgt[lstm - 2];
    float* __restrict__       Hout = (lstm < 2) ? d_h_sen[lstm]     : d_h_tgt[lstm - 2];

    int tid  = threadIdx.x;
    int warp = tid >> 5;
    int u    = tid & 63;                // hidden unit within slice
    int kbg  = tid >> 6;                // batch group 0..3
    int r64u = (int)r * SLC + u;        // global hidden unit

    // ---- load resident Whh slice: local row lr = g*64+u  <- global row g*256+r64u
    for (int i = tid; i < 256 * 32; i += 256) {
        int lr = i >> 5;
        int c8 = i & 31;
        int n  = ((lr >> 6) << 8) + (int)r * SLC + (lr & 63);
        *(uint4*)&Wsh[lr * WLD + c8 * 8] = *(const uint4*)&Wg[(size_t)n * HDIM + c8 * 8];
    }
    // ---- zero both h buffers
    for (int i = tid; i < 2 * BCH * WLD; i += 256) hbuf[i] = __float2bfloat16_rn(0.f);

    float c[4] = {0.f, 0.f, 0.f, 0.f};
    const float bi  = d_bias[lstm][r64u];
    const float bf_ = d_bias[lstm][r64u + 256];
    const float bg  = d_bias[lstm][r64u + 512];
    const float bo  = d_bias[lstm][r64u + 768];

    uint32_t hbase_u32 = smem_u32(hbuf);
    __syncthreads();
    CLUSTER_SYNC();

    for (int step = 0; step < T; step++) {
        int t = rev ? (T - 1 - step) : step;
        const __nv_bfloat16* hcur = hbuf + (step & 1) * (BCH * WLD);
        uint32_t hnxt_u32 = hbase_u32 + (uint32_t)(((step & 1) ^ 1) * H_SZ);

        // ---- gates[16][w*32 .. +32] = hcur @ Wsh^T  (warp's 32-col slice)
        // Low-register form: A-fragment loaded inside the K loop.
        {
            wmma::fragment<wmma::accumulator, 16, 16, 16, float> acc0, acc1;
            wmma::fill_fragment(acc0, 0.f);
            wmma::fill_fragment(acc1, 0.f);
            #pragma unroll
            for (int kk = 0; kk < 16; kk++) {
                wmma::fragment<wmma::matrix_a, 16, 16, 16, __nv_bfloat16, wmma::row_major> af;
                wmma::load_matrix_sync(af, &hcur[kk * 16], WLD);
                wmma::fragment<wmma::matrix_b, 16, 16, 16, __nv_bfloat16, wmma::col_major> b0f, b1f;
                wmma::load_matrix_sync(b0f, &Wsh[(warp * 32) * WLD + kk * 16], WLD);
                wmma::load_matrix_sync(b1f, &Wsh[(warp * 32 + 16) * WLD + kk * 16], WLD);
                wmma::mma_sync(acc0, af, b0f, acc0);
                wmma::mma_sync(acc1, af, b1f, acc1);
            }
            wmma::store_matrix_sync(&gates[warp * 32], acc0, WLD, wmma::mem_row_major);
            wmma::store_matrix_sync(&gates[warp * 32 + 16], acc1, WLD, wmma::mem_row_major);
        }
        __syncthreads();

        // ---- elementwise for this CTA's 64 units x 16 batch (4 per thread)
        const float* xgt = Xg + (size_t)(t * NB + b0) * GDIM;
        #pragma unroll
        for (int j = 0; j < 4; j++) {
            int kb = j * 4 + kbg;
            const float* xr = xgt + (size_t)kb * GDIM;
            float gi = gates[kb * WLD + u]       + xr[r64u]       + bi;
            float gf = gates[kb * WLD + 64 + u]  + xr[r64u + 256] + bf_;
            float gg = gates[kb * WLD + 128 + u] + xr[r64u + 512] + bg;
            float go = gates[kb * WLD + 192 + u] + xr[r64u + 768] + bo;
            float cn = sigf(gf) * c[j] + sigf(gi) * tanhf_(gg);
            c[j] = cn;
            float hv = sigf(go) * tanhf_(cn);
            hstg[kb * SLC + u] = __float2bfloat16_rn(hv);
            Hout[(size_t)(t * NB + b0 + kb) * HDIM + r64u] = hv;
        }
        __syncthreads();

        // ---- broadcast staged slice (2KB) to all 4 ranks with 128-bit stores
        #pragma unroll
        for (int i = tid; i < 512; i += 256) {      // 4 ranks x 128 uint4
            int rk = i >> 7;
            int j  = i & 127;
            int kb = j >> 3;
            int q  = j & 7;
            uint4 v = *(const uint4*)&hstg[kb * SLC + q * 8];
            uint32_t dst = hnxt_u32 +
                (uint32_t)((kb * WLD + (int)r * SLC) * 2 + q * 16);
            st_dsmem_u128(dst, (uint32_t)rk, v);
        }
        CLUSTER_SYNC();
    }
}

// ----------------------------- K4: attention + output (fp32) ----------------
__global__ __launch_bounds__(256) void attn_kernel(const float* __restrict__ Wout,
                                                   const float* __restrict__ bout,
                                                   float* __restrict__ out) {
    int b = blockIdx.x;
    int tid = threadIdx.x;
    int lane = tid & 31, warp = tid >> 5;

    __shared__ float tgt_s[LT][2 * HDIM];
    __shared__ float A_s[LS][LT];
    __shared__ float colmax[LT];
    __shared__ float colsum[LT];
    __shared__ float rowvec[LT];
    __shared__ float attn_s[LS];
    __shared__ float score_s[2 * HDIM];
    __shared__ float logit[NOUT];

    for (int i = tid; i < LT * 2 * HDIM; i += 256) {
        int t = i >> 9;
        int mm = i & 511;
        tgt_s[t][mm] = (mm < HDIM)
            ? d_h_tgt[0][((size_t)t * NB + b) * HDIM + mm]
            : d_h_tgt[1][((size_t)t * NB + b) * HDIM + (mm - HDIM)];
    }
    if (tid < LT) rowvec[tid] = 0.f;
    __syncthreads();

    for (int s = warp; s < LS; s += 8) {
        float p[LT];
        #pragma unroll
        for (int t = 0; t < LT; t++) p[t] = 0.f;
        const float* f0 = &d_h_sen[0][((size_t)s * NB + b) * HDIM];
        const float* f1 = &d_h_sen[1][((size_t)s * NB + b) * HDIM];
        for (int mm = lane; mm < HDIM; mm += 32) {
            float v0 = f0[mm], v1 = f1[mm];
            #pragma unroll
            for (int t = 0; t < LT; t++)
                p[t] += v0 * tgt_s[t][mm] + v1 * tgt_s[t][HDIM + mm];
        }
        #pragma unroll
        for (int t = 0; t < LT; t++) {
            #pragma unroll
            for (int o = 16; o; o >>= 1) p[t] += __shfl_xor_sync(0xffffffffu, p[t], o);
            if (lane == 0) A_s[s][t] = p[t];
        }
    }
    __syncthreads();

    if (tid < LT) {
        float mx = -1e30f;
        for (int s = 0; s < LS; s++) mx = fmaxf(mx, A_s[s][tid]);
        float sm = 0.f;
        for (int s = 0; s < LS; s++) sm += expf(A_s[s][tid] - mx);
        colmax[tid] = mx;
        colsum[tid] = sm;
    }
    if (tid < LS) {
        float mx = -1e30f;
        #pragma unroll
        for (int t = 0; t < LT; t++) mx = fmaxf(mx, A_s[tid][t]);
        float e[LT], sm = 0.f;
        #pragma unroll
        for (int t = 0; t < LT; t++) { e[t] = expf(A_s[tid][t] - mx); sm += e[t]; }
        float inv = 1.f / (sm * (float)LS);
        #pragma unroll
        for (int t = 0; t < LT; t++) atomicAdd(&rowvec[t], e[t] * inv);
    }
    __syncthreads();

    if (tid < LS) {
        float a = 0.f;
        #pragma unroll
        for (int t = 0; t < LT; t++)
            a += (expf(A_s[tid][t] - colmax[t]) / colsum[t]) * rowvec[t];
        attn_s[tid] = a;
    }
    __syncthreads();

    for (int mm = tid; mm < 2 * HDIM; mm += 256) {
        const float* hp = (mm < HDIM) ? d_h_sen[0] : d_h_sen[1];
        int m2 = mm & (HDIM - 1);
        float acc = 0.f;
        for (int s = 0; s < LS; s++)
            acc += attn_s[s] * hp[((size_t)s * NB + b) * HDIM + m2];
        score_s[mm] = acc;
    }
    __syncthreads();

    if (warp < NOUT) {
        float acc = 0.f;
        for (int mm = lane; mm < 2 * HDIM; mm += 32)
            acc += score_s[mm] * Wout[warp * 2 * HDIM + mm];
        #pragma unroll
        for (int o = 16; o; o >>= 1) acc += __shfl_xor_sync(0xffffffffu, acc, o);
        if (lane == 0) logit[warp] = acc + bout[warp];
    }
    __syncthreads();

    if (tid == 0) {
        float mx = fmaxf(logit[0], fmaxf(logit[1], logit[2]));
        float e0 = expf(logit[0] - mx);
        float e1 = expf(logit[1] - mx);
        float e2 = expf(logit[2] - mx);
        float inv = 1.f / (e0 + e1 + e2);
        out[b * NOUT + 0] = e0 * inv;
        out[b * NOUT + 1] = e1 * inv;
        out[b * NOUT + 2] = e2 * inv;
    }
}

// ----------------------------- launch ---------------------------------------
extern "C" void kernel_launch(void* const* d_in, const int* in_sizes, int n_in,
                              void* d_out, int out_size) {
    const int*   sen_src = (const int*)d_in[0];
    const int*   tgt_src = (const int*)d_in[1];
    const float* emb     = (const float*)d_in[2];
    WPtrs wp;
    for (int l = 0; l < 4; l++) {
        wp.wih[l] = (const float*)d_in[3 + 4 * l];
        wp.whh[l] = (const float*)d_in[4 + 4 * l];
        wp.bih[l] = (const float*)d_in[5 + 4 * l];
        wp.bhh[l] = (const float*)d_in[6 + 4 * l];
    }
    const float* Wout = (const float*)d_in[19];
    const float* bout = (const float*)d_in[20];
    float* out = (float*)d_out;

    cudaFuncSetAttribute(lstm_kernel, cudaFuncAttributeMaxDynamicSharedMemorySize, LSTM_SMEM);

    prep_kernel<<<dim3(256, 4), 256>>>(wp);
    embed_kernel<<<(LS + LT) * NB, EPAD>>>(sen_src, tgt_src, emb);
    gemm_xw<<<dim3(LS * NB / GBM, GDIM / GBN, 4), 256>>>();
    lstm_kernel<<<128, 256, LSTM_SMEM>>>();   // 32 clusters x 4 CTAs
    attn_kernel<<<NB, 256>>>(Wout, bout, out);
}

// round 12
// speedup vs baseline: 8.0480x; 1.4104x over previous
#include <cuda_runtime.h>
#include <cuda_bf16.h>
#include <cstdint>
#include <math.h>
#include <mma.h>

using namespace nvcuda;

#define NB   128   // batch
#define LS   128   // sentence length
#define LT   8     // target length
#define EDIM 300   // true embedding dim (E=300)
#define EPAD 320   // padded embedding dim
#define HDIM 256
#define GDIM 1024  // 4*H
#define NOUT 3

// ----------------------------- scratch (static __device__, no allocs) ------
__device__ __align__(128) __nv_bfloat16 d_x_sen[LS * NB * EPAD];   // [t][b][e] zero-pad
__device__ __align__(128) __nv_bfloat16 d_x_tgt[LT * NB * EPAD];
__device__ __align__(128) __nv_bfloat16 d_Wih[4][GDIM * EPAD];     // zero-pad [n][k]
__device__ __align__(128) __nv_bfloat16 d_Whh[4][GDIM * HDIM];     // [n][k] row-major
__device__ __align__(128) float d_bias[4][GDIM];                   // bih+bhh
__device__ __align__(128) float d_gates_sen[2][LS * NB * GDIM];
__device__ __align__(128) float d_gates_tgt[2][LT * NB * GDIM];
__device__ __align__(128) float d_h_sen[2][LS * NB * HDIM];        // [t][b][h]
__device__ __align__(128) float d_h_tgt[2][LT * NB * HDIM];

struct WPtrs {
    const float* wih[4];
    const float* whh[4];
    const float* bih[4];
    const float* bhh[4];
};

// fast-math activation helpers (rel err ~1e-6; budget is 1e-3)
__device__ __forceinline__ float sigf(float x) {
    return __fdividef(1.f, 1.f + __expf(-x));
}
__device__ __forceinline__ float tanhf_(float x) {
    return 1.f - __fdividef(2.f, __expf(2.f * x) + 1.f);
}

__device__ __forceinline__ uint32_t smem_u32(const void* p) {
    uint32_t a;
    asm("{ .reg .u64 t; cvta.to.shared.u64 t, %1; cvt.u32.u64 %0, t; }" : "=r"(a) : "l"(p));
    return a;
}
__device__ __forceinline__ uint32_t cluster_rank() {
    uint32_t r;
    asm("mov.u32 %0, %%cluster_ctarank;" : "=r"(r));
    return r;
}
__device__ __forceinline__ void st_dsmem_b16(uint32_t laddr, uint32_t rank, __nv_bfloat16 v) {
    unsigned short s = *reinterpret_cast<unsigned short*>(&v);
    asm volatile(
        "{\n\t.reg .b32 ra;\n\t"
        "mapa.shared::cluster.u32 ra, %0, %1;\n\t"
        "st.shared::cluster.b16 [ra], %2;\n\t}"
        :: "r"(laddr), "r"(rank), "h"(s) : "memory");
}
#define CLUSTER_ARRIVE() asm volatile("barrier.cluster.arrive.aligned;" ::: "memory")
#define CLUSTER_WAIT()   asm volatile("barrier.cluster.wait.aligned;" ::: "memory")

// ----------------------------- K0: weight prep ------------------------------
__global__ void prep_kernel(WPtrs p) {
    int l = blockIdx.y;
    int stride = gridDim.x * blockDim.x;
    int start = blockIdx.x * blockDim.x + threadIdx.x;
    for (int i = start; i < GDIM * EPAD; i += stride) {
        int n = i / EPAD;
        int k = i - n * EPAD;
        d_Wih[l][i] = __float2bfloat16_rn((k < EDIM) ? p.wih[l][(size_t)n * EDIM + k] : 0.f);
    }
    for (int i = start; i < GDIM * HDIM; i += stride)
        d_Whh[l][i] = __float2bfloat16_rn(p.whh[l][i]);
    for (int i = start; i < GDIM; i += stride)
        d_bias[l][i] = p.bih[l][i] + p.bhh[l][i];
}

// ----------------------------- K1: embedding gather -------------------------
__global__ void embed_kernel(const int* __restrict__ sen_src,
                             const int* __restrict__ tgt_src,
                             const float* __restrict__ emb) {
    int row = blockIdx.x;
    int tid = threadIdx.x;  // 320 threads == EPAD
    if (row < LS * NB) {
        int t = row / NB, b = row % NB;
        int idx = sen_src[b * LS + t];
        float v = (idx == 0 || tid >= EDIM) ? 0.f : emb[(size_t)idx * EDIM + tid];
        d_x_sen[(size_t)row * EPAD + tid] = __float2bfloat16_rn(v);
    } else {
        int r = row - LS * NB;
        int t = r / NB, b = r % NB;
        int idx = tgt_src[b * LT + t];
        float v = (idx == 0 || tid >= EDIM) ? 0.f : emb[(size_t)idx * EDIM + tid];
        d_x_tgt[(size_t)r * EPAD + tid] = __float2bfloat16_rn(v);
    }
}

// ----------------------------- K2: input projection GEMM (bf16 wmma) --------
#define GBM 128
#define GBN 128
#define GBK 64
#define GLD 72

__global__ __launch_bounds__(256) void gemm_xw() {
    int l = blockIdx.z;
    if (l >= 2 && blockIdx.x >= (LT * NB / GBM)) return;

    const __nv_bfloat16* __restrict__ X = (l < 2) ? d_x_sen : d_x_tgt;
    const __nv_bfloat16* __restrict__ W = d_Wih[l];
    float* __restrict__ C = (l < 2) ? d_gates_sen[l] : d_gates_tgt[l - 2];

    __shared__ __align__(128) __nv_bfloat16 As[GBM * GLD];
    __shared__ __align__(128) __nv_bfloat16 Bs[GBN * GLD];

    int tid = threadIdx.x;
    int warp = tid >> 5;
    int wm = warp & 1;
    int wn = warp >> 1;
    int m0 = blockIdx.x * GBM;
    int n0 = blockIdx.y * GBN;

    wmma::fragment<wmma::accumulator, 16, 16, 16, float> acc[4][2];
    #pragma unroll
    for (int mi = 0; mi < 4; mi++)
        #pragma unroll
        for (int ni = 0; ni < 2; ni++) wmma::fill_fragment(acc[mi][ni], 0.f);

    for (int kc = 0; kc < EPAD; kc += GBK) {
        int r0 = tid >> 3;
        int c  = (tid & 7) * 8;
        #pragma unroll
        for (int i = 0; i < 4; i++) {
            int r = r0 + i * 32;
            *(uint4*)&As[r * GLD + c] = *(const uint4*)&X[(size_t)(m0 + r) * EPAD + kc + c];
            *(uint4*)&Bs[r * GLD + c] = *(const uint4*)&W[(size_t)(n0 + r) * EPAD + kc + c];
        }
        __syncthreads();
        #pragma unroll
        for (int kk = 0; kk < GBK; kk += 16) {
            wmma::fragment<wmma::matrix_a, 16, 16, 16, __nv_bfloat16, wmma::row_major> af[4];
            wmma::fragment<wmma::matrix_b, 16, 16, 16, __nv_bfloat16, wmma::col_major> bf[2];
            #pragma unroll
            for (int mi = 0; mi < 4; mi++)
                wmma::load_matrix_sync(af[mi], &As[(wm * 64 + mi * 16) * GLD + kk], GLD);
            #pragma unroll
            for (int ni = 0; ni < 2; ni++)
                wmma::load_matrix_sync(bf[ni], &Bs[(wn * 32 + ni * 16) * GLD + kk], GLD);
            #pragma unroll
            for (int mi = 0; mi < 4; mi++)
                #pragma unroll
                for (int ni = 0; ni < 2; ni++)
                    wmma::mma_sync(acc[mi][ni], af[mi], bf[ni], acc[mi][ni]);
        }
        __syncthreads();
    }
    #pragma unroll
    for (int mi = 0; mi < 4; mi++)
        #pragma unroll
        for (int ni = 0; ni < 2; ni++)
            wmma::store_matrix_sync(
                &C[(size_t)(m0 + wm * 64 + mi * 16) * GDIM + n0 + wn * 32 + ni * 16],
                acc[mi][ni], GDIM, wmma::mem_row_major);
}

// ----------------------------- K3: LSTM recurrence (cluster, pipelined) -----
// Cluster of 4 CTAs per (lstm, batch-chunk-of-16). CTA rank r owns hidden
// units [r*64, r*64+64). Whh slice resident in smem. Per step:
//   mma -> syncthreads -> elementwise (prefetched x) + direct DSMEM scatter
//   -> cluster.arrive -> prefetch x(t+1) + Hout stores -> cluster.wait
#define BCH    16
#define SLC    64                       // hidden units per CTA
#define WLD    264                      // smem leading dim (bf16)
#define W_SZ   (256 * WLD * 2)          // 135168 B
#define H_SZ   (BCH * WLD * 2)          // 8448 B per h buffer
#define G_SZ   (BCH * WLD * 4)          // 16896 B (fp32 gates, ld 264)
#define LSTM_SMEM (W_SZ + 2 * H_SZ + G_SZ)   // 168960 B

__global__ void __cluster_dims__(4, 1, 1) __launch_bounds__(256, 1) lstm_kernel() {
    extern __shared__ __align__(128) unsigned char smem[];
    __nv_bfloat16* Wsh   = (__nv_bfloat16*)smem;                        // [256][264]
    __nv_bfloat16* hbuf  = (__nv_bfloat16*)(smem + W_SZ);               // [2][16][264]
    float*         gates = (float*)(smem + W_SZ + 2 * H_SZ);            // [16][264]

    int bx   = blockIdx.x;
    int cid  = bx >> 2;                 // cluster id 0..31
    int lstm = cid >> 3;                // 0=sf 1=sb 2=tf 3=tb
    int b0   = (cid & 7) * BCH;
    uint32_t r = cluster_rank();        // 0..3
    int T    = (lstm < 2) ? LS : LT;
    bool rev = (lstm & 1);
    const __nv_bfloat16* __restrict__ Wg = d_Whh[lstm];
    const float* __restrict__ Xg   = (lstm < 2) ? d_gates_sen[lstm] : d_gates_tgt[lstm - 2];
    float* __restrict__       Hout = (lstm < 2) ? d_h_sen[lstm]     : d_h_tgt[lstm - 2];

    int tid  = threadIdx.x;
    int warp = tid >> 5;
    int u    = tid & 63;                // hidden unit within slice
    int kbg  = tid >> 6;                // batch group 0..3
    int r64u = (int)r * SLC + u;        // global hidden unit

    // ---- load resident Whh slice: local row lr = g*64+u  <- global row g*256+r64u
    for (int i = tid; i < 256 * 32; i += 256) {
        int lr = i >> 5;
        int c8 = i & 31;
        int n  = ((lr >> 6) << 8) + (int)r * SLC + (lr & 63);
        *(uint4*)&Wsh[lr * WLD + c8 * 8] = *(const uint4*)&Wg[(size_t)n * HDIM + c8 * 8];
    }
    // ---- zero both h buffers
    for (int i = tid; i < 2 * BCH * WLD; i += 256) hbuf[i] = __float2bfloat16_rn(0.f);

    float c[4] = {0.f, 0.f, 0.f, 0.f};
    const float bi  = d_bias[lstm][r64u];
    const float bf_ = d_bias[lstm][r64u + 256];
    const float bg  = d_bias[lstm][r64u + 512];
    const float bo  = d_bias[lstm][r64u + 768];

    uint32_t hbase_u32 = smem_u32(hbuf);

    // ---- prefetch x-gates for step 0
    float xv[4][4];
    {
        int t0 = rev ? (T - 1) : 0;
        const float* xgt = Xg + (size_t)(t0 * NB + b0) * GDIM;
        #pragma unroll
        for (int j = 0; j < 4; j++) {
            const float* xr = xgt + (size_t)(j * 4 + kbg) * GDIM;
            xv[j][0] = xr[r64u];
            xv[j][1] = xr[r64u + 256];
            xv[j][2] = xr[r64u + 512];
            xv[j][3] = xr[r64u + 768];
        }
    }

    __syncthreads();
    CLUSTER_ARRIVE();
    CLUSTER_WAIT();

    for (int step = 0; step < T; step++) {
        int t = rev ? (T - 1 - step) : step;
        const __nv_bfloat16* hcur = hbuf + (step & 1) * (BCH * WLD);
        uint32_t hnxt_u32 = hbase_u32 + (uint32_t)(((step & 1) ^ 1) * H_SZ);

        // ---- gates[16][w*32 .. +32] = hcur @ Wsh^T  (warp's 32-col slice)
        {
            wmma::fragment<wmma::accumulator, 16, 16, 16, float> acc0, acc1;
            wmma::fill_fragment(acc0, 0.f);
            wmma::fill_fragment(acc1, 0.f);
            #pragma unroll
            for (int kk = 0; kk < 16; kk++) {
                wmma::fragment<wmma::matrix_a, 16, 16, 16, __nv_bfloat16, wmma::row_major> af;
                wmma::load_matrix_sync(af, &hcur[kk * 16], WLD);
                wmma::fragment<wmma::matrix_b, 16, 16, 16, __nv_bfloat16, wmma::col_major> b0f, b1f;
                wmma::load_matrix_sync(b0f, &Wsh[(warp * 32) * WLD + kk * 16], WLD);
                wmma::load_matrix_sync(b1f, &Wsh[(warp * 32 + 16) * WLD + kk * 16], WLD);
                wmma::mma_sync(acc0, af, b0f, acc0);
                wmma::mma_sync(acc1, af, b1f, acc1);
            }
            wmma::store_matrix_sync(&gates[warp * 32], acc0, WLD, wmma::mem_row_major);
            wmma::store_matrix_sync(&gates[warp * 32 + 16], acc1, WLD, wmma::mem_row_major);
        }
        __syncthreads();

        // ---- elementwise (prefetched x) + direct DSMEM scatter
        float hvv[4];
        #pragma unroll
        for (int j = 0; j < 4; j++) {
            int kb = j * 4 + kbg;
            float gi = gates[kb * WLD + u]       + xv[j][0] + bi;
            float gf = gates[kb * WLD + 64 + u]  + xv[j][1] + bf_;
            float gg = gates[kb * WLD + 128 + u] + xv[j][2] + bg;
            float go = gates[kb * WLD + 192 + u] + xv[j][3] + bo;
            float cn = sigf(gf) * c[j] + sigf(gi) * tanhf_(gg);
            c[j] = cn;
            float hv = sigf(go) * tanhf_(cn);
            hvv[j] = hv;
            __nv_bfloat16 hb = __float2bfloat16_rn(hv);
            uint32_t off = hnxt_u32 + (uint32_t)(kb * WLD + r64u) * 2u;
            #pragma unroll
            for (uint32_t rk = 0; rk < 4; rk++) st_dsmem_b16(off, rk, hb);
        }
        CLUSTER_ARRIVE();

        // ---- latency shadow: Hout stores + next-step x prefetch
        {
            float* hrow = Hout + (size_t)(t * NB + b0) * HDIM;
            #pragma unroll
            for (int j = 0; j < 4; j++)
                hrow[(size_t)(j * 4 + kbg) * HDIM + r64u] = hvv[j];
        }
        if (step + 1 < T) {
            int tn = rev ? (T - 2 - step) : (step + 1);
            const float* xgt = Xg + (size_t)(tn * NB + b0) * GDIM;
            #pragma unroll
            for (int j = 0; j < 4; j++) {
                const float* xr = xgt + (size_t)(j * 4 + kbg) * GDIM;
                xv[j][0] = xr[r64u];
                xv[j][1] = xr[r64u + 256];
                xv[j][2] = xr[r64u + 512];
                xv[j][3] = xr[r64u + 768];
            }
        }
        CLUSTER_WAIT();
    }
}

// ----------------------------- K4: attention + output (fp32) ----------------
__global__ __launch_bounds__(256) void attn_kernel(const float* __restrict__ Wout,
                                                   const float* __restrict__ bout,
                                                   float* __restrict__ out) {
    int b = blockIdx.x;
    int tid = threadIdx.x;
    int lane = tid & 31, warp = tid >> 5;

    __shared__ float tgt_s[LT][2 * HDIM];
    __shared__ float A_s[LS][LT];
    __shared__ float colmax[LT];
    __shared__ float colsum[LT];
    __shared__ float rowvec[LT];
    __shared__ float attn_s[LS];
    __shared__ float score_s[2 * HDIM];
    __shared__ float logit[NOUT];

    for (int i = tid; i < LT * 2 * HDIM; i += 256) {
        int t = i >> 9;
        int mm = i & 511;
        tgt_s[t][mm] = (mm < HDIM)
            ? d_h_tgt[0][((size_t)t * NB + b) * HDIM + mm]
            : d_h_tgt[1][((size_t)t * NB + b) * HDIM + (mm - HDIM)];
    }
    if (tid < LT) rowvec[tid] = 0.f;
    __syncthreads();

    for (int s = warp; s < LS; s += 8) {
        float p[LT];
        #pragma unroll
        for (int t = 0; t < LT; t++) p[t] = 0.f;
        const float* f0 = &d_h_sen[0][((size_t)s * NB + b) * HDIM];
        const float* f1 = &d_h_sen[1][((size_t)s * NB + b) * HDIM];
        for (int mm = lane; mm < HDIM; mm += 32) {
            float v0 = f0[mm], v1 = f1[mm];
            #pragma unroll
            for (int t = 0; t < LT; t++)
                p[t] += v0 * tgt_s[t][mm] + v1 * tgt_s[t][HDIM + mm];
        }
        #pragma unroll
        for (int t = 0; t < LT; t++) {
            #pragma unroll
            for (int o = 16; o; o >>= 1) p[t] += __shfl_xor_sync(0xffffffffu, p[t], o);
            if (lane == 0) A_s[s][t] = p[t];
        }
    }
    __syncthreads();

    if (tid < LT) {
        float mx = -1e30f;
        for (int s = 0; s < LS; s++) mx = fmaxf(mx, A_s[s][tid]);
        float sm = 0.f;
        for (int s = 0; s < LS; s++) sm += expf(A_s[s][tid] - mx);
        colmax[tid] = mx;
        colsum[tid] = sm;
    }
    if (tid < LS) {
        float mx = -1e30f;
        #pragma unroll
        for (int t = 0; t < LT; t++) mx = fmaxf(mx, A_s[tid][t]);
        float e[LT], sm = 0.f;
        #pragma unroll
        for (int t = 0; t < LT; t++) { e[t] = expf(A_s[tid][t] - mx); sm += e[t]; }
        float inv = 1.f / (sm * (float)LS);
        #pragma unroll
        for (int t = 0; t < LT; t++) atomicAdd(&rowvec[t], e[t] * inv);
    }
    __syncthreads();

    if (tid < LS) {
        float a = 0.f;
        #pragma unroll
        for (int t = 0; t < LT; t++)
            a += (expf(A_s[tid][t] - colmax[t]) / colsum[t]) * rowvec[t];
        attn_s[tid] = a;
    }
    __syncthreads();

    for (int mm = tid; mm < 2 * HDIM; mm += 256) {
        const float* hp = (mm < HDIM) ? d_h_sen[0] : d_h_sen[1];
        int m2 = mm & (HDIM - 1);
        float acc = 0.f;
        for (int s = 0; s < LS; s++)
            acc += attn_s[s] * hp[((size_t)s * NB + b) * HDIM + m2];
        score_s[mm] = acc;
    }
    __syncthreads();

    if (warp < NOUT) {
        float acc = 0.f;
        for (int mm = lane; mm < 2 * HDIM; mm += 32)
            acc += score_s[mm] * Wout[warp * 2 * HDIM + mm];
        #pragma unroll
        for (int o = 16; o; o >>= 1) acc += __shfl_xor_sync(0xffffffffu, acc, o);
        if (lane == 0) logit[warp] = acc + bout[warp];
    }
    __syncthreads();

    if (tid == 0) {
        float mx = fmaxf(logit[0], fmaxf(logit[1], logit[2]));
        float e0 = expf(logit[0] - mx);
        float e1 = expf(logit[1] - mx);
        float e2 = expf(logit[2] - mx);
        float inv = 1.f / (e0 + e1 + e2);
        out[b * NOUT + 0] = e0 * inv;
        out[b * NOUT + 1] = e1 * inv;
        out[b * NOUT + 2] = e2 * inv;
    }
}

// ----------------------------- launch ---------------------------------------
extern "C" void kernel_launch(void* const* d_in, const int* in_sizes, int n_in,
                              void* d_out, int out_size) {
    const int*   sen_src = (const int*)d_in[0];
    const int*   tgt_src = (const int*)d_in[1];
    const float* emb     = (const float*)d_in[2];
    WPtrs wp;
    for (int l = 0; l < 4; l++) {
        wp.wih[l] = (const float*)d_in[3 + 4 * l];
        wp.whh[l] = (const float*)d_in[4 + 4 * l];
        wp.bih[l] = (const float*)d_in[5 + 4 * l];
        wp.bhh[l] = (const float*)d_in[6 + 4 * l];
    }
    const float* Wout = (const float*)d_in[19];
    const float* bout = (const float*)d_in[20];
    float* out = (float*)d_out;

    cudaFuncSetAttribute(lstm_kernel, cudaFuncAttributeMaxDynamicSharedMemorySize, LSTM_SMEM);

    prep_kernel<<<dim3(256, 4), 256>>>(wp);
    embed_kernel<<<(LS + LT) * NB, EPAD>>>(sen_src, tgt_src, emb);
    gemm_xw<<<dim3(LS * NB / GBM, GDIM / GBN, 4), 256>>>();
    lstm_kernel<<<128, 256, LSTM_SMEM>>>();   // 32 clusters x 4 CTAs
    attn_kernel<<<NB, 256>>>(Wout, bout, out);
}

// round 13
// speedup vs baseline: 8.9529x; 1.1124x over previous
#include <cuda_runtime.h>
#include <cuda_bf16.h>
#include <cstdint>
#include <math.h>
#include <mma.h>

using namespace nvcuda;

#define NB   128   // batch
#define LS   128   // sentence length
#define LT   8     // target length
#define EDIM 300   // true embedding dim (E=300)
#define EPAD 320   // padded embedding dim
#define HDIM 256
#define GDIM 1024  // 4*H
#define NOUT 3

// ----------------------------- scratch (static __device__, no allocs) ------
__device__ __align__(128) __nv_bfloat16 d_x_sen[LS * NB * EPAD];   // [t][b][e] zero-pad
__device__ __align__(128) __nv_bfloat16 d_x_tgt[LT * NB * EPAD];
__device__ __align__(128) __nv_bfloat16 d_Wih[4][GDIM * EPAD];     // zero-pad [n][k]
__device__ __align__(128) __nv_bfloat16 d_Whh[4][GDIM * HDIM];     // [n][k] row-major
__device__ __align__(128) float d_bias[4][GDIM];                   // bih+bhh
__device__ __align__(128) float d_gates_sen[2][LS * NB * GDIM];
__device__ __align__(128) float d_gates_tgt[2][LT * NB * GDIM];
__device__ __align__(128) float d_h_sen[2][LS * NB * HDIM];        // [t][b][h]
__device__ __align__(128) float d_h_tgt[2][LT * NB * HDIM];

struct WPtrs {
    const float* wih[4];
    const float* whh[4];
    const float* bih[4];
    const float* bhh[4];
};

// fast-math activation helpers (rel err ~1e-6; budget is 1e-3)
__device__ __forceinline__ float sigf(float x) {
    return __fdividef(1.f, 1.f + __expf(-x));
}
__device__ __forceinline__ float tanhf_(float x) {
    return 1.f - __fdividef(2.f, __expf(2.f * x) + 1.f);
}

__device__ __forceinline__ uint32_t smem_u32(const void* p) {
    uint32_t a;
    asm("{ .reg .u64 t; cvta.to.shared.u64 t, %1; cvt.u32.u64 %0, t; }" : "=r"(a) : "l"(p));
    return a;
}
__device__ __forceinline__ uint32_t cluster_rank() {
    uint32_t r;
    asm("mov.u32 %0, %%cluster_ctarank;" : "=r"(r));
    return r;
}
__device__ __forceinline__ void st_dsmem_b16(uint32_t laddr, uint32_t rank, __nv_bfloat16 v) {
    unsigned short s = *reinterpret_cast<unsigned short*>(&v);
    asm volatile(
        "{\n\t.reg .b32 ra;\n\t"
        "mapa.shared::cluster.u32 ra, %0, %1;\n\t"
        "st.shared::cluster.b16 [ra], %2;\n\t}"
        :: "r"(laddr), "r"(rank), "h"(s) : "memory");
}
#define CLUSTER_ARRIVE() asm volatile("barrier.cluster.arrive.aligned;" ::: "memory")
#define CLUSTER_WAIT()   asm volatile("barrier.cluster.wait.aligned;" ::: "memory")

// ----------------------------- K0: weight prep ------------------------------
__global__ void prep_kernel(WPtrs p) {
    int l = blockIdx.y;
    int stride = gridDim.x * blockDim.x;
    int start = blockIdx.x * blockDim.x + threadIdx.x;
    for (int i = start; i < GDIM * EPAD; i += stride) {
        int n = i / EPAD;
        int k = i - n * EPAD;
        d_Wih[l][i] = __float2bfloat16_rn((k < EDIM) ? p.wih[l][(size_t)n * EDIM + k] : 0.f);
    }
    for (int i = start; i < GDIM * HDIM; i += stride)
        d_Whh[l][i] = __float2bfloat16_rn(p.whh[l][i]);
    for (int i = start; i < GDIM; i += stride)
        d_bias[l][i] = p.bih[l][i] + p.bhh[l][i];
}

// ----------------------------- K1: embedding gather -------------------------
__global__ void embed_kernel(const int* __restrict__ sen_src,
                             const int* __restrict__ tgt_src,
                             const float* __restrict__ emb) {
    int row = blockIdx.x;
    int tid = threadIdx.x;  // 320 threads == EPAD
    if (row < LS * NB) {
        int t = row / NB, b = row % NB;
        int idx = sen_src[b * LS + t];
        float v = (idx == 0 || tid >= EDIM) ? 0.f : emb[(size_t)idx * EDIM + tid];
        d_x_sen[(size_t)row * EPAD + tid] = __float2bfloat16_rn(v);
    } else {
        int r = row - LS * NB;
        int t = r / NB, b = r % NB;
        int idx = tgt_src[b * LT + t];
        float v = (idx == 0 || tid >= EDIM) ? 0.f : emb[(size_t)idx * EDIM + tid];
        d_x_tgt[(size_t)r * EPAD + tid] = __float2bfloat16_rn(v);
    }
}

// ----------------------------- K2: input projection GEMM (bf16 wmma) --------
#define GBM 128
#define GBN 128
#define GBK 64
#define GLD 72

__global__ __launch_bounds__(256) void gemm_xw() {
    int l = blockIdx.z;
    if (l >= 2 && blockIdx.x >= (LT * NB / GBM)) return;

    const __nv_bfloat16* __restrict__ X = (l < 2) ? d_x_sen : d_x_tgt;
    const __nv_bfloat16* __restrict__ W = d_Wih[l];
    float* __restrict__ C = (l < 2) ? d_gates_sen[l] : d_gates_tgt[l - 2];

    __shared__ __align__(128) __nv_bfloat16 As[GBM * GLD];
    __shared__ __align__(128) __nv_bfloat16 Bs[GBN * GLD];

    int tid = threadIdx.x;
    int warp = tid >> 5;
    int wm = warp & 1;
    int wn = warp >> 1;
    int m0 = blockIdx.x * GBM;
    int n0 = blockIdx.y * GBN;

    wmma::fragment<wmma::accumulator, 16, 16, 16, float> acc[4][2];
    #pragma unroll
    for (int mi = 0; mi < 4; mi++)
        #pragma unroll
        for (int ni = 0; ni < 2; ni++) wmma::fill_fragment(acc[mi][ni], 0.f);

    for (int kc = 0; kc < EPAD; kc += GBK) {
        int r0 = tid >> 3;
        int c  = (tid & 7) * 8;
        #pragma unroll
        for (int i = 0; i < 4; i++) {
            int r = r0 + i * 32;
            *(uint4*)&As[r * GLD + c] = *(const uint4*)&X[(size_t)(m0 + r) * EPAD + kc + c];
            *(uint4*)&Bs[r * GLD + c] = *(const uint4*)&W[(size_t)(n0 + r) * EPAD + kc + c];
        }
        __syncthreads();
        #pragma unroll
        for (int kk = 0; kk < GBK; kk += 16) {
            wmma::fragment<wmma::matrix_a, 16, 16, 16, __nv_bfloat16, wmma::row_major> af[4];
            wmma::fragment<wmma::matrix_b, 16, 16, 16, __nv_bfloat16, wmma::col_major> bf[2];
            #pragma unroll
            for (int mi = 0; mi < 4; mi++)
                wmma::load_matrix_sync(af[mi], &As[(wm * 64 + mi * 16) * GLD + kk], GLD);
            #pragma unroll
            for (int ni = 0; ni < 2; ni++)
                wmma::load_matrix_sync(bf[ni], &Bs[(wn * 32 + ni * 16) * GLD + kk], GLD);
            #pragma unroll
            for (int mi = 0; mi < 4; mi++)
                #pragma unroll
                for (int ni = 0; ni < 2; ni++)
                    wmma::mma_sync(acc[mi][ni], af[mi], bf[ni], acc[mi][ni]);
        }
        __syncthreads();
    }
    #pragma unroll
    for (int mi = 0; mi < 4; mi++)
        #pragma unroll
        for (int ni = 0; ni < 2; ni++)
            wmma::store_matrix_sync(
                &C[(size_t)(m0 + wm * 64 + mi * 16) * GDIM + n0 + wn * 32 + ni * 16],
                acc[mi][ni], GDIM, wmma::mem_row_major);
}

// ----------------------------- K3: LSTM recurrence (cluster, split-K) -------
// Cluster of 4 CTAs per (lstm, batch-chunk-of-16). CTA rank r owns hidden
// units [r*64, r*64+64). 512 threads: 16 warps, warp w = (K-half w>>3,
// col-slice (w&7)*32); partial gates summed in elementwise. One cluster
// barrier per step; x prefetch + Hout stores in the barrier shadow.
#define BCH    16
#define SLC    64                       // hidden units per CTA
#define WLD    264                      // smem leading dim
#define W_SZ   (256 * WLD * 2)          // 135168 B
#define H_SZ   (BCH * WLD * 2)          // 8448 B per h buffer
#define G_SZ   (BCH * WLD * 4)          // 16896 B per partial-gate buffer
#define LSTM_SMEM (W_SZ + 2 * H_SZ + 2 * G_SZ)   // 185856 B

__global__ void __cluster_dims__(4, 1, 1) __launch_bounds__(512, 1) lstm_kernel() {
    extern __shared__ __align__(128) unsigned char smem[];
    __nv_bfloat16* Wsh   = (__nv_bfloat16*)smem;                        // [256][264]
    __nv_bfloat16* hbuf  = (__nv_bfloat16*)(smem + W_SZ);               // [2][16][264]
    float*         gatesA = (float*)(smem + W_SZ + 2 * H_SZ);           // [16][264]
    float*         gatesB = (float*)(smem + W_SZ + 2 * H_SZ + G_SZ);    // [16][264]

    int bx   = blockIdx.x;
    int cid  = bx >> 2;                 // cluster id 0..31
    int lstm = cid >> 3;                // 0=sf 1=sb 2=tf 3=tb
    int b0   = (cid & 7) * BCH;
    uint32_t r = cluster_rank();        // 0..3
    int T    = (lstm < 2) ? LS : LT;
    bool rev = (lstm & 1);
    const __nv_bfloat16* __restrict__ Wg = d_Whh[lstm];
    const float* __restrict__ Xg   = (lstm < 2) ? d_gates_sen[lstm] : d_gates_tgt[lstm - 2];
    float* __restrict__       Hout = (lstm < 2) ? d_h_sen[lstm]     : d_h_tgt[lstm - 2];

    int tid   = threadIdx.x;            // 0..511
    int warp  = tid >> 5;               // 0..15
    int wcol  = warp & 7;               // col slice (32 gates)
    int khalf = warp >> 3;              // 0 or 1 (K half)
    int u     = tid & 63;               // hidden unit within slice
    int kbg   = (tid >> 6) & 7;         // batch group 0..7
    int r64u  = (int)r * SLC + u;       // global hidden unit

    // ---- load resident Whh slice: local row lr = g*64+u  <- global row g*256+r64u
    for (int i = tid; i < 256 * 32; i += 512) {
        int lr = i >> 5;
        int c8 = i & 31;
        int n  = ((lr >> 6) << 8) + (int)r * SLC + (lr & 63);
        *(uint4*)&Wsh[lr * WLD + c8 * 8] = *(const uint4*)&Wg[(size_t)n * HDIM + c8 * 8];
    }
    // ---- zero both h buffers
    for (int i = tid; i < 2 * BCH * WLD; i += 512) hbuf[i] = __float2bfloat16_rn(0.f);

    float c[2] = {0.f, 0.f};
    const float bi  = d_bias[lstm][r64u];
    const float bf_ = d_bias[lstm][r64u + 256];
    const float bg  = d_bias[lstm][r64u + 512];
    const float bo  = d_bias[lstm][r64u + 768];

    uint32_t hbase_u32 = smem_u32(hbuf);
    float* gatesK = khalf ? gatesB : gatesA;

    // ---- prefetch x-gates for step 0
    float xv[2][4];
    {
        int t0 = rev ? (T - 1) : 0;
        const float* xgt = Xg + (size_t)(t0 * NB + b0) * GDIM;
        #pragma unroll
        for (int j = 0; j < 2; j++) {
            const float* xr = xgt + (size_t)(j * 8 + kbg) * GDIM;
            xv[j][0] = xr[r64u];
            xv[j][1] = xr[r64u + 256];
            xv[j][2] = xr[r64u + 512];
            xv[j][3] = xr[r64u + 768];
        }
    }

    __syncthreads();
    CLUSTER_ARRIVE();
    CLUSTER_WAIT();

    for (int step = 0; step < T; step++) {
        int t = rev ? (T - 1 - step) : step;
        const __nv_bfloat16* hcur = hbuf + (step & 1) * (BCH * WLD);
        uint32_t hnxt_u32 = hbase_u32 + (uint32_t)(((step & 1) ^ 1) * H_SZ);

        // ---- partial gates: this warp covers K in [khalf*128, +128), cols wcol*32..+32
        {
            wmma::fragment<wmma::accumulator, 16, 16, 16, float> acc0, acc1;
            wmma::fill_fragment(acc0, 0.f);
            wmma::fill_fragment(acc1, 0.f);
            #pragma unroll
            for (int i = 0; i < 8; i++) {
                int kk = khalf * 8 + i;
                wmma::fragment<wmma::matrix_a, 16, 16, 16, __nv_bfloat16, wmma::row_major> af;
                wmma::load_matrix_sync(af, &hcur[kk * 16], WLD);
                wmma::fragment<wmma::matrix_b, 16, 16, 16, __nv_bfloat16, wmma::col_major> b0f, b1f;
                wmma::load_matrix_sync(b0f, &Wsh[(wcol * 32) * WLD + kk * 16], WLD);
                wmma::load_matrix_sync(b1f, &Wsh[(wcol * 32 + 16) * WLD + kk * 16], WLD);
                wmma::mma_sync(acc0, af, b0f, acc0);
                wmma::mma_sync(acc1, af, b1f, acc1);
            }
            wmma::store_matrix_sync(&gatesK[wcol * 32], acc0, WLD, wmma::mem_row_major);
            wmma::store_matrix_sync(&gatesK[wcol * 32 + 16], acc1, WLD, wmma::mem_row_major);
        }
        __syncthreads();

        // ---- elementwise (prefetched x, summed partials) + direct DSMEM scatter
        float hvv[2];
        #pragma unroll
        for (int j = 0; j < 2; j++) {
            int kb = j * 8 + kbg;
            int rw = kb * WLD;
            float gi = gatesA[rw + u]       + gatesB[rw + u]       + xv[j][0] + bi;
            float gf = gatesA[rw + 64 + u]  + gatesB[rw + 64 + u]  + xv[j][1] + bf_;
            float gg = gatesA[rw + 128 + u] + gatesB[rw + 128 + u] + xv[j][2] + bg;
            float go = gatesA[rw + 192 + u] + gatesB[rw + 192 + u] + xv[j][3] + bo;
            float cn = sigf(gf) * c[j] + sigf(gi) * tanhf_(gg);
            c[j] = cn;
            float hv = sigf(go) * tanhf_(cn);
            hvv[j] = hv;
            __nv_bfloat16 hb = __float2bfloat16_rn(hv);
            uint32_t off = hnxt_u32 + (uint32_t)(kb * WLD + r64u) * 2u;
            #pragma unroll
            for (uint32_t rk = 0; rk < 4; rk++) st_dsmem_b16(off, rk, hb);
        }
        CLUSTER_ARRIVE();

        // ---- latency shadow: Hout stores + next-step x prefetch
        {
            float* hrow = Hout + (size_t)(t * NB + b0) * HDIM;
            #pragma unroll
            for (int j = 0; j < 2; j++)
                hrow[(size_t)(j * 8 + kbg) * HDIM + r64u] = hvv[j];
        }
        if (step + 1 < T) {
            int tn = rev ? (T - 2 - step) : (step + 1);
            const float* xgt = Xg + (size_t)(tn * NB + b0) * GDIM;
            #pragma unroll
            for (int j = 0; j < 2; j++) {
                const float* xr = xgt + (size_t)(j * 8 + kbg) * GDIM;
                xv[j][0] = xr[r64u];
                xv[j][1] = xr[r64u + 256];
                xv[j][2] = xr[r64u + 512];
                xv[j][3] = xr[r64u + 768];
            }
        }
        CLUSTER_WAIT();
    }
}

// ----------------------------- K4: attention + output (fp32) ----------------
__global__ __launch_bounds__(256) void attn_kernel(const float* __restrict__ Wout,
                                                   const float* __restrict__ bout,
                                                   float* __restrict__ out) {
    int b = blockIdx.x;
    int tid = threadIdx.x;
    int lane = tid & 31, warp = tid >> 5;

    __shared__ float tgt_s[LT][2 * HDIM];
    __shared__ float A_s[LS][LT];
    __shared__ float colmax[LT];
    __shared__ float colsum[LT];
    __shared__ float rowvec[LT];
    __shared__ float attn_s[LS];
    __shared__ float score_s[2 * HDIM];
    __shared__ float logit[NOUT];

    for (int i = tid; i < LT * 2 * HDIM; i += 256) {
        int t = i >> 9;
        int mm = i & 511;
        tgt_s[t][mm] = (mm < HDIM)
            ? d_h_tgt[0][((size_t)t * NB + b) * HDIM + mm]
            : d_h_tgt[1][((size_t)t * NB + b) * HDIM + (mm - HDIM)];
    }
    if (tid < LT) rowvec[tid] = 0.f;
    __syncthreads();

    for (int s = warp; s < LS; s += 8) {
        float p[LT];
        #pragma unroll
        for (int t = 0; t < LT; t++) p[t] = 0.f;
        const float* f0 = &d_h_sen[0][((size_t)s * NB + b) * HDIM];
        const float* f1 = &d_h_sen[1][((size_t)s * NB + b) * HDIM];
        for (int mm = lane; mm < HDIM; mm += 32) {
            float v0 = f0[mm], v1 = f1[mm];
            #pragma unroll
            for (int t = 0; t < LT; t++)
                p[t] += v0 * tgt_s[t][mm] + v1 * tgt_s[t][HDIM + mm];
        }
        #pragma unroll
        for (int t = 0; t < LT; t++) {
            #pragma unroll
            for (int o = 16; o; o >>= 1) p[t] += __shfl_xor_sync(0xffffffffu, p[t], o);
            if (lane == 0) A_s[s][t] = p[t];
        }
    }
    __syncthreads();

    if (tid < LT) {
        float mx = -1e30f;
        for (int s = 0; s < LS; s++) mx = fmaxf(mx, A_s[s][tid]);
        float sm = 0.f;
        for (int s = 0; s < LS; s++) sm += expf(A_s[s][tid] - mx);
        colmax[tid] = mx;
        colsum[tid] = sm;
    }
    if (tid < LS) {
        float mx = -1e30f;
        #pragma unroll
        for (int t = 0; t < LT; t++) mx = fmaxf(mx, A_s[tid][t]);
        float e[LT], sm = 0.f;
        #pragma unroll
        for (int t = 0; t < LT; t++) { e[t] = expf(A_s[tid][t] - mx); sm += e[t]; }
        float inv = 1.f / (sm * (float)LS);
        #pragma unroll
        for (int t = 0; t < LT; t++) atomicAdd(&rowvec[t], e[t] * inv);
    }
    __syncthreads();

    if (tid < LS) {
        float a = 0.f;
        #pragma unroll
        for (int t = 0; t < LT; t++)
            a += (expf(A_s[tid][t] - colmax[t]) / colsum[t]) * rowvec[t];
        attn_s[tid] = a;
    }
    __syncthreads();

    // score[h] = sum_s attn[s] * sen_h[b,s,h]  (4-way ILP over s)
    for (int mm = tid; mm < 2 * HDIM; mm += 256) {
        const float* hp = (mm < HDIM) ? d_h_sen[0] : d_h_sen[1];
        int m2 = mm & (HDIM - 1);
        float a0 = 0.f, a1 = 0.f, a2 = 0.f, a3 = 0.f;
        #pragma unroll 4
        for (int s = 0; s < LS; s += 4) {
            a0 += attn_s[s]     * hp[((size_t)(s)     * NB + b) * HDIM + m2];
            a1 += attn_s[s + 1] * hp[((size_t)(s + 1) * NB + b) * HDIM + m2];
            a2 += attn_s[s + 2] * hp[((size_t)(s + 2) * NB + b) * HDIM + m2];
            a3 += attn_s[s + 3] * hp[((size_t)(s + 3) * NB + b) * HDIM + m2];
        }
        score_s[mm] = (a0 + a1) + (a2 + a3);
    }
    __syncthreads();

    if (warp < NOUT) {
        float acc = 0.f;
        for (int mm = lane; mm < 2 * HDIM; mm += 32)
            acc += score_s[mm] * Wout[warp * 2 * HDIM + mm];
        #pragma unroll
        for (int o = 16; o; o >>= 1) acc += __shfl_xor_sync(0xffffffffu, acc, o);
        if (lane == 0) logit[warp] = acc + bout[warp];
    }
    __syncthreads();

    if (tid == 0) {
        float mx = fmaxf(logit[0], fmaxf(logit[1], logit[2]));
        float e0 = expf(logit[0] - mx);
        float e1 = expf(logit[1] - mx);
        float e2 = expf(logit[2] - mx);
        float inv = 1.f / (e0 + e1 + e2);
        out[b * NOUT + 0] = e0 * inv;
        out[b * NOUT + 1] = e1 * inv;
        out[b * NOUT + 2] = e2 * inv;
    }
}

// ----------------------------- launch ---------------------------------------
extern "C" void kernel_launch(void* const* d_in, const int* in_sizes, int n_in,
                              void* d_out, int out_size) {
    const int*   sen_src = (const int*)d_in[0];
    const int*   tgt_src = (const int*)d_in[1];
    const float* emb     = (const float*)d_in[2];
    WPtrs wp;
    for (int l = 0; l < 4; l++) {
        wp.wih[l] = (const float*)d_in[3 + 4 * l];
        wp.whh[l] = (const float*)d_in[4 + 4 * l];
        wp.bih[l] = (const float*)d_in[5 + 4 * l];
        wp.bhh[l] = (const float*)d_in[6 + 4 * l];
    }
    const float* Wout = (const float*)d_in[19];
    const float* bout = (const float*)d_in[20];
    float* out = (float*)d_out;

    cudaFuncSetAttribute(lstm_kernel, cudaFuncAttributeMaxDynamicSharedMemorySize, LSTM_SMEM);

    prep_kernel<<<dim3(256, 4), 256>>>(wp);
    embed_kernel<<<(LS + LT) * NB, EPAD>>>(sen_src, tgt_src, emb);
    gemm_xw<<<dim3(LS * NB / GBM, GDIM / GBN, 4), 256>>>();
    lstm_kernel<<<128, 512, LSTM_SMEM>>>();   // 32 clusters x 4 CTAs
    attn_kernel<<<NB, 256>>>(Wout, bout, out);
}

// round 14
// speedup vs baseline: 9.6861x; 1.0819x over previous
#include <cuda_runtime.h>
#include <cuda_bf16.h>
#include <cstdint>
#include <math.h>
#include <mma.h>

using namespace nvcuda;

#define NB   128   // batch
#define LS   128   // sentence length
#define LT   8     // target length
#define EDIM 300   // true embedding dim (E=300)
#define EPAD 320   // padded embedding dim
#define HDIM 256
#define GDIM 1024  // 4*H
#define NOUT 3

// ----------------------------- scratch (static __device__, no allocs) ------
__device__ __align__(128) __nv_bfloat16 d_x_sen[LS * NB * EPAD];   // [t][b][e] zero-pad
__device__ __align__(128) __nv_bfloat16 d_x_tgt[LT * NB * EPAD];
__device__ __align__(128) __nv_bfloat16 d_Wih[4][GDIM * EPAD];     // zero-pad [n][k]
__device__ __align__(128) __nv_bfloat16 d_Whh[4][GDIM * HDIM];     // [n][k] row-major
__device__ __align__(128) float d_bias[4][GDIM];                   // bih+bhh
__device__ __align__(128) float d_gates_sen[2][LS * NB * GDIM];
__device__ __align__(128) float d_gates_tgt[2][LT * NB * GDIM];
__device__ __align__(128) float d_h_sen[2][LS * NB * HDIM];        // [t][b][h]
__device__ __align__(128) float d_h_tgt[2][LT * NB * HDIM];

struct WPtrs {
    const float* wih[4];
    const float* whh[4];
    const float* bih[4];
    const float* bhh[4];
};

// MUFU.TANH-based activations: tanh.approx max abs err ~6e-4 on gates,
// far below the bf16 h-noise floor (4e-3) that already passes at 1.3e-5.
__device__ __forceinline__ float tanh_fast(float x) {
    float y;
    asm("tanh.approx.f32 %0, %1;" : "=f"(y) : "f"(x));
    return y;
}
__device__ __forceinline__ float sig_fast(float x) {
    return 0.5f + 0.5f * tanh_fast(0.5f * x);
}

__device__ __forceinline__ uint32_t smem_u32(const void* p) {
    uint32_t a;
    asm("{ .reg .u64 t; cvta.to.shared.u64 t, %1; cvt.u32.u64 %0, t; }" : "=r"(a) : "l"(p));
    return a;
}
__device__ __forceinline__ uint32_t cluster_rank() {
    uint32_t r;
    asm("mov.u32 %0, %%cluster_ctarank;" : "=r"(r));
    return r;
}
__device__ __forceinline__ void st_dsmem_u128(uint32_t laddr, uint32_t rank, uint4 v) {
    asm volatile(
        "{\n\t.reg .b32 ra;\n\t"
        "mapa.shared::cluster.u32 ra, %0, %1;\n\t"
        "st.shared::cluster.v4.b32 [ra], {%2, %3, %4, %5};\n\t}"
        :: "r"(laddr), "r"(rank), "r"(v.x), "r"(v.y), "r"(v.z), "r"(v.w) : "memory");
}
#define CLUSTER_ARRIVE() asm volatile("barrier.cluster.arrive.aligned;" ::: "memory")
#define CLUSTER_WAIT()   asm volatile("barrier.cluster.wait.aligned;" ::: "memory")

// ----------------------------- K0: weight prep ------------------------------
__global__ void prep_kernel(WPtrs p) {
    int l = blockIdx.y;
    int stride = gridDim.x * blockDim.x;
    int start = blockIdx.x * blockDim.x + threadIdx.x;
    for (int i = start; i < GDIM * EPAD; i += stride) {
        int n = i / EPAD;
        int k = i - n * EPAD;
        d_Wih[l][i] = __float2bfloat16_rn((k < EDIM) ? p.wih[l][(size_t)n * EDIM + k] : 0.f);
    }
    for (int i = start; i < GDIM * HDIM; i += stride)
        d_Whh[l][i] = __float2bfloat16_rn(p.whh[l][i]);
    for (int i = start; i < GDIM; i += stride)
        d_bias[l][i] = p.bih[l][i] + p.bhh[l][i];
}

// ----------------------------- K1: embedding gather -------------------------
__global__ void embed_kernel(const int* __restrict__ sen_src,
                             const int* __restrict__ tgt_src,
                             const float* __restrict__ emb) {
    int row = blockIdx.x;
    int tid = threadIdx.x;  // 320 threads == EPAD
    if (row < LS * NB) {
        int t = row / NB, b = row % NB;
        int idx = sen_src[b * LS + t];
        float v = (idx == 0 || tid >= EDIM) ? 0.f : emb[(size_t)idx * EDIM + tid];
        d_x_sen[(size_t)row * EPAD + tid] = __float2bfloat16_rn(v);
    } else {
        int r = row - LS * NB;
        int t = r / NB, b = r % NB;
        int idx = tgt_src[b * LT + t];
        float v = (idx == 0 || tid >= EDIM) ? 0.f : emb[(size_t)idx * EDIM + tid];
        d_x_tgt[(size_t)r * EPAD + tid] = __float2bfloat16_rn(v);
    }
}

// ----------------------------- K2: input projection GEMM (bf16 wmma) --------
#define GBM 128
#define GBN 128
#define GBK 64
#define GLD 72

__global__ __launch_bounds__(256) void gemm_xw() {
    int l = blockIdx.z;
    if (l >= 2 && blockIdx.x >= (LT * NB / GBM)) return;

    const __nv_bfloat16* __restrict__ X = (l < 2) ? d_x_sen : d_x_tgt;
    const __nv_bfloat16* __restrict__ W = d_Wih[l];
    float* __restrict__ C = (l < 2) ? d_gates_sen[l] : d_gates_tgt[l - 2];

    __shared__ __align__(128) __nv_bfloat16 As[GBM * GLD];
    __shared__ __align__(128) __nv_bfloat16 Bs[GBN * GLD];

    int tid = threadIdx.x;
    int warp = tid >> 5;
    int wm = warp & 1;
    int wn = warp >> 1;
    int m0 = blockIdx.x * GBM;
    int n0 = blockIdx.y * GBN;

    wmma::fragment<wmma::accumulator, 16, 16, 16, float> acc[4][2];
    #pragma unroll
    for (int mi = 0; mi < 4; mi++)
        #pragma unroll
        for (int ni = 0; ni < 2; ni++) wmma::fill_fragment(acc[mi][ni], 0.f);

    for (int kc = 0; kc < EPAD; kc += GBK) {
        int r0 = tid >> 3;
        int c  = (tid & 7) * 8;
        #pragma unroll
        for (int i = 0; i < 4; i++) {
            int r = r0 + i * 32;
            *(uint4*)&As[r * GLD + c] = *(const uint4*)&X[(size_t)(m0 + r) * EPAD + kc + c];
            *(uint4*)&Bs[r * GLD + c] = *(const uint4*)&W[(size_t)(n0 + r) * EPAD + kc + c];
        }
        __syncthreads();
        #pragma unroll
        for (int kk = 0; kk < GBK; kk += 16) {
            wmma::fragment<wmma::matrix_a, 16, 16, 16, __nv_bfloat16, wmma::row_major> af[4];
            wmma::fragment<wmma::matrix_b, 16, 16, 16, __nv_bfloat16, wmma::col_major> bf[2];
            #pragma unroll
            for (int mi = 0; mi < 4; mi++)
                wmma::load_matrix_sync(af[mi], &As[(wm * 64 + mi * 16) * GLD + kk], GLD);
            #pragma unroll
            for (int ni = 0; ni < 2; ni++)
                wmma::load_matrix_sync(bf[ni], &Bs[(wn * 32 + ni * 16) * GLD + kk], GLD);
            #pragma unroll
            for (int mi = 0; mi < 4; mi++)
                #pragma unroll
                for (int ni = 0; ni < 2; ni++)
                    wmma::mma_sync(acc[mi][ni], af[mi], bf[ni], acc[mi][ni]);
        }
        __syncthreads();
    }
    #pragma unroll
    for (int mi = 0; mi < 4; mi++)
        #pragma unroll
        for (int ni = 0; ni < 2; ni++)
            wmma::store_matrix_sync(
                &C[(size_t)(m0 + wm * 64 + mi * 16) * GDIM + n0 + wn * 32 + ni * 16],
                acc[mi][ni], GDIM, wmma::mem_row_major);
}

// ----------------------------- K3: LSTM recurrence (cluster, reg-B) ---------
// Cluster of 4 CTAs per (lstm, batch-chunk-of-16). CTA rank r owns hidden
// units [r*64,+64). 512 threads, 16 warps: warp w covers K-half (w>>3) and
// col-slice (w&7)*32, with its constant Whh B-fragments held in REGISTERS.
// Per step: 8 A-LDSM + 16 HMMA -> sync -> tanh.approx elementwise -> stage
// -> sync -> wide DSMEM broadcast -> cluster barrier (x prefetch in shadow).
#define BCH    16
#define SLC    64                       // hidden units per CTA
#define WLD    264                      // smem leading dim
#define W_SZ   (256 * WLD * 2)          // 135168 B
#define H_SZ   (BCH * WLD * 2)          // 8448 B per h buffer
#define G_SZ   (BCH * WLD * 4)          // 16896 B per partial-gate buffer
#define S_SZ   (BCH * SLC * 2)          // 2048 B staging
#define LSTM_SMEM (W_SZ + 2 * H_SZ + 2 * G_SZ + S_SZ)   // 187904 B

__global__ void __cluster_dims__(4, 1, 1) __launch_bounds__(512, 1) lstm_kernel() {
    extern __shared__ __align__(128) unsigned char smem[];
    __nv_bfloat16* Wsh    = (__nv_bfloat16*)smem;                        // [256][264]
    __nv_bfloat16* hbuf   = (__nv_bfloat16*)(smem + W_SZ);               // [2][16][264]
    float*         gatesA = (float*)(smem + W_SZ + 2 * H_SZ);            // [16][264]
    float*         gatesB = (float*)(smem + W_SZ + 2 * H_SZ + G_SZ);     // [16][264]
    __nv_bfloat16* hstg   = (__nv_bfloat16*)(smem + W_SZ + 2 * H_SZ + 2 * G_SZ); // [16][64]

    int bx   = blockIdx.x;
    int cid  = bx >> 2;                 // cluster id 0..31
    int lstm = cid >> 3;                // 0=sf 1=sb 2=tf 3=tb
    int b0   = (cid & 7) * BCH;
    uint32_t r = cluster_rank();        // 0..3
    int T    = (lstm < 2) ? LS : LT;
    bool rev = (lstm & 1);
    const __nv_bfloat16* __restrict__ Wg = d_Whh[lstm];
    const float* __restrict__ Xg   = (lstm < 2) ? d_gates_sen[lstm] : d_gates_tgt[lstm - 2];
    float* __restrict__       Hout = (lstm < 2) ? d_h_sen[lstm]     : d_h_tgt[lstm - 2];

    int tid   = threadIdx.x;            // 0..511
    int warp  = tid >> 5;               // 0..15
    int wcol  = warp & 7;               // col slice (32 gates)
    int khalf = warp >> 3;              // 0 or 1 (K half)
    int u     = tid & 63;               // hidden unit within slice
    int kbg   = (tid >> 6) & 7;         // batch group 0..7
    int r64u  = (int)r * SLC + u;       // global hidden unit

    // ---- load resident Whh slice: local row lr = g*64+u  <- global row g*256+r64u
    for (int i = tid; i < 256 * 32; i += 512) {
        int lr = i >> 5;
        int c8 = i & 31;
        int n  = ((lr >> 6) << 8) + (int)r * SLC + (lr & 63);
        *(uint4*)&Wsh[lr * WLD + c8 * 8] = *(const uint4*)&Wg[(size_t)n * HDIM + c8 * 8];
    }
    // ---- zero both h buffers
    for (int i = tid; i < 2 * BCH * WLD; i += 512) hbuf[i] = __float2bfloat16_rn(0.f);

    float c[2] = {0.f, 0.f};
    const float bi  = d_bias[lstm][r64u];
    const float bf_ = d_bias[lstm][r64u + 256];
    const float bg  = d_bias[lstm][r64u + 512];
    const float bo  = d_bias[lstm][r64u + 768];

    uint32_t hbase_u32 = smem_u32(hbuf);
    uint32_t hstg_u32  = smem_u32(hstg);
    float* gatesK = khalf ? gatesB : gatesA;
    __syncthreads();

    // ---- preload this warp's constant Whh B-fragments into registers
    wmma::fragment<wmma::matrix_b, 16, 16, 16, __nv_bfloat16, wmma::col_major> bfr[8][2];
    #pragma unroll
    for (int i = 0; i < 8; i++) {
        int kk = khalf * 8 + i;
        wmma::load_matrix_sync(bfr[i][0], &Wsh[(wcol * 32) * WLD + kk * 16], WLD);
        wmma::load_matrix_sync(bfr[i][1], &Wsh[(wcol * 32 + 16) * WLD + kk * 16], WLD);
    }

    // ---- prefetch x-gates for step 0
    float xv[2][4];
    {
        int t0 = rev ? (T - 1) : 0;
        const float* xgt = Xg + (size_t)(t0 * NB + b0) * GDIM;
        #pragma unroll
        for (int j = 0; j < 2; j++) {
            const float* xr = xgt + (size_t)(j * 8 + kbg) * GDIM;
            xv[j][0] = xr[r64u];
            xv[j][1] = xr[r64u + 256];
            xv[j][2] = xr[r64u + 512];
            xv[j][3] = xr[r64u + 768];
        }
    }

    CLUSTER_ARRIVE();
    CLUSTER_WAIT();

    for (int step = 0; step < T; step++) {
        int t = rev ? (T - 1 - step) : step;
        const __nv_bfloat16* hcur = hbuf + (step & 1) * (BCH * WLD);
        uint32_t hnxt_u32 = hbase_u32 + (uint32_t)(((step & 1) ^ 1) * H_SZ);

        // ---- partial gates: 8 A-LDSM + 16 HMMA (B in registers)
        {
            wmma::fragment<wmma::accumulator, 16, 16, 16, float> acc0, acc1;
            wmma::fill_fragment(acc0, 0.f);
            wmma::fill_fragment(acc1, 0.f);
            #pragma unroll
            for (int i = 0; i < 8; i++) {
                int kk = khalf * 8 + i;
                wmma::fragment<wmma::matrix_a, 16, 16, 16, __nv_bfloat16, wmma::row_major> af;
                wmma::load_matrix_sync(af, &hcur[kk * 16], WLD);
                wmma::mma_sync(acc0, af, bfr[i][0], acc0);
                wmma::mma_sync(acc1, af, bfr[i][1], acc1);
            }
            wmma::store_matrix_sync(&gatesK[wcol * 32], acc0, WLD, wmma::mem_row_major);
            wmma::store_matrix_sync(&gatesK[wcol * 32 + 16], acc1, WLD, wmma::mem_row_major);
        }
        __syncthreads();

        // ---- elementwise (tanh.approx) -> stage + Hout
        float* hrow = Hout + (size_t)(t * NB + b0) * HDIM;
        #pragma unroll
        for (int j = 0; j < 2; j++) {
            int kb = j * 8 + kbg;
            int rw = kb * WLD;
            float gi = gatesA[rw + u]       + gatesB[rw + u]       + xv[j][0] + bi;
            float gf = gatesA[rw + 64 + u]  + gatesB[rw + 64 + u]  + xv[j][1] + bf_;
            float gg = gatesA[rw + 128 + u] + gatesB[rw + 128 + u] + xv[j][2] + bg;
            float go = gatesA[rw + 192 + u] + gatesB[rw + 192 + u] + xv[j][3] + bo;
            float cn = sig_fast(gf) * c[j] + sig_fast(gi) * tanh_fast(gg);
            c[j] = cn;
            float hv = sig_fast(go) * tanh_fast(cn);
            hstg[kb * SLC + u] = __float2bfloat16_rn(hv);
            hrow[(size_t)kb * HDIM + r64u] = hv;
        }
        __syncthreads();

        // ---- wide broadcast: 512 uint4 msgs (4 ranks x 128), 1 per thread
        {
            int rk = tid >> 7;          // target rank 0..3
            int j  = tid & 127;
            int kb = j >> 3;
            int q  = j & 7;
            uint4 v = *(const uint4*)(hstg + kb * SLC + q * 8);
            uint32_t dst = hnxt_u32 +
                (uint32_t)((kb * WLD + (int)r * SLC) * 2 + q * 16);
            st_dsmem_u128(dst, (uint32_t)rk, v);
        }
        CLUSTER_ARRIVE();

        // ---- latency shadow: next-step x prefetch
        if (step + 1 < T) {
            int tn = rev ? (T - 2 - step) : (step + 1);
            const float* xgt = Xg + (size_t)(tn * NB + b0) * GDIM;
            #pragma unroll
            for (int j = 0; j < 2; j++) {
                const float* xr = xgt + (size_t)(j * 8 + kbg) * GDIM;
                xv[j][0] = xr[r64u];
                xv[j][1] = xr[r64u + 256];
                xv[j][2] = xr[r64u + 512];
                xv[j][3] = xr[r64u + 768];
            }
        }
        CLUSTER_WAIT();
    }
}

// ----------------------------- K4: attention + output (fp32) ----------------
__global__ __launch_bounds__(256) void attn_kernel(const float* __restrict__ Wout,
                                                   const float* __restrict__ bout,
                                                   float* __restrict__ out) {
    int b = blockIdx.x;
    int tid = threadIdx.x;
    int lane = tid & 31, warp = tid >> 5;

    __shared__ float tgt_s[LT][2 * HDIM];
    __shared__ float A_s[LS][LT];
    __shared__ float colmax[LT];
    __shared__ float colsum[LT];
    __shared__ float rowvec[LT];
    __shared__ float attn_s[LS];
    __shared__ float score_s[2 * HDIM];
    __shared__ float logit[NOUT];

    for (int i = tid; i < LT * 2 * HDIM; i += 256) {
        int t = i >> 9;
        int mm = i & 511;
        tgt_s[t][mm] = (mm < HDIM)
            ? d_h_tgt[0][((size_t)t * NB + b) * HDIM + mm]
            : d_h_tgt[1][((size_t)t * NB + b) * HDIM + (mm - HDIM)];
    }
    if (tid < LT) rowvec[tid] = 0.f;
    __syncthreads();

    for (int s = warp; s < LS; s += 8) {
        float p[LT];
        #pragma unroll
        for (int t = 0; t < LT; t++) p[t] = 0.f;
        const float* f0 = &d_h_sen[0][((size_t)s * NB + b) * HDIM];
        const float* f1 = &d_h_sen[1][((size_t)s * NB + b) * HDIM];
        for (int mm = lane; mm < HDIM; mm += 32) {
            float v0 = f0[mm], v1 = f1[mm];
            #pragma unroll
            for (int t = 0; t < LT; t++)
                p[t] += v0 * tgt_s[t][mm] + v1 * tgt_s[t][HDIM + mm];
        }
        #pragma unroll
        for (int t = 0; t < LT; t++) {
            #pragma unroll
            for (int o = 16; o; o >>= 1) p[t] += __shfl_xor_sync(0xffffffffu, p[t], o);
            if (lane == 0) A_s[s][t] = p[t];
        }
    }
    __syncthreads();

    if (tid < LT) {
        float mx = -1e30f;
        for (int s = 0; s < LS; s++) mx = fmaxf(mx, A_s[s][tid]);
        float sm = 0.f;
        for (int s = 0; s < LS; s++) sm += expf(A_s[s][tid] - mx);
        colmax[tid] = mx;
        colsum[tid] = sm;
    }
    if (tid < LS) {
        float mx = -1e30f;
        #pragma unroll
        for (int t = 0; t < LT; t++) mx = fmaxf(mx, A_s[tid][t]);
        float e[LT], sm = 0.f;
        #pragma unroll
        for (int t = 0; t < LT; t++) { e[t] = expf(A_s[tid][t] - mx); sm += e[t]; }
        float inv = 1.f / (sm * (float)LS);
        #pragma unroll
        for (int t = 0; t < LT; t++) atomicAdd(&rowvec[t], e[t] * inv);
    }
    __syncthreads();

    if (tid < LS) {
        float a = 0.f;
        #pragma unroll
        for (int t = 0; t < LT; t++)
            a += (expf(A_s[tid][t] - colmax[t]) / colsum[t]) * rowvec[t];
        attn_s[tid] = a;
    }
    __syncthreads();

    // score[h] = sum_s attn[s] * sen_h[b,s,h]  (4-way ILP over s)
    for (int mm = tid; mm < 2 * HDIM; mm += 256) {
        const float* hp = (mm < HDIM) ? d_h_sen[0] : d_h_sen[1];
        int m2 = mm & (HDIM - 1);
        float a0 = 0.f, a1 = 0.f, a2 = 0.f, a3 = 0.f;
        #pragma unroll 4
        for (int s = 0; s < LS; s += 4) {
            a0 += attn_s[s]     * hp[((size_t)(s)     * NB + b) * HDIM + m2];
            a1 += attn_s[s + 1] * hp[((size_t)(s + 1) * NB + b) * HDIM + m2];
            a2 += attn_s[s + 2] * hp[((size_t)(s + 2) * NB + b) * HDIM + m2];
            a3 += attn_s[s + 3] * hp[((size_t)(s + 3) * NB + b) * HDIM + m2];
        }
        score_s[mm] = (a0 + a1) + (a2 + a3);
    }
    __syncthreads();

    if (warp < NOUT) {
        float acc = 0.f;
        for (int mm = lane; mm < 2 * HDIM; mm += 32)
            acc += score_s[mm] * Wout[warp * 2 * HDIM + mm];
        #pragma unroll
        for (int o = 16; o; o >>= 1) acc += __shfl_xor_sync(0xffffffffu, acc, o);
        if (lane == 0) logit[warp] = acc + bout[warp];
    }
    __syncthreads();

    if (tid == 0) {
        float mx = fmaxf(logit[0], fmaxf(logit[1], logit[2]));
        float e0 = expf(logit[0] - mx);
        float e1 = expf(logit[1] - mx);
        float e2 = expf(logit[2] - mx);
        float inv = 1.f / (e0 + e1 + e2);
        out[b * NOUT + 0] = e0 * inv;
        out[b * NOUT + 1] = e1 * inv;
        out[b * NOUT + 2] = e2 * inv;
    }
}

// ----------------------------- launch ---------------------------------------
extern "C" void kernel_launch(void* const* d_in, const int* in_sizes, int n_in,
                              void* d_out, int out_size) {
    const int*   sen_src = (const int*)d_in[0];
    const int*   tgt_src = (const int*)d_in[1];
    const float* emb     = (const float*)d_in[2];
    WPtrs wp;
    for (int l = 0; l < 4; l++) {
        wp.wih[l] = (const float*)d_in[3 + 4 * l];
        wp.whh[l] = (const float*)d_in[4 + 4 * l];
        wp.bih[l] = (const float*)d_in[5 + 4 * l];
        wp.bhh[l] = (const float*)d_in[6 + 4 * l];
    }
    const float* Wout = (const float*)d_in[19];
    const float* bout = (const float*)d_in[20];
    float* out = (float*)d_out;

    cudaFuncSetAttribute(lstm_kernel, cudaFuncAttributeMaxDynamicSharedMemorySize, LSTM_SMEM);

    prep_kernel<<<dim3(256, 4), 256>>>(wp);
    embed_kernel<<<(LS + LT) * NB, EPAD>>>(sen_src, tgt_src, emb);
    gemm_xw<<<dim3(LS * NB / GBM, GDIM / GBN, 4), 256>>>();
    lstm_kernel<<<128, 512, LSTM_SMEM>>>();   // 32 clusters x 4 CTAs
    attn_kernel<<<NB, 256>>>(Wout, bout, out);
}

// round 15
// speedup vs baseline: 9.9669x; 1.0290x over previous
#include <cuda_runtime.h>
#include <cuda_bf16.h>
#include <cstdint>
#include <math.h>
#include <mma.h>

using namespace nvcuda;

#define NB   128   // batch
#define LS   128   // sentence length
#define LT   8     // target length
#define EDIM 300   // true embedding dim (E=300)
#define EPAD 320   // padded embedding dim
#define HDIM 256
#define GDIM 1024  // 4*H
#define NOUT 3

// ----------------------------- scratch (static __device__, no allocs) ------
__device__ __align__(128) __nv_bfloat16 d_x_sen[LS * NB * EPAD];   // [t][b][e] zero-pad
__device__ __align__(128) __nv_bfloat16 d_x_tgt[LT * NB * EPAD];
__device__ __align__(128) __nv_bfloat16 d_Wih[4][GDIM * EPAD];     // zero-pad [n][k]
__device__ __align__(128) __nv_bfloat16 d_Whh[4][GDIM * HDIM];     // [n][k] row-major
__device__ __align__(128) float d_bias[4][GDIM];                   // bih+bhh
__device__ __align__(128) float d_gates_sen[2][LS * NB * GDIM];
__device__ __align__(128) float d_gates_tgt[2][LT * NB * GDIM];
__device__ __align__(128) float d_h_sen[2][LS * NB * HDIM];        // [t][b][h]
__device__ __align__(128) float d_h_tgt[2][LT * NB * HDIM];

struct WPtrs {
    const float* wih[4];
    const float* whh[4];
    const float* bih[4];
    const float* bhh[4];
};

// MUFU.TANH-based activations (validated: rel_err 1.31e-5 overall)
__device__ __forceinline__ float tanh_fast(float x) {
    float y;
    asm("tanh.approx.f32 %0, %1;" : "=f"(y) : "f"(x));
    return y;
}
__device__ __forceinline__ float sig_fast(float x) {
    return 0.5f + 0.5f * tanh_fast(0.5f * x);
}

__device__ __forceinline__ uint32_t smem_u32(const void* p) {
    uint32_t a;
    asm("{ .reg .u64 t; cvta.to.shared.u64 t, %1; cvt.u32.u64 %0, t; }" : "=r"(a) : "l"(p));
    return a;
}
__device__ __forceinline__ uint32_t cluster_rank() {
    uint32_t r;
    asm("mov.u32 %0, %%cluster_ctarank;" : "=r"(r));
    return r;
}
__device__ __forceinline__ void st_dsmem_u128(uint32_t laddr, uint32_t rank, uint4 v) {
    asm volatile(
        "{\n\t.reg .b32 ra;\n\t"
        "mapa.shared::cluster.u32 ra, %0, %1;\n\t"
        "st.shared::cluster.v4.b32 [ra], {%2, %3, %4, %5};\n\t}"
        :: "r"(laddr), "r"(rank), "r"(v.x), "r"(v.y), "r"(v.z), "r"(v.w) : "memory");
}
__device__ __forceinline__ void mbar_arrive_remote(uint32_t laddr, uint32_t rank) {
    asm volatile(
        "{\n\t.reg .b32 ra;\n\t"
        "mapa.shared::cluster.u32 ra, %0, %1;\n\t"
        "mbarrier.arrive.release.cluster.shared::cluster.b64 _, [ra];\n\t}"
        :: "r"(laddr), "r"(rank) : "memory");
}
__device__ __forceinline__ void mbar_wait_parity(uint32_t laddr, uint32_t parity) {
    uint32_t done;
    asm volatile(
        "{\n\t.reg .pred p;\n\t"
        "mbarrier.try_wait.parity.acquire.cluster.shared::cta.b64 p, [%1], %2;\n\t"
        "selp.b32 %0, 1, 0, p;\n\t}"
        : "=r"(done) : "r"(laddr), "r"(parity) : "memory");
    while (!done) {
        asm volatile(
            "{\n\t.reg .pred p;\n\t"
            "mbarrier.try_wait.parity.acquire.cluster.shared::cta.b64 p, [%1], %2;\n\t"
            "selp.b32 %0, 1, 0, p;\n\t}"
            : "=r"(done) : "r"(laddr), "r"(parity) : "memory");
    }
}
#define CLUSTER_ARRIVE() asm volatile("barrier.cluster.arrive.aligned;" ::: "memory")
#define CLUSTER_WAIT()   asm volatile("barrier.cluster.wait.aligned;" ::: "memory")

// ----------------------------- K0: weight prep ------------------------------
__global__ void prep_kernel(WPtrs p) {
    int l = blockIdx.y;
    int stride = gridDim.x * blockDim.x;
    int start = blockIdx.x * blockDim.x + threadIdx.x;
    for (int i = start; i < GDIM * EPAD; i += stride) {
        int n = i / EPAD;
        int k = i - n * EPAD;
        d_Wih[l][i] = __float2bfloat16_rn((k < EDIM) ? p.wih[l][(size_t)n * EDIM + k] : 0.f);
    }
    for (int i = start; i < GDIM * HDIM; i += stride)
        d_Whh[l][i] = __float2bfloat16_rn(p.whh[l][i]);
    for (int i = start; i < GDIM; i += stride)
        d_bias[l][i] = p.bih[l][i] + p.bhh[l][i];
}

// ----------------------------- K1: embedding gather -------------------------
__global__ void embed_kernel(const int* __restrict__ sen_src,
                             const int* __restrict__ tgt_src,
                             const float* __restrict__ emb) {
    int row = blockIdx.x;
    int tid = threadIdx.x;  // 320 threads == EPAD
    if (row < LS * NB) {
        int t = row / NB, b = row % NB;
        int idx = sen_src[b * LS + t];
        float v = (idx == 0 || tid >= EDIM) ? 0.f : emb[(size_t)idx * EDIM + tid];
        d_x_sen[(size_t)row * EPAD + tid] = __float2bfloat16_rn(v);
    } else {
        int r = row - LS * NB;
        int t = r / NB, b = r % NB;
        int idx = tgt_src[b * LT + t];
        float v = (idx == 0 || tid >= EDIM) ? 0.f : emb[(size_t)idx * EDIM + tid];
        d_x_tgt[(size_t)r * EPAD + tid] = __float2bfloat16_rn(v);
    }
}

// ----------------------------- K2: input projection GEMM (bf16 wmma) --------
#define GBM 128
#define GBN 128
#define GBK 64
#define GLD 72

__global__ __launch_bounds__(256) void gemm_xw() {
    int l = blockIdx.z;
    if (l >= 2 && blockIdx.x >= (LT * NB / GBM)) return;

    const __nv_bfloat16* __restrict__ X = (l < 2) ? d_x_sen : d_x_tgt;
    const __nv_bfloat16* __restrict__ W = d_Wih[l];
    float* __restrict__ C = (l < 2) ? d_gates_sen[l] : d_gates_tgt[l - 2];

    __shared__ __align__(128) __nv_bfloat16 As[GBM * GLD];
    __shared__ __align__(128) __nv_bfloat16 Bs[GBN * GLD];

    int tid = threadIdx.x;
    int warp = tid >> 5;
    int wm = warp & 1;
    int wn = warp >> 1;
    int m0 = blockIdx.x * GBM;
    int n0 = blockIdx.y * GBN;

    wmma::fragment<wmma::accumulator, 16, 16, 16, float> acc[4][2];
    #pragma unroll
    for (int mi = 0; mi < 4; mi++)
        #pragma unroll
        for (int ni = 0; ni < 2; ni++) wmma::fill_fragment(acc[mi][ni], 0.f);

    for (int kc = 0; kc < EPAD; kc += GBK) {
        int r0 = tid >> 3;
        int c  = (tid & 7) * 8;
        #pragma unroll
        for (int i = 0; i < 4; i++) {
            int r = r0 + i * 32;
            *(uint4*)&As[r * GLD + c] = *(const uint4*)&X[(size_t)(m0 + r) * EPAD + kc + c];
            *(uint4*)&Bs[r * GLD + c] = *(const uint4*)&W[(size_t)(n0 + r) * EPAD + kc + c];
        }
        __syncthreads();
        #pragma unroll
        for (int kk = 0; kk < GBK; kk += 16) {
            wmma::fragment<wmma::matrix_a, 16, 16, 16, __nv_bfloat16, wmma::row_major> af[4];
            wmma::fragment<wmma::matrix_b, 16, 16, 16, __nv_bfloat16, wmma::col_major> bf[2];
            #pragma unroll
            for (int mi = 0; mi < 4; mi++)
                wmma::load_matrix_sync(af[mi], &As[(wm * 64 + mi * 16) * GLD + kk], GLD);
            #pragma unroll
            for (int ni = 0; ni < 2; ni++)
                wmma::load_matrix_sync(bf[ni], &Bs[(wn * 32 + ni * 16) * GLD + kk], GLD);
            #pragma unroll
            for (int mi = 0; mi < 4; mi++)
                #pragma unroll
                for (int ni = 0; ni < 2; ni++)
                    wmma::mma_sync(acc[mi][ni], af[mi], bf[ni], acc[mi][ni]);
        }
        __syncthreads();
    }
    #pragma unroll
    for (int mi = 0; mi < 4; mi++)
        #pragma unroll
        for (int ni = 0; ni < 2; ni++)
            wmma::store_matrix_sync(
                &C[(size_t)(m0 + wm * 64 + mi * 16) * GDIM + n0 + wn * 32 + ni * 16],
                acc[mi][ni], GDIM, wmma::mem_row_major);
}

// ----------------------------- K3: LSTM recurrence (cluster, mbarrier) ------
// Cluster of 4 CTAs per (lstm, batch-chunk-of-16). CTA rank r owns hidden
// units [r*64,+64); its Whh B-fragments live in registers. Per step:
//   mma -> sync -> elementwise -> stage -> sync -> wide DSMEM stores ->
//   sync -> 4 release-arrives (one per peer mbarrier) ->
//   [shadow: Hout stores + x prefetch] -> acquire parity-wait.
#define BCH    16
#define SLC    64                       // hidden units per CTA
#define WLD    264                      // smem leading dim
#define W_SZ   (256 * WLD * 2)          // 135168 B
#define H_SZ   (BCH * WLD * 2)          // 8448 B per h buffer
#define G_SZ   (BCH * WLD * 4)          // 16896 B per partial-gate buffer
#define S_SZ   (BCH * SLC * 2)          // 2048 B staging
#define LSTM_SMEM (W_SZ + 2 * H_SZ + 2 * G_SZ + S_SZ + 16)   // +mbarrier

__global__ void __cluster_dims__(4, 1, 1) __launch_bounds__(512, 1) lstm_kernel() {
    extern __shared__ __align__(128) unsigned char smem[];
    __nv_bfloat16* Wsh    = (__nv_bfloat16*)smem;                        // [256][264]
    __nv_bfloat16* hbuf   = (__nv_bfloat16*)(smem + W_SZ);               // [2][16][264]
    float*         gatesA = (float*)(smem + W_SZ + 2 * H_SZ);            // [16][264]
    float*         gatesB = (float*)(smem + W_SZ + 2 * H_SZ + G_SZ);     // [16][264]
    __nv_bfloat16* hstg   = (__nv_bfloat16*)(smem + W_SZ + 2 * H_SZ + 2 * G_SZ); // [16][64]
    unsigned long long* mbar = (unsigned long long*)(smem + W_SZ + 2 * H_SZ + 2 * G_SZ + S_SZ);

    int bx   = blockIdx.x;
    int cid  = bx >> 2;                 // cluster id 0..31
    int lstm = cid >> 3;                // 0=sf 1=sb 2=tf 3=tb
    int b0   = (cid & 7) * BCH;
    uint32_t r = cluster_rank();        // 0..3
    int T    = (lstm < 2) ? LS : LT;
    bool rev = (lstm & 1);
    const __nv_bfloat16* __restrict__ Wg = d_Whh[lstm];
    const float* __restrict__ Xg   = (lstm < 2) ? d_gates_sen[lstm] : d_gates_tgt[lstm - 2];
    float* __restrict__       Hout = (lstm < 2) ? d_h_sen[lstm]     : d_h_tgt[lstm - 2];

    int tid   = threadIdx.x;            // 0..511
    int warp  = tid >> 5;               // 0..15
    int wcol  = warp & 7;               // col slice (32 gates)
    int khalf = warp >> 3;              // 0 or 1 (K half)
    int u     = tid & 63;               // hidden unit within slice
    int kbg   = (tid >> 6) & 7;         // batch group 0..7
    int r64u  = (int)r * SLC + u;       // global hidden unit

    uint32_t mbar_u32 = smem_u32(mbar);
    if (tid == 0)
        asm volatile("mbarrier.init.shared.b64 [%0], %1;" :: "r"(mbar_u32), "r"(4u) : "memory");

    // ---- load resident Whh slice: local row lr = g*64+u  <- global row g*256+r64u
    for (int i = tid; i < 256 * 32; i += 512) {
        int lr = i >> 5;
        int c8 = i & 31;
        int n  = ((lr >> 6) << 8) + (int)r * SLC + (lr & 63);
        *(uint4*)&Wsh[lr * WLD + c8 * 8] = *(const uint4*)&Wg[(size_t)n * HDIM + c8 * 8];
    }
    // ---- zero both h buffers
    for (int i = tid; i < 2 * BCH * WLD; i += 512) hbuf[i] = __float2bfloat16_rn(0.f);

    float c[2] = {0.f, 0.f};
    const float bi  = d_bias[lstm][r64u];
    const float bf_ = d_bias[lstm][r64u + 256];
    const float bg  = d_bias[lstm][r64u + 512];
    const float bo  = d_bias[lstm][r64u + 768];

    uint32_t hbase_u32 = smem_u32(hbuf);
    float* gatesK = khalf ? gatesB : gatesA;
    __syncthreads();

    // ---- preload this warp's constant Whh B-fragments into registers
    wmma::fragment<wmma::matrix_b, 16, 16, 16, __nv_bfloat16, wmma::col_major> bfr[8][2];
    #pragma unroll
    for (int i = 0; i < 8; i++) {
        int kk = khalf * 8 + i;
        wmma::load_matrix_sync(bfr[i][0], &Wsh[(wcol * 32) * WLD + kk * 16], WLD);
        wmma::load_matrix_sync(bfr[i][1], &Wsh[(wcol * 32 + 16) * WLD + kk * 16], WLD);
    }

    // ---- prefetch x-gates for step 0
    float xv[2][4];
    {
        int t0 = rev ? (T - 1) : 0;
        const float* xgt = Xg + (size_t)(t0 * NB + b0) * GDIM;
        #pragma unroll
        for (int j = 0; j < 2; j++) {
            const float* xr = xgt + (size_t)(j * 8 + kbg) * GDIM;
            xv[j][0] = xr[r64u];
            xv[j][1] = xr[r64u + 256];
            xv[j][2] = xr[r64u + 512];
            xv[j][3] = xr[r64u + 768];
        }
    }

    // startup rendezvous: h buffers zeroed + mbarriers initialized everywhere
    CLUSTER_ARRIVE();
    CLUSTER_WAIT();

    for (int step = 0; step < T; step++) {
        int t = rev ? (T - 1 - step) : step;
        const __nv_bfloat16* hcur = hbuf + (step & 1) * (BCH * WLD);
        uint32_t hnxt_u32 = hbase_u32 + (uint32_t)(((step & 1) ^ 1) * H_SZ);

        // ---- partial gates: 8 A-LDSM + 16 HMMA (B in registers)
        {
            wmma::fragment<wmma::accumulator, 16, 16, 16, float> acc0, acc1;
            wmma::fill_fragment(acc0, 0.f);
            wmma::fill_fragment(acc1, 0.f);
            #pragma unroll
            for (int i = 0; i < 8; i++) {
                int kk = khalf * 8 + i;
                wmma::fragment<wmma::matrix_a, 16, 16, 16, __nv_bfloat16, wmma::row_major> af;
                wmma::load_matrix_sync(af, &hcur[kk * 16], WLD);
                wmma::mma_sync(acc0, af, bfr[i][0], acc0);
                wmma::mma_sync(acc1, af, bfr[i][1], acc1);
            }
            wmma::store_matrix_sync(&gatesK[wcol * 32], acc0, WLD, wmma::mem_row_major);
            wmma::store_matrix_sync(&gatesK[wcol * 32 + 16], acc1, WLD, wmma::mem_row_major);
        }
        __syncthreads();

        // ---- elementwise (tanh.approx) -> stage
        float hvv[2];
        #pragma unroll
        for (int j = 0; j < 2; j++) {
            int kb = j * 8 + kbg;
            int rw = kb * WLD;
            float gi = gatesA[rw + u]       + gatesB[rw + u]       + xv[j][0] + bi;
            float gf = gatesA[rw + 64 + u]  + gatesB[rw + 64 + u]  + xv[j][1] + bf_;
            float gg = gatesA[rw + 128 + u] + gatesB[rw + 128 + u] + xv[j][2] + bg;
            float go = gatesA[rw + 192 + u] + gatesB[rw + 192 + u] + xv[j][3] + bo;
            float cn = sig_fast(gf) * c[j] + sig_fast(gi) * tanh_fast(gg);
            c[j] = cn;
            float hv = sig_fast(go) * tanh_fast(cn);
            hvv[j] = hv;
            hstg[kb * SLC + u] = __float2bfloat16_rn(hv);
        }
        __syncthreads();

        // ---- wide broadcast: 512 uint4 msgs (4 ranks x 128), 1 per thread
        {
            int rk = tid >> 7;          // target rank 0..3
            int j  = tid & 127;
            int kb = j >> 3;
            int q  = j & 7;
            uint4 v = *(const uint4*)(hstg + kb * SLC + q * 8);
            uint32_t dst = hnxt_u32 +
                (uint32_t)((kb * WLD + (int)r * SLC) * 2 + q * 16);
            st_dsmem_u128(dst, (uint32_t)rk, v);
        }
        __syncthreads();            // all stores issued before the arrives

        if (tid < 4) mbar_arrive_remote(mbar_u32, (uint32_t)tid);

        // ---- latency shadow: Hout stores + next-step x prefetch
        {
            float* hrow = Hout + (size_t)(t * NB + b0) * HDIM;
            #pragma unroll
            for (int j = 0; j < 2; j++)
                hrow[(size_t)(j * 8 + kbg) * HDIM + r64u] = hvv[j];
        }
        if (step + 1 < T) {
            int tn = rev ? (T - 2 - step) : (step + 1);
            const float* xgt = Xg + (size_t)(tn * NB + b0) * GDIM;
            #pragma unroll
            for (int j = 0; j < 2; j++) {
                const float* xr = xgt + (size_t)(j * 8 + kbg) * GDIM;
                xv[j][0] = xr[r64u];
                xv[j][1] = xr[r64u + 256];
                xv[j][2] = xr[r64u + 512];
                xv[j][3] = xr[r64u + 768];
            }
        }
        mbar_wait_parity(mbar_u32, (uint32_t)(step & 1));
    }
}

// ----------------------------- K4: attention + output (fp32) ----------------
__global__ __launch_bounds__(256) void attn_kernel(const float* __restrict__ Wout,
                                                   const float* __restrict__ bout,
                                                   float* __restrict__ out) {
    int b = blockIdx.x;
    int tid = threadIdx.x;
    int lane = tid & 31, warp = tid >> 5;

    __shared__ float tgt_s[LT][2 * HDIM];
    __shared__ float A_s[LS][LT];
    __shared__ float colmax[LT];
    __shared__ float colsum[LT];
    __shared__ float rowvec[LT];
    __shared__ float attn_s[LS];
    __shared__ float score_s[2 * HDIM];
    __shared__ float logit[NOUT];

    for (int i = tid; i < LT * 2 * HDIM; i += 256) {
        int t = i >> 9;
        int mm = i & 511;
        tgt_s[t][mm] = (mm < HDIM)
            ? d_h_tgt[0][((size_t)t * NB + b) * HDIM + mm]
            : d_h_tgt[1][((size_t)t * NB + b) * HDIM + (mm - HDIM)];
    }
    if (tid < LT) rowvec[tid] = 0.f;
    __syncthreads();

    for (int s = warp; s < LS; s += 8) {
        float p[LT];
        #pragma unroll
        for (int t = 0; t < LT; t++) p[t] = 0.f;
        const float* f0 = &d_h_sen[0][((size_t)s * NB + b) * HDIM];
        const float* f1 = &d_h_sen[1][((size_t)s * NB + b) * HDIM];
        for (int mm = lane; mm < HDIM; mm += 32) {
            float v0 = f0[mm], v1 = f1[mm];
            #pragma unroll
            for (int t = 0; t < LT; t++)
                p[t] += v0 * tgt_s[t][mm] + v1 * tgt_s[t][HDIM + mm];
        }
        #pragma unroll
        for (int t = 0; t < LT; t++) {
            #pragma unroll
            for (int o = 16; o; o >>= 1) p[t] += __shfl_xor_sync(0xffffffffu, p[t], o);
            if (lane == 0) A_s[s][t] = p[t];
        }
    }
    __syncthreads();

    if (tid < LT) {
        float mx = -1e30f;
        for (int s = 0; s < LS; s++) mx = fmaxf(mx, A_s[s][tid]);
        float sm = 0.f;
        for (int s = 0; s < LS; s++) sm += expf(A_s[s][tid] - mx);
        colmax[tid] = mx;
        colsum[tid] = sm;
    }
    if (tid < LS) {
        float mx = -1e30f;
        #pragma unroll
        for (int t = 0; t < LT; t++) mx = fmaxf(mx, A_s[tid][t]);
        float e[LT], sm = 0.f;
        #pragma unroll
        for (int t = 0; t < LT; t++) { e[t] = expf(A_s[tid][t] - mx); sm += e[t]; }
        float inv = 1.f / (sm * (float)LS);
        #pragma unroll
        for (int t = 0; t < LT; t++) atomicAdd(&rowvec[t], e[t] * inv);
    }
    __syncthreads();

    if (tid < LS) {
        float a = 0.f;
        #pragma unroll
        for (int t = 0; t < LT; t++)
            a += (expf(A_s[tid][t] - colmax[t]) / colsum[t]) * rowvec[t];
        attn_s[tid] = a;
    }
    __syncthreads();

    // score[h] = sum_s attn[s] * sen_h[b,s,h]  (4-way ILP over s)
    for (int mm = tid; mm < 2 * HDIM; mm += 256) {
        const float* hp = (mm < HDIM) ? d_h_sen[0] : d_h_sen[1];
        int m2 = mm & (HDIM - 1);
        float a0 = 0.f, a1 = 0.f, a2 = 0.f, a3 = 0.f;
        #pragma unroll 4
        for (int s = 0; s < LS; s += 4) {
            a0 += attn_s[s]     * hp[((size_t)(s)     * NB + b) * HDIM + m2];
            a1 += attn_s[s + 1] * hp[((size_t)(s + 1) * NB + b) * HDIM + m2];
            a2 += attn_s[s + 2] * hp[((size_t)(s + 2) * NB + b) * HDIM + m2];
            a3 += attn_s[s + 3] * hp[((size_t)(s + 3) * NB + b) * HDIM + m2];
        }
        score_s[mm] = (a0 + a1) + (a2 + a3);
    }
    __syncthreads();

    if (warp < NOUT) {
        float acc = 0.f;
        for (int mm = lane; mm < 2 * HDIM; mm += 32)
            acc += score_s[mm] * Wout[warp * 2 * HDIM + mm];
        #pragma unroll
        for (int o = 16; o; o >>= 1) acc += __shfl_xor_sync(0xffffffffu, acc, o);
        if (lane == 0) logit[warp] = acc + bout[warp];
    }
    __syncthreads();

    if (tid == 0) {
        float mx = fmaxf(logit[0], fmaxf(logit[1], logit[2]));
        float e0 = expf(logit[0] - mx);
        float e1 = expf(logit[1] - mx);
        float e2 = expf(logit[2] - mx);
        float inv = 1.f / (e0 + e1 + e2);
        out[b * NOUT + 0] = e0 * inv;
        out[b * NOUT + 1] = e1 * inv;
        out[b * NOUT + 2] = e2 * inv;
    }
}

// ----------------------------- launch ---------------------------------------
extern "C" void kernel_launch(void* const* d_in, const int* in_sizes, int n_in,
                              void* d_out, int out_size) {
    const int*   sen_src = (const int*)d_in[0];
    const int*   tgt_src = (const int*)d_in[1];
    const float* emb     = (const float*)d_in[2];
    WPtrs wp;
    for (int l = 0; l < 4; l++) {
        wp.wih[l] = (const float*)d_in[3 + 4 * l];
        wp.whh[l] = (const float*)d_in[4 + 4 * l];
        wp.bih[l] = (const float*)d_in[5 + 4 * l];
        wp.bhh[l] = (const float*)d_in[6 + 4 * l];
    }
    const float* Wout = (const float*)d_in[19];
    const float* bout = (const float*)d_in[20];
    float* out = (float*)d_out;

    cudaFuncSetAttribute(lstm_kernel, cudaFuncAttributeMaxDynamicSharedMemorySize, LSTM_SMEM);

    prep_kernel<<<dim3(256, 4), 256>>>(wp);
    embed_kernel<<<(LS + LT) * NB, EPAD>>>(sen_src, tgt_src, emb);
    gemm_xw<<<dim3(LS * NB / GBM, GDIM / GBN, 4), 256>>>();
    lstm_kernel<<<128, 512, LSTM_SMEM>>>();   // 32 clusters x 4 CTAs
    attn_kernel<<<NB, 256>>>(Wout, bout, out);
}

// round 16
// speedup vs baseline: 10.8067x; 1.0843x over previous
#include <cuda_runtime.h>
#include <cuda_bf16.h>
#include <cstdint>
#include <math.h>
#include <mma.h>

using namespace nvcuda;

#define NB   128   // batch
#define LS   128   // sentence length
#define LT   8     // target length
#define EDIM 300   // true embedding dim (E=300)
#define EPAD 320   // padded embedding dim
#define HDIM 256
#define GDIM 1024  // 4*H
#define NOUT 3

// ----------------------------- scratch (static __device__, no allocs) ------
__device__ __align__(128) __nv_bfloat16 d_x_sen[LS * NB * EPAD];   // [t][b][e] zero-pad
__device__ __align__(128) __nv_bfloat16 d_x_tgt[LT * NB * EPAD];
__device__ __align__(128) __nv_bfloat16 d_Wih[4][GDIM * EPAD];     // zero-pad [n][k]
__device__ __align__(128) __nv_bfloat16 d_Whh[4][GDIM * HDIM];     // [n][k] row-major
__device__ __align__(128) float d_bias[4][GDIM];                   // bih+bhh
__device__ __align__(128) float d_gates_sen[2][LS * NB * GDIM];
__device__ __align__(128) float d_gates_tgt[2][LT * NB * GDIM];
__device__ __align__(128) float d_h_sen[2][LS * NB * HDIM];        // [t][b][h]
__device__ __align__(128) float d_h_tgt[2][LT * NB * HDIM];

struct WPtrs {
    const float* wih[4];
    const float* whh[4];
    const float* bih[4];
    const float* bhh[4];
};

// MUFU.TANH-based activations (validated: rel_err 1.31e-5 overall)
__device__ __forceinline__ float tanh_fast(float x) {
    float y;
    asm("tanh.approx.f32 %0, %1;" : "=f"(y) : "f"(x));
    return y;
}
__device__ __forceinline__ float sig_fast(float x) {
    return 0.5f + 0.5f * tanh_fast(0.5f * x);
}

__device__ __forceinline__ uint32_t smem_u32(const void* p) {
    uint32_t a;
    asm("{ .reg .u64 t; cvta.to.shared.u64 t, %1; cvt.u32.u64 %0, t; }" : "=r"(a) : "l"(p));
    return a;
}
__device__ __forceinline__ uint32_t cluster_rank() {
    uint32_t r;
    asm("mov.u32 %0, %%cluster_ctarank;" : "=r"(r));
    return r;
}
__device__ __forceinline__ void st_dsmem_b16(uint32_t laddr, uint32_t rank, __nv_bfloat16 v) {
    unsigned short s = *reinterpret_cast<unsigned short*>(&v);
    asm volatile(
        "{\n\t.reg .b32 ra;\n\t"
        "mapa.shared::cluster.u32 ra, %0, %1;\n\t"
        "st.shared::cluster.b16 [ra], %2;\n\t}"
        :: "r"(laddr), "r"(rank), "h"(s) : "memory");
}
__device__ __forceinline__ void mbar_arrive_remote(uint32_t laddr, uint32_t rank) {
    asm volatile(
        "{\n\t.reg .b32 ra;\n\t"
        "mapa.shared::cluster.u32 ra, %0, %1;\n\t"
        "mbarrier.arrive.release.cluster.shared::cluster.b64 _, [ra];\n\t}"
        :: "r"(laddr), "r"(rank) : "memory");
}
__device__ __forceinline__ void mbar_wait_parity(uint32_t laddr, uint32_t parity) {
    uint32_t done;
    asm volatile(
        "{\n\t.reg .pred p;\n\t"
        "mbarrier.try_wait.parity.acquire.cluster.shared::cta.b64 p, [%1], %2;\n\t"
        "selp.b32 %0, 1, 0, p;\n\t}"
        : "=r"(done) : "r"(laddr), "r"(parity) : "memory");
    while (!done) {
        asm volatile(
            "{\n\t.reg .pred p;\n\t"
            "mbarrier.try_wait.parity.acquire.cluster.shared::cta.b64 p, [%1], %2;\n\t"
            "selp.b32 %0, 1, 0, p;\n\t}"
            : "=r"(done) : "r"(laddr), "r"(parity) : "memory");
    }
}
__device__ __forceinline__ void cp_async16(uint32_t dst_smem, const void* src) {
    asm volatile("cp.async.ca.shared.global [%0], [%1], 16;"
                 :: "r"(dst_smem), "l"(src) : "memory");
}
#define CP_COMMIT() asm volatile("cp.async.commit_group;" ::: "memory")
#define CLUSTER_ARRIVE() asm volatile("barrier.cluster.arrive.aligned;" ::: "memory")
#define CLUSTER_WAIT()   asm volatile("barrier.cluster.wait.aligned;" ::: "memory")

// ----------------------------- K0: weight prep ------------------------------
__global__ void prep_kernel(WPtrs p) {
    int l = blockIdx.y;
    int stride = gridDim.x * blockDim.x;
    int start = blockIdx.x * blockDim.x + threadIdx.x;
    for (int i = start; i < GDIM * EPAD; i += stride) {
        int n = i / EPAD;
        int k = i - n * EPAD;
        d_Wih[l][i] = __float2bfloat16_rn((k < EDIM) ? p.wih[l][(size_t)n * EDIM + k] : 0.f);
    }
    for (int i = start; i < GDIM * HDIM; i += stride)
        d_Whh[l][i] = __float2bfloat16_rn(p.whh[l][i]);
    for (int i = start; i < GDIM; i += stride)
        d_bias[l][i] = p.bih[l][i] + p.bhh[l][i];
}

// ----------------------------- K1: embedding gather -------------------------
__global__ void embed_kernel(const int* __restrict__ sen_src,
                             const int* __restrict__ tgt_src,
                             const float* __restrict__ emb) {
    int row = blockIdx.x;
    int tid = threadIdx.x;  // 320 threads == EPAD
    if (row < LS * NB) {
        int t = row / NB, b = row % NB;
        int idx = sen_src[b * LS + t];
        float v = (idx == 0 || tid >= EDIM) ? 0.f : emb[(size_t)idx * EDIM + tid];
        d_x_sen[(size_t)row * EPAD + tid] = __float2bfloat16_rn(v);
    } else {
        int r = row - LS * NB;
        int t = r / NB, b = r % NB;
        int idx = tgt_src[b * LT + t];
        float v = (idx == 0 || tid >= EDIM) ? 0.f : emb[(size_t)idx * EDIM + tid];
        d_x_tgt[(size_t)r * EPAD + tid] = __float2bfloat16_rn(v);
    }
}

// ----------------------------- K2: input projection GEMM (cp.async pipe) ----
#define GBM 128
#define GBN 128
#define GBK 64
#define GLD 72
#define GTILE (GBM * GLD)                 // elements per tile buffer
#define GEMM_SMEM (4 * GTILE * 2)         // A0,B0,A1,B1 bf16 = 73728 B
#define NKIT (EPAD / GBK)                 // 5

__global__ __launch_bounds__(256) void gemm_xw() {
    int l = blockIdx.z;
    if (l >= 2 && blockIdx.x >= (LT * NB / GBM)) return;

    const __nv_bfloat16* __restrict__ X = (l < 2) ? d_x_sen : d_x_tgt;
    const __nv_bfloat16* __restrict__ W = d_Wih[l];
    float* __restrict__ C = (l < 2) ? d_gates_sen[l] : d_gates_tgt[l - 2];

    extern __shared__ __align__(128) unsigned char gsm[];
    __nv_bfloat16* buf = (__nv_bfloat16*)gsm;   // [4][GTILE]: A0 B0 A1 B1
    uint32_t buf_u32 = smem_u32(buf);

    int tid = threadIdx.x;
    int warp = tid >> 5;
    int wm = warp & 1;
    int wn = warp >> 1;
    int m0 = blockIdx.x * GBM;
    int n0 = blockIdx.y * GBN;

    int r0 = tid >> 3;
    int c  = (tid & 7) * 8;

    // tile loader: issues 8 cp.async (4 A rows + 4 B rows) for K-chunk it
    auto issue_tile = [&](int it, int s) {
        uint32_t aofs = buf_u32 + (uint32_t)((2 * s) * GTILE * 2);
        uint32_t bofs = buf_u32 + (uint32_t)((2 * s + 1) * GTILE * 2);
        int kc = it * GBK;
        #pragma unroll
        for (int i = 0; i < 4; i++) {
            int r = r0 + i * 32;
            cp_async16(aofs + (uint32_t)(r * GLD + c) * 2,
                       &X[(size_t)(m0 + r) * EPAD + kc + c]);
            cp_async16(bofs + (uint32_t)(r * GLD + c) * 2,
                       &W[(size_t)(n0 + r) * EPAD + kc + c]);
        }
    };

    wmma::fragment<wmma::accumulator, 16, 16, 16, float> acc[4][2];
    #pragma unroll
    for (int mi = 0; mi < 4; mi++)
        #pragma unroll
        for (int ni = 0; ni < 2; ni++) wmma::fill_fragment(acc[mi][ni], 0.f);

    issue_tile(0, 0);
    CP_COMMIT();

    for (int it = 0; it < NKIT; it++) {
        int s = it & 1;
        if (it + 1 < NKIT) {
            issue_tile(it + 1, s ^ 1);
            CP_COMMIT();
            asm volatile("cp.async.wait_group 1;" ::: "memory");
        } else {
            asm volatile("cp.async.wait_group 0;" ::: "memory");
        }
        __syncthreads();

        const __nv_bfloat16* As = buf + (2 * s) * GTILE;
        const __nv_bfloat16* Bs = buf + (2 * s + 1) * GTILE;
        #pragma unroll
        for (int kk = 0; kk < GBK; kk += 16) {
            wmma::fragment<wmma::matrix_a, 16, 16, 16, __nv_bfloat16, wmma::row_major> af[4];
            wmma::fragment<wmma::matrix_b, 16, 16, 16, __nv_bfloat16, wmma::col_major> bf[2];
            #pragma unroll
            for (int mi = 0; mi < 4; mi++)
                wmma::load_matrix_sync(af[mi], &As[(wm * 64 + mi * 16) * GLD + kk], GLD);
            #pragma unroll
            for (int ni = 0; ni < 2; ni++)
                wmma::load_matrix_sync(bf[ni], &Bs[(wn * 32 + ni * 16) * GLD + kk], GLD);
            #pragma unroll
            for (int mi = 0; mi < 4; mi++)
                #pragma unroll
                for (int ni = 0; ni < 2; ni++)
                    wmma::mma_sync(acc[mi][ni], af[mi], bf[ni], acc[mi][ni]);
        }
        __syncthreads();
    }
    #pragma unroll
    for (int mi = 0; mi < 4; mi++)
        #pragma unroll
        for (int ni = 0; ni < 2; ni++)
            wmma::store_matrix_sync(
                &C[(size_t)(m0 + wm * 64 + mi * 16) * GDIM + n0 + wn * 32 + ni * 16],
                acc[mi][ni], GDIM, wmma::mem_row_major);
}

// ----------------------------- K3: LSTM recurrence (cluster, mbarrier) ------
// Cluster of 4 CTAs per (lstm, batch-chunk-of-16). CTA rank r owns hidden
// units [r*64,+64); its Whh B-fragments live in registers. Per step:
//   mma -> sync -> elementwise + fused scalar DSMEM scatter -> sync ->
//   4 release-arrives -> [shadow: Hout + x prefetch] -> acquire parity-wait.
#define BCH    16
#define SLC    64                       // hidden units per CTA
#define WLD    264                      // smem leading dim
#define W_SZ   (256 * WLD * 2)          // 135168 B
#define H_SZ   (BCH * WLD * 2)          // 8448 B per h buffer
#define G_SZ   (BCH * WLD * 4)          // 16896 B per partial-gate buffer
#define LSTM_SMEM (W_SZ + 2 * H_SZ + 2 * G_SZ + 16)   // +mbarrier

__global__ void __cluster_dims__(4, 1, 1) __launch_bounds__(512, 1) lstm_kernel() {
    extern __shared__ __align__(128) unsigned char smem[];
    __nv_bfloat16* Wsh    = (__nv_bfloat16*)smem;                        // [256][264]
    __nv_bfloat16* hbuf   = (__nv_bfloat16*)(smem + W_SZ);               // [2][16][264]
    float*         gatesA = (float*)(smem + W_SZ + 2 * H_SZ);            // [16][264]
    float*         gatesB = (float*)(smem + W_SZ + 2 * H_SZ + G_SZ);     // [16][264]
    unsigned long long* mbar = (unsigned long long*)(smem + W_SZ + 2 * H_SZ + 2 * G_SZ);

    int bx   = blockIdx.x;
    int cid  = bx >> 2;                 // cluster id 0..31
    int lstm = cid >> 3;                // 0=sf 1=sb 2=tf 3=tb
    int b0   = (cid & 7) * BCH;
    uint32_t r = cluster_rank();        // 0..3
    int T    = (lstm < 2) ? LS : LT;
    bool rev = (lstm & 1);
    const __nv_bfloat16* __restrict__ Wg = d_Whh[lstm];
    const float* __restrict__ Xg   = (lstm < 2) ? d_gates_sen[lstm] : d_gates_tgt[lstm - 2];
    float* __restrict__       Hout = (lstm < 2) ? d_h_sen[lstm]     : d_h_tgt[lstm - 2];

    int tid   = threadIdx.x;            // 0..511
    int warp  = tid >> 5;               // 0..15
    int wcol  = warp & 7;               // col slice (32 gates)
    int khalf = warp >> 3;              // 0 or 1 (K half)
    int u     = tid & 63;               // hidden unit within slice
    int kbg   = (tid >> 6) & 7;         // batch group 0..7
    int r64u  = (int)r * SLC + u;       // global hidden unit

    uint32_t mbar_u32 = smem_u32(mbar);
    if (tid == 0)
        asm volatile("mbarrier.init.shared.b64 [%0], %1;" :: "r"(mbar_u32), "r"(4u) : "memory");

    // ---- load resident Whh slice: local row lr = g*64+u  <- global row g*256+r64u
    for (int i = tid; i < 256 * 32; i += 512) {
        int lr = i >> 5;
        int c8 = i & 31;
        int n  = ((lr >> 6) << 8) + (int)r * SLC + (lr & 63);
        *(uint4*)&Wsh[lr * WLD + c8 * 8] = *(const uint4*)&Wg[(size_t)n * HDIM + c8 * 8];
    }
    // ---- zero both h buffers
    for (int i = tid; i < 2 * BCH * WLD; i += 512) hbuf[i] = __float2bfloat16_rn(0.f);

    float c[2] = {0.f, 0.f};
    const float bi  = d_bias[lstm][r64u];
    const float bf_ = d_bias[lstm][r64u + 256];
    const float bg  = d_bias[lstm][r64u + 512];
    const float bo  = d_bias[lstm][r64u + 768];

    uint32_t hbase_u32 = smem_u32(hbuf);
    float* gatesK = khalf ? gatesB : gatesA;
    __syncthreads();

    // ---- preload this warp's constant Whh B-fragments into registers
    wmma::fragment<wmma::matrix_b, 16, 16, 16, __nv_bfloat16, wmma::col_major> bfr[8][2];
    #pragma unroll
    for (int i = 0; i < 8; i++) {
        int kk = khalf * 8 + i;
        wmma::load_matrix_sync(bfr[i][0], &Wsh[(wcol * 32) * WLD + kk * 16], WLD);
        wmma::load_matrix_sync(bfr[i][1], &Wsh[(wcol * 32 + 16) * WLD + kk * 16], WLD);
    }

    // ---- prefetch x-gates for step 0
    float xv[2][4];
    {
        int t0 = rev ? (T - 1) : 0;
        const float* xgt = Xg + (size_t)(t0 * NB + b0) * GDIM;
        #pragma unroll
        for (int j = 0; j < 2; j++) {
            const float* xr = xgt + (size_t)(j * 8 + kbg) * GDIM;
            xv[j][0] = xr[r64u];
            xv[j][1] = xr[r64u + 256];
            xv[j][2] = xr[r64u + 512];
            xv[j][3] = xr[r64u + 768];
        }
    }

    // startup rendezvous: h buffers zeroed + mbarriers initialized everywhere
    CLUSTER_ARRIVE();
    CLUSTER_WAIT();

    for (int step = 0; step < T; step++) {
        int t = rev ? (T - 1 - step) : step;
        const __nv_bfloat16* hcur = hbuf + (step & 1) * (BCH * WLD);
        uint32_t hnxt_u32 = hbase_u32 + (uint32_t)(((step & 1) ^ 1) * H_SZ);

        // ---- partial gates: 8 A-LDSM + 16 HMMA (B in registers)
        {
            wmma::fragment<wmma::accumulator, 16, 16, 16, float> acc0, acc1;
            wmma::fill_fragment(acc0, 0.f);
            wmma::fill_fragment(acc1, 0.f);
            #pragma unroll
            for (int i = 0; i < 8; i++) {
                int kk = khalf * 8 + i;
                wmma::fragment<wmma::matrix_a, 16, 16, 16, __nv_bfloat16, wmma::row_major> af;
                wmma::load_matrix_sync(af, &hcur[kk * 16], WLD);
                wmma::mma_sync(acc0, af, bfr[i][0], acc0);
                wmma::mma_sync(acc1, af, bfr[i][1], acc1);
            }
            wmma::store_matrix_sync(&gatesK[wcol * 32], acc0, WLD, wmma::mem_row_major);
            wmma::store_matrix_sync(&gatesK[wcol * 32 + 16], acc1, WLD, wmma::mem_row_major);
        }
        __syncthreads();

        // ---- elementwise (tanh.approx) + fused scalar DSMEM scatter
        float hvv[2];
        #pragma unroll
        for (int j = 0; j < 2; j++) {
            int kb = j * 8 + kbg;
            int rw = kb * WLD;
            float gi = gatesA[rw + u]       + gatesB[rw + u]       + xv[j][0] + bi;
            float gf = gatesA[rw + 64 + u]  + gatesB[rw + 64 + u]  + xv[j][1] + bf_;
            float gg = gatesA[rw + 128 + u] + gatesB[rw + 128 + u] + xv[j][2] + bg;
            float go = gatesA[rw + 192 + u] + gatesB[rw + 192 + u] + xv[j][3] + bo;
            float cn = sig_fast(gf) * c[j] + sig_fast(gi) * tanh_fast(gg);
            c[j] = cn;
            float hv = sig_fast(go) * tanh_fast(cn);
            hvv[j] = hv;
            __nv_bfloat16 hb = __float2bfloat16_rn(hv);
            uint32_t off = hnxt_u32 + (uint32_t)(kb * WLD + r64u) * 2u;
            #pragma unroll
            for (uint32_t rk = 0; rk < 4; rk++) st_dsmem_b16(off, rk, hb);
        }
        __syncthreads();            // all stores issued before the arrives

        if (tid < 4) mbar_arrive_remote(mbar_u32, (uint32_t)tid);

        // ---- latency shadow: Hout stores + next-step x prefetch
        {
            float* hrow = Hout + (size_t)(t * NB + b0) * HDIM;
            #pragma unroll
            for (int j = 0; j < 2; j++)
                hrow[(size_t)(j * 8 + kbg) * HDIM + r64u] = hvv[j];
        }
        if (step + 1 < T) {
            int tn = rev ? (T - 2 - step) : (step + 1);
            const float* xgt = Xg + (size_t)(tn * NB + b0) * GDIM;
            #pragma unroll
            for (int j = 0; j < 2; j++) {
                const float* xr = xgt + (size_t)(j * 8 + kbg) * GDIM;
                xv[j][0] = xr[r64u];
                xv[j][1] = xr[r64u + 256];
                xv[j][2] = xr[r64u + 512];
                xv[j][3] = xr[r64u + 768];
            }
        }
        mbar_wait_parity(mbar_u32, (uint32_t)(step & 1));
    }
}

// ----------------------------- K4: attention + output (fp32) ----------------
__global__ __launch_bounds__(256) void attn_kernel(const float* __restrict__ Wout,
                                                   const float* __restrict__ bout,
                                                   float* __restrict__ out) {
    int b = blockIdx.x;
    int tid = threadIdx.x;
    int lane = tid & 31, warp = tid >> 5;

    __shared__ float tgt_s[LT][2 * HDIM];
    __shared__ float A_s[LS][LT];
    __shared__ float colmax[LT];
    __shared__ float colsum[LT];
    __shared__ float rowvec[LT];
    __shared__ float attn_s[LS];
    __shared__ float score_s[2 * HDIM];
    __shared__ float logit[NOUT];

    for (int i = tid; i < LT * 2 * HDIM; i += 256) {
        int t = i >> 9;
        int mm = i & 511;
        tgt_s[t][mm] = (mm < HDIM)
            ? d_h_tgt[0][((size_t)t * NB + b) * HDIM + mm]
            : d_h_tgt[1][((size_t)t * NB + b) * HDIM + (mm - HDIM)];
    }
    if (tid < LT) rowvec[tid] = 0.f;
    __syncthreads();

    for (int s = warp; s < LS; s += 8) {
        float p[LT];
        #pragma unroll
        for (int t = 0; t < LT; t++) p[t] = 0.f;
        const float* f0 = &d_h_sen[0][((size_t)s * NB + b) * HDIM];
        const float* f1 = &d_h_sen[1][((size_t)s * NB + b) * HDIM];
        for (int mm = lane; mm < HDIM; mm += 32) {
            float v0 = f0[mm], v1 = f1[mm];
            #pragma unroll
            for (int t = 0; t < LT; t++)
                p[t] += v0 * tgt_s[t][mm] + v1 * tgt_s[t][HDIM + mm];
        }
        #pragma unroll
        for (int t = 0; t < LT; t++) {
            #pragma unroll
            for (int o = 16; o; o >>= 1) p[t] += __shfl_xor_sync(0xffffffffu, p[t], o);
            if (lane == 0) A_s[s][t] = p[t];
        }
    }
    __syncthreads();

    if (tid < LT) {
        float mx = -1e30f;
        for (int s = 0; s < LS; s++) mx = fmaxf(mx, A_s[s][tid]);
        float sm = 0.f;
        for (int s = 0; s < LS; s++) sm += expf(A_s[s][tid] - mx);
        colmax[tid] = mx;
        colsum[tid] = sm;
    }
    if (tid < LS) {
        float mx = -1e30f;
        #pragma unroll
        for (int t = 0; t < LT; t++) mx = fmaxf(mx, A_s[tid][t]);
        float e[LT], sm = 0.f;
        #pragma unroll
        for (int t = 0; t < LT; t++) { e[t] = expf(A_s[tid][t] - mx); sm += e[t]; }
        float inv = 1.f / (sm * (float)LS);
        #pragma unroll
        for (int t = 0; t < LT; t++) atomicAdd(&rowvec[t], e[t] * inv);
    }
    __syncthreads();

    if (tid < LS) {
        float a = 0.f;
        #pragma unroll
        for (int t = 0; t < LT; t++)
            a += (expf(A_s[tid][t] - colmax[t]) / colsum[t]) * rowvec[t];
        attn_s[tid] = a;
    }
    __syncthreads();

    // score[h] = sum_s attn[s] * sen_h[b,s,h]  (4-way ILP over s)
    for (int mm = tid; mm < 2 * HDIM; mm += 256) {
        const float* hp = (mm < HDIM) ? d_h_sen[0] : d_h_sen[1];
        int m2 = mm & (HDIM - 1);
        float a0 = 0.f, a1 = 0.f, a2 = 0.f, a3 = 0.f;
        #pragma unroll 4
        for (int s = 0; s < LS; s += 4) {
            a0 += attn_s[s]     * hp[((size_t)(s)     * NB + b) * HDIM + m2];
            a1 += attn_s[s + 1] * hp[((size_t)(s + 1) * NB + b) * HDIM + m2];
            a2 += attn_s[s + 2] * hp[((size_t)(s + 2) * NB + b) * HDIM + m2];
            a3 += attn_s[s + 3] * hp[((size_t)(s + 3) * NB + b) * HDIM + m2];
        }
        score_s[mm] = (a0 + a1) + (a2 + a3);
    }
    __syncthreads();

    if (warp < NOUT) {
        float acc = 0.f;
        for (int mm = lane; mm < 2 * HDIM; mm += 32)
            acc += score_s[mm] * Wout[warp * 2 * HDIM + mm];
        #pragma unroll
        for (int o = 16; o; o >>= 1) acc += __shfl_xor_sync(0xffffffffu, acc, o);
        if (lane == 0) logit[warp] = acc + bout[warp];
    }
    __syncthreads();

    if (tid == 0) {
        float mx = fmaxf(logit[0], fmaxf(logit[1], logit[2]));
        float e0 = expf(logit[0] - mx);
        float e1 = expf(logit[1] - mx);
        float e2 = expf(logit[2] - mx);
        float inv = 1.f / (e0 + e1 + e2);
        out[b * NOUT + 0] = e0 * inv;
        out[b * NOUT + 1] = e1 * inv;
        out[b * NOUT + 2] = e2 * inv;
    }
}

// ----------------------------- launch ---------------------------------------
extern "C" void kernel_launch(void* const* d_in, const int* in_sizes, int n_in,
                              void* d_out, int out_size) {
    const int*   sen_src = (const int*)d_in[0];
    const int*   tgt_src = (const int*)d_in[1];
    const float* emb     = (const float*)d_in[2];
    WPtrs wp;
    for (int l = 0; l < 4; l++) {
        wp.wih[l] = (const float*)d_in[3 + 4 * l];
        wp.whh[l] = (const float*)d_in[4 + 4 * l];
        wp.bih[l] = (const float*)d_in[5 + 4 * l];
        wp.bhh[l] = (const float*)d_in[6 + 4 * l];
    }
    const float* Wout = (const float*)d_in[19];
    const float* bout = (const float*)d_in[20];
    float* out = (float*)d_out;

    cudaFuncSetAttribute(gemm_xw, cudaFuncAttributeMaxDynamicSharedMemorySize, GEMM_SMEM);
    cudaFuncSetAttribute(lstm_kernel, cudaFuncAttributeMaxDynamicSharedMemorySize, LSTM_SMEM);

    prep_kernel<<<dim3(256, 4), 256>>>(wp);
    embed_kernel<<<(LS + LT) * NB, EPAD>>>(sen_src, tgt_src, emb);
    gemm_xw<<<dim3(LS * NB / GBM, GDIM / GBN, 4), 256, GEMM_SMEM>>>();
    lstm_kernel<<<128, 512, LSTM_SMEM>>>();   // 32 clusters x 4 CTAs
    attn_kernel<<<NB, 256>>>(Wout, bout, out);
}

// round 17
// speedup vs baseline: 10.9785x; 1.0159x over previous
#include <cuda_runtime.h>
#include <cuda_bf16.h>
#include <cstdint>
#include <math.h>
#include <mma.h>

using namespace nvcuda;

#define NB   128   // batch
#define LS   128   // sentence length
#define LT   8     // target length
#define EDIM 300   // true embedding dim (E=300)
#define EPAD 320   // padded embedding dim
#define HDIM 256
#define GDIM 1024  // 4*H
#define NOUT 3

// Weight rows are stored GATE-INTERLEAVED (unit-major): new row = u*4 + g,
// where old (PyTorch) row = g*256 + u. Gates of one unit are contiguous.

// ----------------------------- scratch (static __device__, no allocs) ------
__device__ __align__(128) __nv_bfloat16 d_x_sen[LS * NB * EPAD];   // [t][b][e] zero-pad
__device__ __align__(128) __nv_bfloat16 d_x_tgt[LT * NB * EPAD];
__device__ __align__(128) __nv_bfloat16 d_Wih[4][GDIM * EPAD];     // interleaved rows
__device__ __align__(128) __nv_bfloat16 d_Whh[4][GDIM * HDIM];     // interleaved rows
__device__ __align__(128) float d_bias[4][GDIM];                   // interleaved bih+bhh
__device__ __align__(128) float d_gates_sen[2][LS * NB * GDIM];    // interleaved cols
__device__ __align__(128) float d_gates_tgt[2][LT * NB * GDIM];
__device__ __align__(128) float d_h_sen[2][LS * NB * HDIM];        // [t][b][h]
__device__ __align__(128) float d_h_tgt[2][LT * NB * HDIM];

struct WPtrs {
    const float* wih[4];
    const float* whh[4];
    const float* bih[4];
    const float* bhh[4];
};

// MUFU.TANH-based activations (validated: rel_err 1.31e-5 overall)
__device__ __forceinline__ float tanh_fast(float x) {
    float y;
    asm("tanh.approx.f32 %0, %1;" : "=f"(y) : "f"(x));
    return y;
}
__device__ __forceinline__ float sig_fast(float x) {
    return 0.5f + 0.5f * tanh_fast(0.5f * x);
}

__device__ __forceinline__ uint32_t smem_u32(const void* p) {
    uint32_t a;
    asm("{ .reg .u64 t; cvta.to.shared.u64 t, %1; cvt.u32.u64 %0, t; }" : "=r"(a) : "l"(p));
    return a;
}
__device__ __forceinline__ uint32_t cluster_rank() {
    uint32_t r;
    asm("mov.u32 %0, %%cluster_ctarank;" : "=r"(r));
    return r;
}
__device__ __forceinline__ void st_dsmem_b16(uint32_t laddr, uint32_t rank, __nv_bfloat16 v) {
    unsigned short s = *reinterpret_cast<unsigned short*>(&v);
    asm volatile(
        "{\n\t.reg .b32 ra;\n\t"
        "mapa.shared::cluster.u32 ra, %0, %1;\n\t"
        "st.shared::cluster.b16 [ra], %2;\n\t}"
        :: "r"(laddr), "r"(rank), "h"(s) : "memory");
}
__device__ __forceinline__ void mbar_arrive_remote(uint32_t laddr, uint32_t rank) {
    asm volatile(
        "{\n\t.reg .b32 ra;\n\t"
        "mapa.shared::cluster.u32 ra, %0, %1;\n\t"
        "mbarrier.arrive.release.cluster.shared::cluster.b64 _, [ra];\n\t}"
        :: "r"(laddr), "r"(rank) : "memory");
}
__device__ __forceinline__ void mbar_wait_parity(uint32_t laddr, uint32_t parity) {
    uint32_t done;
    asm volatile(
        "{\n\t.reg .pred p;\n\t"
        "mbarrier.try_wait.parity.acquire.cluster.shared::cta.b64 p, [%1], %2;\n\t"
        "selp.b32 %0, 1, 0, p;\n\t}"
        : "=r"(done) : "r"(laddr), "r"(parity) : "memory");
    while (!done) {
        asm volatile(
            "{\n\t.reg .pred p;\n\t"
            "mbarrier.try_wait.parity.acquire.cluster.shared::cta.b64 p, [%1], %2;\n\t"
            "selp.b32 %0, 1, 0, p;\n\t}"
            : "=r"(done) : "r"(laddr), "r"(parity) : "memory");
    }
}
__device__ __forceinline__ void cp_async16(uint32_t dst_smem, const void* src) {
    asm volatile("cp.async.ca.shared.global [%0], [%1], 16;"
                 :: "r"(dst_smem), "l"(src) : "memory");
}
#define CP_COMMIT() asm volatile("cp.async.commit_group;" ::: "memory")
#define CLUSTER_ARRIVE() asm volatile("barrier.cluster.arrive.aligned;" ::: "memory")
#define CLUSTER_WAIT()   asm volatile("barrier.cluster.wait.aligned;" ::: "memory")

// ----------------------------- K0: weight prep (gate-interleave) ------------
__global__ void prep_kernel(WPtrs p) {
    int l = blockIdx.y;
    int stride = gridDim.x * blockDim.x;
    int start = blockIdx.x * blockDim.x + threadIdx.x;
    for (int i = start; i < GDIM * EPAD; i += stride) {
        int nn = i / EPAD;            // new (interleaved) row
        int k  = i - nn * EPAD;
        int u  = nn >> 2;
        int g  = nn & 3;
        int no = g * 256 + u;         // old row
        d_Wih[l][i] = __float2bfloat16_rn((k < EDIM) ? p.wih[l][(size_t)no * EDIM + k] : 0.f);
    }
    for (int i = start; i < GDIM * HDIM; i += stride) {
        int nn = i >> 8;              // new row (HDIM=256)
        int k  = i & 255;
        int u  = nn >> 2;
        int g  = nn & 3;
        int no = g * 256 + u;
        d_Whh[l][i] = __float2bfloat16_rn(p.whh[l][(size_t)no * HDIM + k]);
    }
    for (int i = start; i < GDIM; i += stride) {
        int u = i >> 2, g = i & 3;
        int no = g * 256 + u;
        d_bias[l][i] = p.bih[l][no] + p.bhh[l][no];
    }
}

// ----------------------------- K1: embedding gather -------------------------
__global__ void embed_kernel(const int* __restrict__ sen_src,
                             const int* __restrict__ tgt_src,
                             const float* __restrict__ emb) {
    int row = blockIdx.x;
    int tid = threadIdx.x;  // 320 threads == EPAD
    if (row < LS * NB) {
        int t = row / NB, b = row % NB;
        int idx = sen_src[b * LS + t];
        float v = (idx == 0 || tid >= EDIM) ? 0.f : emb[(size_t)idx * EDIM + tid];
        d_x_sen[(size_t)row * EPAD + tid] = __float2bfloat16_rn(v);
    } else {
        int r = row - LS * NB;
        int t = r / NB, b = r % NB;
        int idx = tgt_src[b * LT + t];
        float v = (idx == 0 || tid >= EDIM) ? 0.f : emb[(size_t)idx * EDIM + tid];
        d_x_tgt[(size_t)r * EPAD + tid] = __float2bfloat16_rn(v);
    }
}

// ----------------------------- K2: input projection GEMM (cp.async pipe) ----
#define GBM 128
#define GBN 128
#define GBK 64
#define GLD 72
#define GTILE (GBM * GLD)                 // elements per tile buffer
#define GEMM_SMEM (4 * GTILE * 2)         // A0,B0,A1,B1 bf16 = 73728 B
#define NKIT (EPAD / GBK)                 // 5

__global__ __launch_bounds__(256, 2) void gemm_xw() {
    int l = blockIdx.z;
    if (l >= 2 && blockIdx.x >= (LT * NB / GBM)) return;

    const __nv_bfloat16* __restrict__ X = (l < 2) ? d_x_sen : d_x_tgt;
    const __nv_bfloat16* __restrict__ W = d_Wih[l];
    float* __restrict__ C = (l < 2) ? d_gates_sen[l] : d_gates_tgt[l - 2];

    extern __shared__ __align__(128) unsigned char gsm[];
    __nv_bfloat16* buf = (__nv_bfloat16*)gsm;   // [4][GTILE]: A0 B0 A1 B1
    uint32_t buf_u32 = smem_u32(buf);

    int tid = threadIdx.x;
    int warp = tid >> 5;
    int wm = warp & 1;
    int wn = warp >> 1;
    int m0 = blockIdx.x * GBM;
    int n0 = blockIdx.y * GBN;

    int r0 = tid >> 3;
    int c  = (tid & 7) * 8;

    auto issue_tile = [&](int it, int s) {
        uint32_t aofs = buf_u32 + (uint32_t)((2 * s) * GTILE * 2);
        uint32_t bofs = buf_u32 + (uint32_t)((2 * s + 1) * GTILE * 2);
        int kc = it * GBK;
        #pragma unroll
        for (int i = 0; i < 4; i++) {
            int r = r0 + i * 32;
            cp_async16(aofs + (uint32_t)(r * GLD + c) * 2,
                       &X[(size_t)(m0 + r) * EPAD + kc + c]);
            cp_async16(bofs + (uint32_t)(r * GLD + c) * 2,
                       &W[(size_t)(n0 + r) * EPAD + kc + c]);
        }
    };

    wmma::fragment<wmma::accumulator, 16, 16, 16, float> acc[4][2];
    #pragma unroll
    for (int mi = 0; mi < 4; mi++)
        #pragma unroll
        for (int ni = 0; ni < 2; ni++) wmma::fill_fragment(acc[mi][ni], 0.f);

    issue_tile(0, 0);
    CP_COMMIT();

    for (int it = 0; it < NKIT; it++) {
        int s = it & 1;
        if (it + 1 < NKIT) {
            issue_tile(it + 1, s ^ 1);
            CP_COMMIT();
            asm volatile("cp.async.wait_group 1;" ::: "memory");
        } else {
            asm volatile("cp.async.wait_group 0;" ::: "memory");
        }
        __syncthreads();

        const __nv_bfloat16* As = buf + (2 * s) * GTILE;
        const __nv_bfloat16* Bs = buf + (2 * s + 1) * GTILE;
        #pragma unroll
        for (int kk = 0; kk < GBK; kk += 16) {
            wmma::fragment<wmma::matrix_a, 16, 16, 16, __nv_bfloat16, wmma::row_major> af[4];
            wmma::fragment<wmma::matrix_b, 16, 16, 16, __nv_bfloat16, wmma::col_major> bf[2];
            #pragma unroll
            for (int mi = 0; mi < 4; mi++)
                wmma::load_matrix_sync(af[mi], &As[(wm * 64 + mi * 16) * GLD + kk], GLD);
            #pragma unroll
            for (int ni = 0; ni < 2; ni++)
                wmma::load_matrix_sync(bf[ni], &Bs[(wn * 32 + ni * 16) * GLD + kk], GLD);
            #pragma unroll
            for (int mi = 0; mi < 4; mi++)
                #pragma unroll
                for (int ni = 0; ni < 2; ni++)
                    wmma::mma_sync(acc[mi][ni], af[mi], bf[ni], acc[mi][ni]);
        }
        __syncthreads();
    }
    #pragma unroll
    for (int mi = 0; mi < 4; mi++)
        #pragma unroll
        for (int ni = 0; ni < 2; ni++)
            wmma::store_matrix_sync(
                &C[(size_t)(m0 + wm * 64 + mi * 16) * GDIM + n0 + wn * 32 + ni * 16],
                acc[mi][ni], GDIM, wmma::mem_row_major);
}

// ----------------------------- K3: LSTM recurrence (cluster, interleaved) ---
// Cluster of 4 CTAs per (lstm, batch-chunk-of-16). CTA rank r owns hidden
// units [r*64,+64); its (interleaved) Whh B-fragments live in registers.
// Gate-interleaved layout => all gate/x/bias accesses are float4.
#define BCH    16
#define SLC    64                       // hidden units per CTA
#define WLD    264                      // smem leading dim
#define W_SZ   (256 * WLD * 2)          // 135168 B
#define H_SZ   (BCH * WLD * 2)          // 8448 B per h buffer
#define G_SZ   (BCH * WLD * 4)          // 16896 B per partial-gate buffer
#define LSTM_SMEM (W_SZ + 2 * H_SZ + 2 * G_SZ + 16)   // +mbarrier

__global__ void __cluster_dims__(4, 1, 1) __launch_bounds__(512, 1) lstm_kernel() {
    extern __shared__ __align__(128) unsigned char smem[];
    __nv_bfloat16* Wsh    = (__nv_bfloat16*)smem;                        // [256][264]
    __nv_bfloat16* hbuf   = (__nv_bfloat16*)(smem + W_SZ);               // [2][16][264]
    float*         gatesA = (float*)(smem + W_SZ + 2 * H_SZ);            // [16][264]
    float*         gatesB = (float*)(smem + W_SZ + 2 * H_SZ + G_SZ);     // [16][264]
    unsigned long long* mbar = (unsigned long long*)(smem + W_SZ + 2 * H_SZ + 2 * G_SZ);

    int bx   = blockIdx.x;
    int cid  = bx >> 2;                 // cluster id 0..31
    int lstm = cid >> 3;                // 0=sf 1=sb 2=tf 3=tb
    int b0   = (cid & 7) * BCH;
    uint32_t r = cluster_rank();        // 0..3
    int T    = (lstm < 2) ? LS : LT;
    bool rev = (lstm & 1);
    const __nv_bfloat16* __restrict__ Wg = d_Whh[lstm];
    const float* __restrict__ Xg   = (lstm < 2) ? d_gates_sen[lstm] : d_gates_tgt[lstm - 2];
    float* __restrict__       Hout = (lstm < 2) ? d_h_sen[lstm]     : d_h_tgt[lstm - 2];

    int tid   = threadIdx.x;            // 0..511
    int warp  = tid >> 5;               // 0..15
    int wcol  = warp & 7;               // col slice (32 gates = 8 units)
    int khalf = warp >> 3;              // 0 or 1 (K half)
    int u     = tid & 63;               // hidden unit within slice
    int kbg   = (tid >> 6) & 7;         // batch group 0..7
    int r64u  = (int)r * SLC + u;       // global hidden unit

    uint32_t mbar_u32 = smem_u32(mbar);
    if (tid == 0)
        asm volatile("mbarrier.init.shared.b64 [%0], %1;" :: "r"(mbar_u32), "r"(4u) : "memory");

    // ---- load resident Whh slice: local row lr <- interleaved row r*256+lr
    for (int i = tid; i < 256 * 32; i += 512) {
        int lr = i >> 5;
        int c8 = i & 31;
        int n  = (int)r * 256 + lr;
        *(uint4*)&Wsh[lr * WLD + c8 * 8] = *(const uint4*)&Wg[(size_t)n * HDIM + c8 * 8];
    }
    // ---- zero both h buffers
    for (int i = tid; i < 2 * BCH * WLD; i += 512) hbuf[i] = __float2bfloat16_rn(0.f);

    float c[2] = {0.f, 0.f};
    const float4 bv = *(const float4*)&d_bias[lstm][r64u * 4];  // i,f,g,o

    uint32_t hbase_u32 = smem_u32(hbuf);
    float* gatesK = khalf ? gatesB : gatesA;
    __syncthreads();

    // ---- preload this warp's constant Whh B-fragments into registers
    wmma::fragment<wmma::matrix_b, 16, 16, 16, __nv_bfloat16, wmma::col_major> bfr[8][2];
    #pragma unroll
    for (int i = 0; i < 8; i++) {
        int kk = khalf * 8 + i;
        wmma::load_matrix_sync(bfr[i][0], &Wsh[(wcol * 32) * WLD + kk * 16], WLD);
        wmma::load_matrix_sync(bfr[i][1], &Wsh[(wcol * 32 + 16) * WLD + kk * 16], WLD);
    }

    // ---- prefetch x-gates for step 0 (interleaved -> one float4 per row)
    float4 xv[2];
    {
        int t0 = rev ? (T - 1) : 0;
        const float* xgt = Xg + (size_t)(t0 * NB + b0) * GDIM;
        #pragma unroll
        for (int j = 0; j < 2; j++)
            xv[j] = *(const float4*)&xgt[(size_t)(j * 8 + kbg) * GDIM + r64u * 4];
    }

    CLUSTER_ARRIVE();
    CLUSTER_WAIT();

    for (int step = 0; step < T; step++) {
        int t = rev ? (T - 1 - step) : step;
        const __nv_bfloat16* hcur = hbuf + (step & 1) * (BCH * WLD);
        uint32_t hnxt_u32 = hbase_u32 + (uint32_t)(((step & 1) ^ 1) * H_SZ);

        // ---- partial gates: 8 A-LDSM + 16 HMMA (B in registers)
        {
            wmma::fragment<wmma::accumulator, 16, 16, 16, float> acc0, acc1;
            wmma::fill_fragment(acc0, 0.f);
            wmma::fill_fragment(acc1, 0.f);
            #pragma unroll
            for (int i = 0; i < 8; i++) {
                int kk = khalf * 8 + i;
                wmma::fragment<wmma::matrix_a, 16, 16, 16, __nv_bfloat16, wmma::row_major> af;
                wmma::load_matrix_sync(af, &hcur[kk * 16], WLD);
                wmma::mma_sync(acc0, af, bfr[i][0], acc0);
                wmma::mma_sync(acc1, af, bfr[i][1], acc1);
            }
            wmma::store_matrix_sync(&gatesK[wcol * 32], acc0, WLD, wmma::mem_row_major);
            wmma::store_matrix_sync(&gatesK[wcol * 32 + 16], acc1, WLD, wmma::mem_row_major);
        }
        __syncthreads();

        // ---- elementwise: float4 gate reads + fused scalar DSMEM scatter
        float hvv[2];
        #pragma unroll
        for (int j = 0; j < 2; j++) {
            int kb = j * 8 + kbg;
            int rw = kb * WLD + 4 * u;
            float4 ga = *(const float4*)&gatesA[rw];
            float4 gb = *(const float4*)&gatesB[rw];
            float gi = ga.x + gb.x + xv[j].x + bv.x;
            float gf = ga.y + gb.y + xv[j].y + bv.y;
            float gg = ga.z + gb.z + xv[j].z + bv.z;
            float go = ga.w + gb.w + xv[j].w + bv.w;
            float cn = sig_fast(gf) * c[j] + sig_fast(gi) * tanh_fast(gg);
            c[j] = cn;
            float hv = sig_fast(go) * tanh_fast(cn);
            hvv[j] = hv;
            __nv_bfloat16 hb = __float2bfloat16_rn(hv);
            uint32_t off = hnxt_u32 + (uint32_t)(kb * WLD + r64u) * 2u;
            #pragma unroll
            for (uint32_t rk = 0; rk < 4; rk++) st_dsmem_b16(off, rk, hb);
        }
        __syncthreads();            // all stores issued before the arrives

        if (tid < 4) mbar_arrive_remote(mbar_u32, (uint32_t)tid);

        // ---- latency shadow: Hout stores + next-step x prefetch
        {
            float* hrow = Hout + (size_t)(t * NB + b0) * HDIM;
            #pragma unroll
            for (int j = 0; j < 2; j++)
                hrow[(size_t)(j * 8 + kbg) * HDIM + r64u] = hvv[j];
        }
        if (step + 1 < T) {
            int tn = rev ? (T - 2 - step) : (step + 1);
            const float* xgt = Xg + (size_t)(tn * NB + b0) * GDIM;
            #pragma unroll
            for (int j = 0; j < 2; j++)
                xv[j] = *(const float4*)&xgt[(size_t)(j * 8 + kbg) * GDIM + r64u * 4];
        }
        mbar_wait_parity(mbar_u32, (uint32_t)(step & 1));
    }
}

// ----------------------------- K4: attention + output (fp32) ----------------
__global__ __launch_bounds__(256) void attn_kernel(const float* __restrict__ Wout,
                                                   const float* __restrict__ bout,
                                                   float* __restrict__ out) {
    int b = blockIdx.x;
    int tid = threadIdx.x;
    int lane = tid & 31, warp = tid >> 5;

    __shared__ float tgt_s[LT][2 * HDIM];
    __shared__ float A_s[LS][LT];
    __shared__ float colmax[LT];
    __shared__ float colsum[LT];
    __shared__ float rowvec[LT];
    __shared__ float attn_s[LS];
    __shared__ float score_s[2 * HDIM];
    __shared__ float logit[NOUT];

    for (int i = tid; i < LT * 2 * HDIM; i += 256) {
        int t = i >> 9;
        int mm = i & 511;
        tgt_s[t][mm] = (mm < HDIM)
            ? d_h_tgt[0][((size_t)t * NB + b) * HDIM + mm]
            : d_h_tgt[1][((size_t)t * NB + b) * HDIM + (mm - HDIM)];
    }
    if (tid < LT) rowvec[tid] = 0.f;
    __syncthreads();

    for (int s = warp; s < LS; s += 8) {
        float p[LT];
        #pragma unroll
        for (int t = 0; t < LT; t++) p[t] = 0.f;
        const float* f0 = &d_h_sen[0][((size_t)s * NB + b) * HDIM];
        const float* f1 = &d_h_sen[1][((size_t)s * NB + b) * HDIM];
        for (int mm = lane; mm < HDIM; mm += 32) {
            float v0 = f0[mm], v1 = f1[mm];
            #pragma unroll
            for (int t = 0; t < LT; t++)
                p[t] += v0 * tgt_s[t][mm] + v1 * tgt_s[t][HDIM + mm];
        }
        #pragma unroll
        for (int t = 0; t < LT; t++) {
            #pragma unroll
            for (int o = 16; o; o >>= 1) p[t] += __shfl_xor_sync(0xffffffffu, p[t], o);
            if (lane == 0) A_s[s][t] = p[t];
        }
    }
    __syncthreads();

    if (tid < LT) {
        float mx = -1e30f;
        for (int s = 0; s < LS; s++) mx = fmaxf(mx, A_s[s][tid]);
        float sm = 0.f;
        for (int s = 0; s < LS; s++) sm += expf(A_s[s][tid] - mx);
        colmax[tid] = mx;
        colsum[tid] = sm;
    }
    if (tid < LS) {
        float mx = -1e30f;
        #pragma unroll
        for (int t = 0; t < LT; t++) mx = fmaxf(mx, A_s[tid][t]);
        float e[LT], sm = 0.f;
        #pragma unroll
        for (int t = 0; t < LT; t++) { e[t] = expf(A_s[tid][t] - mx); sm += e[t]; }
        float inv = 1.f / (sm * (float)LS);
        #pragma unroll
        for (int t = 0; t < LT; t++) atomicAdd(&rowvec[t], e[t] * inv);
    }
    __syncthreads();

    if (tid < LS) {
        float a = 0.f;
        #pragma unroll
        for (int t = 0; t < LT; t++)
            a += (expf(A_s[tid][t] - colmax[t]) / colsum[t]) * rowvec[t];
        attn_s[tid] = a;
    }
    __syncthreads();

    // score[h] = sum_s attn[s] * sen_h[b,s,h]  (4-way ILP over s)
    for (int mm = tid; mm < 2 * HDIM; mm += 256) {
        const float* hp = (mm < HDIM) ? d_h_sen[0] : d_h_sen[1];
        int m2 = mm & (HDIM - 1);
        float a0 = 0.f, a1 = 0.f, a2 = 0.f, a3 = 0.f;
        #pragma unroll 4
        for (int s = 0; s < LS; s += 4) {
            a0 += attn_s[s]     * hp[((size_t)(s)     * NB + b) * HDIM + m2];
            a1 += attn_s[s + 1] * hp[((size_t)(s + 1) * NB + b) * HDIM + m2];
            a2 += attn_s[s + 2] * hp[((size_t)(s + 2) * NB + b) * HDIM + m2];
            a3 += attn_s[s + 3] * hp[((size_t)(s + 3) * NB + b) * HDIM + m2];
        }
        score_s[mm] = (a0 + a1) + (a2 + a3);
    }
    __syncthreads();

    if (warp < NOUT) {
        float acc = 0.f;
        for (int mm = lane; mm < 2 * HDIM; mm += 32)
            acc += score_s[mm] * Wout[warp * 2 * HDIM + mm];
        #pragma unroll
        for (int o = 16; o; o >>= 1) acc += __shfl_xor_sync(0xffffffffu, acc, o);
        if (lane == 0) logit[warp] = acc + bout[warp];
    }
    __syncthreads();

    if (tid == 0) {
        float mx = fmaxf(logit[0], fmaxf(logit[1], logit[2]));
        float e0 = expf(logit[0] - mx);
        float e1 = expf(logit[1] - mx);
        float e2 = expf(logit[2] - mx);
        float inv = 1.f / (e0 + e1 + e2);
        out[b * NOUT + 0] = e0 * inv;
        out[b * NOUT + 1] = e1 * inv;
        out[b * NOUT + 2] = e2 * inv;
    }
}

// ----------------------------- launch ---------------------------------------
extern "C" void kernel_launch(void* const* d_in, const int* in_sizes, int n_in,
                              void* d_out, int out_size) {
    const int*   sen_src = (const int*)d_in[0];
    const int*   tgt_src = (const int*)d_in[1];
    const float* emb     = (const float*)d_in[2];
    WPtrs wp;
    for (int l = 0; l < 4; l++) {
        wp.wih[l] = (const float*)d_in[3 + 4 * l];
        wp.whh[l] = (const float*)d_in[4 + 4 * l];
        wp.bih[l] = (const float*)d_in[5 + 4 * l];
        wp.bhh[l] = (const float*)d_in[6 + 4 * l];
    }
    const float* Wout = (const float*)d_in[19];
    const float* bout = (const float*)d_in[20];
    float* out = (float*)d_out;

    cudaFuncSetAttribute(gemm_xw, cudaFuncAttributeMaxDynamicSharedMemorySize, GEMM_SMEM);
    cudaFuncSetAttribute(lstm_kernel, cudaFuncAttributeMaxDynamicSharedMemorySize, LSTM_SMEM);

    prep_kernel<<<dim3(256, 4), 256>>>(wp);
    embed_kernel<<<(LS + LT) * NB, EPAD>>>(sen_src, tgt_src, emb);
    gemm_xw<<<dim3(LS * NB / GBM, GDIM / GBN, 4), 256, GEMM_SMEM>>>();
    lstm_kernel<<<128, 512, LSTM_SMEM>>>();   // 32 clusters x 4 CTAs
    attn_kernel<<<NB, 256>>>(Wout, bout, out);
}